// round 11
// baseline (speedup 1.0000x reference)
#include <cuda_runtime.h>
#include <cuda_bf16.h>
#include <math.h>
#include <stdint.h>

#define DM   128
#define NH   8
#define HD   16
#define KTOT 164          // 9 + 25 + 49 + 81
#define PER_B 21504       // 128*128 + 64*64 + 32*32
#define MAXN 2048
#define MAXROWS (2*PER_B + MAXN*9)
#define MAXL 4

typedef unsigned long long ull;

// ---------------- device scratch ----------------
__device__ float g_x  [MAXN*DM];
__device__ float g_q  [MAXN*DM];
__device__ float g_o  [MAXN*DM];
__device__ float g_qcs[MAXN*16];
__device__ int   g_kidx[MAXN*KTOT];
__device__ int   g_kval[MAXN*KTOT];
__device__ int   g_rowsrc[MAXROWS];
__device__ float g_rcs[MAXROWS*16];              // per-row RoPE cos/sin
__device__ float g_Kc[(size_t)MAXROWS*DM];
__device__ float g_Vc[(size_t)MAXROWS*DM];
__device__ __align__(16) __nv_bfloat16 g_WBhi[MAXL*256*128];   // [layer][n: Wk|Wv][k]
__device__ __align__(16) __nv_bfloat16 g_WBlo[MAXL*256*128];
__device__ float g_ktab[4*2*264*8];              // [level][axis][g+4][4cos,4sin]

__device__ __constant__ float c_invfreq[4] = {1.0f, 0.56234132519f, 0.316227766017f, 0.177827941004f};

// ---------------- helpers ----------------
__device__ __forceinline__ ull fma2(ull a, ull b, ull c) {
    ull d; asm("fma.rn.f32x2 %0, %1, %2, %3;" : "=l"(d) : "l"(a), "l"(b), "l"(c)); return d;
}
__device__ __forceinline__ ull pack2(float f) {
    ull r; asm("mov.b64 %0, {%1, %1};" : "=l"(r) : "r"(__float_as_uint(f))); return r;
}
__device__ __forceinline__ ull packab(float a, float b) {
    ull r; asm("mov.b64 %0, {%1, %2};" : "=l"(r) : "r"(__float_as_uint(a)), "r"(__float_as_uint(b))); return r;
}
__device__ __forceinline__ void unpack2(ull v, float& lo, float& hi) {
    unsigned int a, b; asm("mov.b64 {%0, %1}, %2;" : "=r"(a), "=r"(b) : "l"(v));
    lo = __uint_as_float(a); hi = __uint_as_float(b);
}
__device__ __forceinline__ float gelu_tanh(float v) {
    float u = 0.7978845608028654f * (v + 0.044715f * v * v * v);
    return 0.5f * v * (1.f + tanhf(u));
}
__device__ __forceinline__ int batch_of(int q, const int* qbo, int n_off) {
    int b = 0;
    for (int t = 1; t < n_off - 1; t++) if (q >= qbo[t]) b = t;
    return b;
}
__device__ __forceinline__ uint32_t smem_u32(const void* p) {
    uint32_t a;
    asm("{ .reg .u64 t; cvta.to.shared.u64 t, %1; cvt.u32.u64 %0, t; }" : "=r"(a) : "l"(p));
    return a;
}
__device__ __forceinline__ uint32_t bf2(float a, float b) {
    __nv_bfloat162 h = __floats2bfloat162_rn(a, b);
    return *(uint32_t*)&h;
}
__device__ __forceinline__ float bflo(float x, __nv_bfloat16 hi) {
    return x - __bfloat162float(hi);
}
__device__ __forceinline__ void ldsm_x4(uint32_t addr, uint32_t& r0, uint32_t& r1, uint32_t& r2, uint32_t& r3) {
    asm volatile("ldmatrix.sync.aligned.m8n8.x4.shared.b16 {%0,%1,%2,%3}, [%4];"
                 : "=r"(r0), "=r"(r1), "=r"(r2), "=r"(r3) : "r"(addr));
}
__device__ __forceinline__ void mma_bf16(float* c, uint32_t a0, uint32_t a1, uint32_t a2, uint32_t a3,
                                         uint32_t b0, uint32_t b1) {
    asm volatile("mma.sync.aligned.m16n8k16.row.col.f32.bf16.bf16.f32 "
                 "{%0,%1,%2,%3}, {%4,%5,%6,%7}, {%8,%9}, {%0,%1,%2,%3};"
                 : "+f"(c[0]), "+f"(c[1]), "+f"(c[2]), "+f"(c[3])
                 : "r"(a0), "r"(a1), "r"(a2), "r"(a3), "r"(b0), "r"(b1));
}
__device__ __forceinline__ void cpa16(uint32_t saddr, const void* gaddr) {
    asm volatile("cp.async.cg.shared.global [%0], [%1], 16;" :: "r"(saddr), "l"(gaddr));
}
__device__ __forceinline__ void cp_commit() { asm volatile("cp.async.commit_group;" ::: "memory"); }
__device__ __forceinline__ void cp_wait1()  { asm volatile("cp.async.wait_group 1;" ::: "memory"); }
__device__ __forceinline__ void cp_wait0()  { asm volatile("cp.async.wait_group 0;" ::: "memory"); }

// ---------------- LN1 + Qproj + RoPE body (per-query, 128 threads) ----------------
__device__ void ln_qproj_body(int q, const float* __restrict__ lg, const float* __restrict__ lb,
                              const float* __restrict__ Wq) {
    int tid = threadIdx.x;
    int lane = tid & 31, w = tid >> 5;
    __shared__ float sh[128];
    __shared__ float sraw[128];
    __shared__ float red[8];
    float x = g_x[q*DM + tid];
    float s1 = x, s2 = x * x;
    #pragma unroll
    for (int o = 16; o; o >>= 1) {
        s1 += __shfl_xor_sync(0xffffffffu, s1, o);
        s2 += __shfl_xor_sync(0xffffffffu, s2, o);
    }
    if (lane == 0) { red[w] = s1; red[4 + w] = s2; }
    __syncthreads();
    float mean = (red[0] + red[1] + red[2] + red[3]) * (1.f / 128.f);
    float var  = (red[4] + red[5] + red[6] + red[7]) * (1.f / 128.f) - mean * mean;
    sh[tid] = (x - mean) * rsqrtf(var + 1e-5f) * lg[tid] + lb[tid];
    __syncthreads();
    float acc = 0.f;
    #pragma unroll 8
    for (int i = 0; i < 128; i++) acc += sh[i] * Wq[i * DM + tid];
    sraw[tid] = acc;
    __syncthreads();
    int p = (tid >> 1) & 7;
    float c = g_qcs[q*16 + p], s = g_qcs[q*16 + 8 + p];
    float x1 = sraw[tid & ~1];
    float x2 = sraw[tid |  1];
    g_q[q*DM + tid] = (tid & 1) ? (x1 * s + x2 * c) : (x1 * c - x2 * s);
}

// ---------------- fused prep kernel #1 (256 threads) ----------------
__global__ void prep1_kernel(const float* __restrict__ queries,
                             const float* __restrict__ qpos,
                             const int* __restrict__ qbo, int n_off,
                             const int* __restrict__ shapes,
                             const float* __restrict__ Wk, const float* __restrict__ Wv,
                             int N, int nl, int R123, int R,
                             int o1, int o2, int o3, int o4) {
    int bid = blockIdx.x, tid = threadIdx.x;
    if (bid < o1) {                                      // copy_x
        int i = bid * 256 + tid;
        if (i < N * DM) g_x[i] = queries[i];
    } else if (bid < o2) {                               // rowsrc
        int e = (bid - o1) * 256 + tid;
        if (e >= R) return;
        int src;
        if (e < R123) {
            int b = e / PER_B, r = e % PER_B;
            int l, i, j;
            if (r < 16384)      { l = 1; i = r >> 7; j = r & 127; }
            else if (r < 20480) { int rr = r - 16384; l = 2; i = rr >> 6; j = rr & 63; }
            else                { int rr = r - 20480; l = 3; i = rr >> 5; j = rr & 31; }
            src = ((b * 256 + i) * 256 + j) * 4 + l;
        } else {
            int e2 = e - R123;
            int q = e2 / 9, t = e2 % 9;
            int b = batch_of(q, qbo, n_off);
            int c0 = (int)floorf(qpos[2*q]), c1 = (int)floorf(qpos[2*q+1]);
            int gi = min(max(c0 + t / 3 - 1, 0), 255);
            int gj = min(max(c1 + t % 3 - 1, 0), 255);
            src = ((b * 256 + gi) * 256 + gj) * 4 + 0;
        }
        g_rowsrc[e] = src;
    } else if (bid < o3) {                               // wt split
        int id = (bid - o2) * 256 + tid;
        if (id >= nl * 256 * 128) return;
        int li = id / (256 * 128);
        int r  = id % (256 * 128);
        int n = r / 128, k = r % 128;
        float w = (n < 128) ? Wk[li*DM*DM + k*DM + n] : Wv[li*DM*DM + k*DM + (n - 128)];
        __nv_bfloat16 hi = __float2bfloat16(w);
        g_WBhi[id] = hi;
        g_WBlo[id] = __float2bfloat16(w - __bfloat162float(hi));
    } else if (bid < o4) {                               // ktab
        int id = (bid - o3) * 256 + tid;
        if (id >= 4 * 2 * 264) return;
        int l = id / (2 * 264);
        int axis = (id / 264) & 1;
        int g = (id % 264) - 4;
        float scale = (float)shapes[2*l + axis] / (float)shapes[axis];
        float kp = ((float)g + 0.5f) / scale;
        float* t = &g_ktab[(size_t)id * 8];
        #pragma unroll
        for (int f = 0; f < 4; f++) {
            float a = kp * c_invfreq[f];
            t[f] = cosf(a);
            t[4 + f] = sinf(a);
        }
    } else {                                             // qcs
        int q = (bid - o4) * 256 + tid;
        if (q >= N) return;
        float p0 = qpos[2*q], p1 = qpos[2*q+1];
        float* cs = &g_qcs[q * 16];
        #pragma unroll
        for (int f = 0; f < 4; f++) {
            float a0 = p0 * c_invfreq[f];
            float a1 = p1 * c_invfreq[f];
            cs[f]      = cosf(a0);  cs[8  + f] = sinf(a0);
            cs[4 + f]  = cosf(a1);  cs[12 + f] = sinf(a1);
        }
    }
}

// ---------------- fused prep kernel #2 (128 threads) ----------------
__global__ void prep2_kernel(const float* __restrict__ lg, const float* __restrict__ lb,
                             const float* __restrict__ Wq,
                             const float* __restrict__ qpos,
                             const int* __restrict__ qbo, int n_off,
                             const int* __restrict__ shapes,
                             int N, int R123, int R, int KB) {
    int bid = blockIdx.x, tid = threadIdx.x;
    if (bid < N) {
        ln_qproj_body(bid, lg, lb, Wq);
    } else if (bid < N + KB) {                           // build_keys (idx + valid only)
        int id = (bid - N) * 128 + tid;
        if (id >= N * KTOT) return;
        int q = id / KTOT, k = id % KTOT;
        int l, t, d;
        if      (k < 9)  { l = 0; t = k;      d = 3; }
        else if (k < 34) { l = 1; t = k - 9;  d = 5; }
        else if (k < 83) { l = 2; t = k - 34; d = 7; }
        else             { l = 3; t = k - 83; d = 9; }
        int Hl = shapes[2*l], Wl = shapes[2*l+1];
        float sh = (float)Hl / (float)shapes[0];
        float sw = (float)Wl / (float)shapes[1];
        int c0 = (int)floorf(qpos[2*q] * sh), c1 = (int)floorf(qpos[2*q+1] * sw);
        int gi = c0 + t / d - d / 2;
        int gj = c1 + t % d - d / 2;
        int valid = (gi >= 0 && gi < Hl && gj >= 0 && gj < Wl);
        int ci = min(max(gi, 0), Hl - 1), cj = min(max(gj, 0), Wl - 1);
        int b = batch_of(q, qbo, n_off);
        int idx;
        if (l == 0) idx = R123 + q * 9 + t;
        else {
            int base = (l == 1) ? 0 : (l == 2) ? 16384 : 20480;
            idx = b * PER_B + base + ci * Wl + cj;
        }
        g_kidx[id] = idx;
        g_kval[id] = valid;
    } else {                                             // build_rcs
        int e = (bid - N - KB) * 128 + tid;
        if (e >= R * 16) return;
        int row = e >> 4, idx = e & 15;
        int l, gi, gj;
        if (row < R123) {
            int r = row % PER_B;
            if (r < 16384)      { l = 1; gi = r >> 7; gj = r & 127; }
            else if (r < 20480) { int rr = r - 16384; l = 2; gi = rr >> 6; gj = rr & 63; }
            else                { int rr = r - 20480; l = 3; gi = rr >> 5; gj = rr & 31; }
        } else {
            int e2 = row - R123;
            int q = e2 / 9, t = e2 % 9;
            l = 0;
            gi = min(max((int)floorf(qpos[2*q])   + t / 3 - 1, 0), 255);
            gj = min(max((int)floorf(qpos[2*q+1]) + t % 3 - 1, 0), 255);
        }
        int trig = idx >> 3, p = idx & 7, axis = p >> 2, f = p & 3;
        int g = axis ? gj : gi;
        g_rcs[e] = g_ktab[(size_t)((l * 2 + axis) * 264 + (g + 4)) * 8 + trig * 4 + f];
    }
}

__global__ void ln_qproj_kernel(const float* __restrict__ lg, const float* __restrict__ lb,
                                const float* __restrict__ Wq) {
    ln_qproj_body(blockIdx.x, lg, lb, Wq);
}

// ---------------- mma.sync KV projection (cp.async double-buffered B; rope fused) ----------------
#define A_STR 136
#define B_STR 40
#define OFF_AHI 0
#define OFF_ALO 34816
#define OFF_B   69632
#define BUF_SZ  20480            // one buffer: BHI 10240 + BLO 10240
#define SM_MMA_TOTAL (OFF_B + 2*BUF_SZ)   // 110592

__device__ __forceinline__ void kv_issue_chunk(uint32_t sbase,
                                               const __nv_bfloat16* __restrict__ wbh,
                                               const __nv_bfloat16* __restrict__ wbl,
                                               int h, int c, int b, int tid) {
    #pragma unroll
    for (int it = 0; it < 2; it++) {
        int idx = tid + 256 * it;            // 0..511
        int n = idx >> 2, kk = (idx & 3) * 8;
        const __nv_bfloat16* gh = wbh + ((size_t)(h * 128 + n)) * 128 + c * 32 + kk;
        const __nv_bfloat16* gl = wbl + ((size_t)(h * 128 + n)) * 128 + c * 32 + kk;
        uint32_t so_ = sbase + OFF_B + b * BUF_SZ + (uint32_t)(n * B_STR + kk) * 2;
        cpa16(so_, gh);
        cpa16(so_ + 10240, gl);
    }
}

__global__ void __launch_bounds__(256, 2)
kvproj_mma_kernel(const float* __restrict__ fm, int li, int R) {
    extern __shared__ char smem[];
    uint32_t sbase = smem_u32(smem);
    int tid = threadIdx.x;
    int wid = tid >> 5, lane = tid & 31;
    int wm = wid & 3, wn = wid >> 2;
    int row0 = blockIdx.x * 128;

    // ---- A gather + bf16 hi/lo split ----
    #pragma unroll
    for (int it = 0; it < 16; it++) {
        int idx = tid + 256 * it;
        int r = idx >> 5, c4 = idx & 31;
        int row = row0 + r; if (row >= R) row = R - 1;
        int src = g_rowsrc[row];
        float4 v = *(const float4*)(fm + (size_t)src * 128 + c4 * 4);
        __nv_bfloat16 hx = __float2bfloat16(v.x);
        __nv_bfloat16 hy = __float2bfloat16(v.y);
        __nv_bfloat16 hz = __float2bfloat16(v.z);
        __nv_bfloat16 hw = __float2bfloat16(v.w);
        uint32_t h01 = ((uint32_t)*(uint16_t*)&hy << 16) | *(uint16_t*)&hx;
        uint32_t h23 = ((uint32_t)*(uint16_t*)&hw << 16) | *(uint16_t*)&hz;
        uint32_t l01 = bf2(bflo(v.x, hx), bflo(v.y, hy));
        uint32_t l23 = bf2(bflo(v.z, hz), bflo(v.w, hw));
        uint32_t off = (uint32_t)(r * A_STR + c4 * 4) * 2;
        *(uint2*)(smem + OFF_AHI + off) = make_uint2(h01, h23);
        *(uint2*)(smem + OFF_ALO + off) = make_uint2(l01, l23);
    }

    const __nv_bfloat16* wbh = g_WBhi + (size_t)li * 256 * 128;
    const __nv_bfloat16* wbl = g_WBlo + (size_t)li * 256 * 128;

    float acc[2][8][4];
    #pragma unroll
    for (int i = 0; i < 2; i++)
        #pragma unroll
        for (int j = 0; j < 8; j++)
            #pragma unroll
            for (int e = 0; e < 4; e++) acc[i][j][e] = 0.f;

    // pipeline prologue: issue chunk 0
    kv_issue_chunk(sbase, wbh, wbl, 0, 0, 0, tid);
    cp_commit();

    for (int ch = 0; ch < 8; ch++) {
        int h = ch >> 2, c = ch & 3, b = ch & 1;
        if (ch < 7) {
            kv_issue_chunk(sbase, wbh, wbl, (ch + 1) >> 2, (ch + 1) & 3, (ch + 1) & 1, tid);
            cp_commit();
            cp_wait1();
        } else {
            cp_wait0();
        }
        __syncthreads();

        uint32_t bhi = OFF_B + b * BUF_SZ;
        uint32_t blo = bhi + 10240;
        #pragma unroll
        for (int s = 0; s < 2; s++) {
            uint32_t ah[2][4], al[2][4];
            #pragma unroll
            for (int i = 0; i < 2; i++) {
                uint32_t arow = wm * 32 + i * 16 + (lane & 15);
                uint32_t akol = c * 32 + s * 16 + ((lane >> 4) << 3);
                uint32_t aoff = (arow * A_STR + akol) * 2;
                ldsm_x4(sbase + OFF_AHI + aoff, ah[i][0], ah[i][1], ah[i][2], ah[i][3]);
                ldsm_x4(sbase + OFF_ALO + aoff, al[i][0], al[i][1], al[i][2], al[i][3]);
            }
            #pragma unroll
            for (int jj = 0; jj < 4; jj++) {
                int m = lane >> 3, w8 = lane & 7;
                uint32_t bn = wn * 64 + (2 * jj + (m >> 1)) * 8 + w8;
                uint32_t bk = s * 16 + (m & 1) * 8;
                uint32_t boff = (bn * B_STR + bk) * 2;
                uint32_t bh0, bh1, bh2, bh3, bl0, bl1, bl2, bl3;
                ldsm_x4(sbase + bhi + boff, bh0, bh1, bh2, bh3);
                ldsm_x4(sbase + blo + boff, bl0, bl1, bl2, bl3);
                #pragma unroll
                for (int i = 0; i < 2; i++) {
                    mma_bf16(acc[i][2*jj],   ah[i][0], ah[i][1], ah[i][2], ah[i][3], bh0, bh1);
                    mma_bf16(acc[i][2*jj],   ah[i][0], ah[i][1], ah[i][2], ah[i][3], bl0, bl1);
                    mma_bf16(acc[i][2*jj],   al[i][0], al[i][1], al[i][2], al[i][3], bh0, bh1);
                    mma_bf16(acc[i][2*jj+1], ah[i][0], ah[i][1], ah[i][2], ah[i][3], bh2, bh3);
                    mma_bf16(acc[i][2*jj+1], ah[i][0], ah[i][1], ah[i][2], ah[i][3], bl2, bl3);
                    mma_bf16(acc[i][2*jj+1], al[i][0], al[i][1], al[i][2], al[i][3], bh2, bh3);
                }
            }
        }

        if (c == 3) {
            // epilogue for half h
            float* dstbase = h ? g_Vc : g_Kc;
            int pb = lane & 3;
            #pragma unroll
            for (int i = 0; i < 2; i++) {
                int rA = row0 + wm * 32 + i * 16 + (lane >> 2);
                int rB = rA + 8;
                if (h == 0) {
                    float cA0 = g_rcs[rA*16 + pb],     sA0 = g_rcs[rA*16 + 8 + pb];
                    float cA1 = g_rcs[rA*16 + 4 + pb], sA1 = g_rcs[rA*16 + 12 + pb];
                    float cB0 = g_rcs[rB*16 + pb],     sB0 = g_rcs[rB*16 + 8 + pb];
                    float cB1 = g_rcs[rB*16 + 4 + pb], sB1 = g_rcs[rB*16 + 12 + pb];
                    #pragma unroll
                    for (int j = 0; j < 8; j++) {
                        int col = wn * 64 + j * 8 + pb * 2;
                        float cc = (j & 1) ? cA1 : cA0, ss = (j & 1) ? sA1 : sA0;
                        float a0 = acc[i][j][0], a1 = acc[i][j][1];
                        if (rA < R) *(float2*)(dstbase + (size_t)rA * 128 + col) =
                            make_float2(a0 * cc - a1 * ss, a0 * ss + a1 * cc);
                        float cc2 = (j & 1) ? cB1 : cB0, ss2 = (j & 1) ? sB1 : sB0;
                        float b0 = acc[i][j][2], b1 = acc[i][j][3];
                        if (rB < R) *(float2*)(dstbase + (size_t)rB * 128 + col) =
                            make_float2(b0 * cc2 - b1 * ss2, b0 * ss2 + b1 * cc2);
                    }
                } else {
                    #pragma unroll
                    for (int j = 0; j < 8; j++) {
                        int col = wn * 64 + j * 8 + pb * 2;
                        if (rA < R) *(float2*)(dstbase + (size_t)rA * 128 + col) = make_float2(acc[i][j][0], acc[i][j][1]);
                        if (rB < R) *(float2*)(dstbase + (size_t)rB * 128 + col) = make_float2(acc[i][j][2], acc[i][j][3]);
                    }
                }
            }
            if (h == 0) {
                #pragma unroll
                for (int i = 0; i < 2; i++)
                    #pragma unroll
                    for (int j = 0; j < 8; j++)
                        #pragma unroll
                        for (int e = 0; e < 4; e++) acc[i][j][e] = 0.f;
            }
        }
        __syncthreads();
    }
}

// ---------------- attention (K pre-rotated; vectorized V accumulate) ----------------
__global__ void attn_kernel() {
    int q = blockIdx.x, tid = threadIdx.x;
    int lane = tid & 31, w = tid >> 5;
    __shared__ float sq[128];
    __shared__ float ssc[8 * KTOT];
    __shared__ int   skidx[KTOT];
    __shared__ float sacc[4][128];
    sq[tid] = g_q[q*DM + tid];
    for (int k = tid; k < KTOT; k += 128) skidx[k] = g_kidx[q*KTOT + k];
    __syncthreads();
    float4 qv = *(const float4*)&sq[lane * 4];
    for (int k = w; k < KTOT; k += 4) {
        int idx = skidx[k];
        float4 kv = *(const float4*)&g_Kc[(size_t)idx*DM + lane*4];
        float ps = kv.x*qv.x + kv.y*qv.y + kv.z*qv.z + kv.w*qv.w;
        ps += __shfl_xor_sync(0xffffffffu, ps, 1);
        ps += __shfl_xor_sync(0xffffffffu, ps, 2);
        if ((lane & 3) == 0) {
            int h = lane >> 2;
            int val = g_kval[q*KTOT + k];
            ssc[h*KTOT + k] = val ? ps * 0.25f : -1.0e9f;
        }
    }
    __syncthreads();
    #pragma unroll
    for (int hh = 0; hh < 2; hh++) {
        int h = w * 2 + hh;
        float mx = -3.0e38f;
        for (int k = lane; k < KTOT; k += 32) mx = fmaxf(mx, ssc[h*KTOT + k]);
        #pragma unroll
        for (int o = 16; o; o >>= 1) mx = fmaxf(mx, __shfl_xor_sync(0xffffffffu, mx, o));
        float sum = 0.f;
        for (int k = lane; k < KTOT; k += 32) {
            float e = expf(ssc[h*KTOT + k] - mx);
            ssc[h*KTOT + k] = e;
            sum += e;
        }
        #pragma unroll
        for (int o = 16; o; o >>= 1) sum += __shfl_xor_sync(0xffffffffu, sum, o);
        float inv = 1.f / sum;
        for (int k = lane; k < KTOT; k += 32) ssc[h*KTOT + k] *= inv;
    }
    __syncthreads();
    // V phase: 4 k-groups x 32 dim-threads, float4 per thread
    {
        int g4 = tid >> 5, c = tid & 31;
        int h = c >> 2;                        // head of dims 4c..4c+3
        float4 a = make_float4(0.f, 0.f, 0.f, 0.f);
        for (int k = g4; k < KTOT; k += 4) {
            int idx = skidx[k];
            float wgt = ssc[h*KTOT + k];
            float4 v = *(const float4*)&g_Vc[(size_t)idx*DM + c*4];
            a.x += wgt * v.x; a.y += wgt * v.y;
            a.z += wgt * v.z; a.w += wgt * v.w;
        }
        *(float4*)&sacc[g4][c*4] = a;
    }
    __syncthreads();
    g_o[q*DM + tid] = sacc[0][tid] + sacc[1][tid] + sacc[2][tid] + sacc[3][tid];
}

// ---------------- fused oproj + LN2 + FFN.  8 q/block, 256 threads ----------------
__global__ void ffn_kernel(const float* __restrict__ Wo,
                           const float* __restrict__ lg, const float* __restrict__ lb,
                           const float* __restrict__ W1, const float* __restrict__ b1v,
                           const float* __restrict__ W2, const float* __restrict__ b2v, int N) {
    int q0 = blockIdx.x * 8, tid = threadIdx.x;
    int col = tid & 127, half = tid >> 7;
    int lane = tid & 31, w = tid >> 5;       // w: 0..7; warps 0-3 = half 0
    __shared__ float so[8][128];
    __shared__ float sh2[8][128];
    __shared__ float st[8][512];
    __shared__ float red1[8][4], red2[8][4];
    for (int i = tid; i < 1024; i += 256) {
        int r = i >> 7, c = i & 127;
        int q = q0 + r;
        so[r][c] = (q < N) ? g_o[q*DM + c] : 0.f;
    }
    __syncthreads();
    // ---- oproj: 4 queries per half, packed f32x2 ----
    float xn[4];
    {
        ull a01 = 0ull, a23 = 0ull;
        #pragma unroll 4
        for (int i = 0; i < 128; i++) {
            ull wv = pack2(Wo[i*128 + col]);
            a01 = fma2(packab(so[half*4 + 0][i], so[half*4 + 1][i]), wv, a01);
            a23 = fma2(packab(so[half*4 + 2][i], so[half*4 + 3][i]), wv, a23);
        }
        float v[4];
        unpack2(a01, v[0], v[1]);
        unpack2(a23, v[2], v[3]);
        #pragma unroll
        for (int j = 0; j < 4; j++) {
            int q = q0 + half*4 + j;
            xn[j] = v[j] + ((q < N) ? g_x[q*DM + col] : 0.f);
            if (q < N) g_x[q*DM + col] = xn[j];
        }
    }
    // ---- LN2: reduce per query across the 128 threads of this half ----
    #pragma unroll
    for (int j = 0; j < 4; j++) {
        float s1 = xn[j], s2 = xn[j]*xn[j];
        #pragma unroll
        for (int o = 16; o; o >>= 1) {
            s1 += __shfl_xor_sync(0xffffffffu, s1, o);
            s2 += __shfl_xor_sync(0xffffffffu, s2, o);
        }
        if (lane == 0) { red1[half*4 + j][w & 3] = s1; red2[half*4 + j][w & 3] = s2; }
    }
    __syncthreads();
    float lgv = lg[col], lbv = lb[col];
    #pragma unroll
    for (int j = 0; j < 4; j++) {
        int qr = half*4 + j;
        float s1 = red1[qr][0] + red1[qr][1] + red1[qr][2] + red1[qr][3];
        float s2 = red2[qr][0] + red2[qr][1] + red2[qr][2] + red2[qr][3];
        float mean = s1 * (1.f / 128.f);
        float var  = s2 * (1.f / 128.f) - mean * mean;
        sh2[qr][col] = (xn[j] - mean) * rsqrtf(var + 1e-5f) * lgv + lbv;
    }
    __syncthreads();
    // ---- FFN1: t = gelu(h @ W1 + b1) ----
    {
        ull acc0[4], acc1[4];
        #pragma unroll
        for (int p = 0; p < 4; p++) { acc0[p] = 0ull; acc1[p] = 0ull; }
        #pragma unroll 4
        for (int i = 0; i < 128; i++) {
            ull w0 = pack2(W1[i*512 + tid]);
            ull w1 = pack2(W1[i*512 + 256 + tid]);
            #pragma unroll
            for (int p = 0; p < 4; p++) {
                ull hp = packab(sh2[2*p][i], sh2[2*p+1][i]);
                acc0[p] = fma2(hp, w0, acc0[p]);
                acc1[p] = fma2(hp, w1, acc1[p]);
            }
        }
        float bb0 = b1v[tid], bb1 = b1v[256 + tid];
        #pragma unroll
        for (int p = 0; p < 4; p++) {
            float a0, a1, c0, c1;
            unpack2(acc0[p], a0, a1);
            unpack2(acc1[p], c0, c1);
            st[2*p][tid]           = gelu_tanh(a0 + bb0);
            st[2*p][256 + tid]     = gelu_tanh(c0 + bb1);
            st[2*p + 1][tid]       = gelu_tanh(a1 + bb0);
            st[2*p + 1][256 + tid] = gelu_tanh(c1 + bb1);
        }
    }
    __syncthreads();
    // ---- FFN2: x += t @ W2 + b2 ----
    {
        ull a01 = 0ull, a23 = 0ull;
        #pragma unroll 4
        for (int i = 0; i < 512; i++) {
            ull wv = pack2(W2[i*128 + col]);
            a01 = fma2(packab(st[half*4 + 0][i], st[half*4 + 1][i]), wv, a01);
            a23 = fma2(packab(st[half*4 + 2][i], st[half*4 + 3][i]), wv, a23);
        }
        float v0, v1, v2, v3;
        unpack2(a01, v0, v1);
        unpack2(a23, v2, v3);
        float bb = b2v[col];
        int qb = q0 + half * 4;
        if (qb + 0 < N) g_x[(qb+0)*DM + col] += v0 + bb;
        if (qb + 1 < N) g_x[(qb+1)*DM + col] += v1 + bb;
        if (qb + 2 < N) g_x[(qb+2)*DM + col] += v2 + bb;
        if (qb + 3 < N) g_x[(qb+3)*DM + col] += v3 + bb;
    }
}

__global__ void logits_kernel(const float* __restrict__ fm, const float* __restrict__ qpos,
                              const int* __restrict__ qbo, int n_off,
                              const int* __restrict__ shapes, float* __restrict__ out) {
    int q = blockIdx.x, tid = threadIdx.x;
    int lane = tid & 31, w = tid >> 5;
    __shared__ float sx[128];
    __shared__ int sb;
    if (tid < 128) sx[tid] = g_x[q*DM + tid];
    if (tid == 0) sb = batch_of(q, qbo, n_off);
    __syncthreads();
    int H0 = shapes[0], W0 = shapes[1];
    float p0 = qpos[2*q], p1 = qpos[2*q+1];
    int c0 = (int)floorf(p0), c1 = (int)floorf(p1);
    float4 xv = *(const float4*)&sx[lane * 4];
    int b = sb;
    for (int pp = w; pp < 49; pp += 8) {
        int gi = c0 + pp / 7 - 3;
        int gj = c1 + pp % 7 - 3;
        bool valid = (gi >= 0 && gi < H0 && gj >= 0 && gj < W0);
        int ci = min(max(gi, 0), H0 - 1), cj = min(max(gj, 0), W0 - 1);
        const float* f = fm + ((((size_t)b * 256 + ci) * 256 + cj) * 4 + 0) * 128;
        float4 fv = *(const float4*)(f + lane * 4);
        float d = fv.x*xv.x + fv.y*xv.y + fv.z*xv.z + fv.w*xv.w;
        #pragma unroll
        for (int o = 16; o; o >>= 1) d += __shfl_xor_sync(0xffffffffu, d, o);
        if (lane == 0) out[q*49 + pp] = valid ? d : 0.f;
    }
}

// ---------------- launch ----------------
extern "C" void kernel_launch(void* const* d_in, const int* in_sizes, int n_in,
                              void* d_out, int out_size) {
    const float* queries = (const float*)d_in[0];
    const int*   qbo     = (const int*)  d_in[1];
    const float* qpos    = (const float*)d_in[2];
    const float* fm      = (const float*)d_in[3];
    const int*   shapes  = (const int*)  d_in[4];
    const float* Wq      = (const float*)d_in[5];
    const float* Wk      = (const float*)d_in[6];
    const float* Wv      = (const float*)d_in[7];
    const float* Wo      = (const float*)d_in[8];
    const float* ln1g    = (const float*)d_in[9];
    const float* ln1b    = (const float*)d_in[10];
    const float* ln2g    = (const float*)d_in[11];
    const float* ln2b    = (const float*)d_in[12];
    const float* W1      = (const float*)d_in[13];
    const float* b1      = (const float*)d_in[14];
    const float* W2      = (const float*)d_in[15];
    const float* b2      = (const float*)d_in[16];

    int N     = in_sizes[0] / DM;
    int n_off = in_sizes[1];
    int nl    = in_sizes[5] / (DM * DM);
    int B     = in_sizes[3] / (256 * 256 * 4 * DM);
    int R123  = B * PER_B;
    int R     = R123 + N * 9;
    int gridR = (R + 127) / 128;

    cudaFuncSetAttribute(kvproj_mma_kernel, cudaFuncAttributeMaxDynamicSharedMemorySize, SM_MMA_TOTAL);

    int s0 = (N * DM + 255) / 256;
    int s1 = (R + 255) / 256;
    int s2 = (nl * 256 * 128 + 255) / 256;
    int s3 = (4 * 2 * 264 + 255) / 256;
    int s4 = (N + 255) / 256;
    int o1 = s0, o2 = o1 + s1, o3 = o2 + s2, o4 = o3 + s3;
    int gridP1 = o4 + s4;

    int KB = (N * KTOT + 127) / 128;
    int RB = (R * 16 + 127) / 128;
    int gridP2 = N + KB + RB;

    prep1_kernel<<<gridP1, 256>>>(queries, qpos, qbo, n_off, shapes, Wk, Wv,
                                  N, nl, R123, R, o1, o2, o3, o4);
    prep2_kernel<<<gridP2, 128>>>(ln1g, ln1b, Wq, qpos, qbo, n_off, shapes, N, R123, R, KB);
    kvproj_mma_kernel<<<gridR, 256, SM_MMA_TOTAL>>>(fm, 0, R);
    attn_kernel<<<N, 128>>>();                      // my-index 3 -> profiled
    ffn_kernel<<<(N + 7) / 8, 256>>>(Wo, ln2g, ln2b, W1, b1, W2, b2, N);

    for (int li = 1; li < nl; li++) {
        kvproj_mma_kernel<<<gridR, 256, SM_MMA_TOTAL>>>(fm, li, R);
        ln_qproj_kernel<<<N, 128>>>(ln1g + li*DM, ln1b + li*DM, Wq + li*DM*DM);
        attn_kernel<<<N, 128>>>();
        ffn_kernel<<<(N + 7) / 8, 256>>>(Wo + li*DM*DM, ln2g + li*DM, ln2b + li*DM,
                                         W1 + li*DM*512, b1 + li*512, W2 + li*512*DM, b2 + li*DM, N);
    }
    logits_kernel<<<N, 256>>>(fm, qpos, qbo, n_off, shapes, (float*)d_out);
}

// round 12
// speedup vs baseline: 1.0211x; 1.0211x over previous
#include <cuda_runtime.h>
#include <cuda_bf16.h>
#include <math.h>
#include <stdint.h>

#define DM   128
#define NH   8
#define HD   16
#define KTOT 164          // 9 + 25 + 49 + 81
#define PER_B 21504       // 128*128 + 64*64 + 32*32
#define MAXN 2048
#define MAXROWS (2*PER_B + MAXN*9)
#define MAXL 4

typedef unsigned long long ull;

// ---------------- device scratch ----------------
__device__ float g_x  [MAXN*DM];
__device__ float g_q  [MAXN*DM];
__device__ float g_o  [MAXN*DM];
__device__ float g_qcs[MAXN*16];
__device__ int   g_kidx[MAXN*KTOT];
__device__ int   g_kval[MAXN*KTOT];
__device__ int   g_rowsrc[MAXROWS];
__device__ float g_rcs[MAXROWS*16];              // per-row RoPE cos/sin
__device__ float g_Kc[(size_t)MAXROWS*DM];
__device__ float g_Vc[(size_t)MAXROWS*DM];
__device__ __align__(16) __nv_bfloat16 g_WBhi[MAXL*256*128];   // [layer][n: Wk|Wv][k]
__device__ __align__(16) __nv_bfloat16 g_WBlo[MAXL*256*128];
__device__ float g_ktab[4*2*264*8];              // [level][axis][g+4][4cos,4sin]

__device__ __constant__ float c_invfreq[4] = {1.0f, 0.56234132519f, 0.316227766017f, 0.177827941004f};

// ---------------- helpers ----------------
__device__ __forceinline__ ull fma2(ull a, ull b, ull c) {
    ull d; asm("fma.rn.f32x2 %0, %1, %2, %3;" : "=l"(d) : "l"(a), "l"(b), "l"(c)); return d;
}
__device__ __forceinline__ ull pack2(float f) {
    ull r; asm("mov.b64 %0, {%1, %1};" : "=l"(r) : "r"(__float_as_uint(f))); return r;
}
__device__ __forceinline__ ull packab(float a, float b) {
    ull r; asm("mov.b64 %0, {%1, %2};" : "=l"(r) : "r"(__float_as_uint(a)), "r"(__float_as_uint(b))); return r;
}
__device__ __forceinline__ void unpack2(ull v, float& lo, float& hi) {
    unsigned int a, b; asm("mov.b64 {%0, %1}, %2;" : "=r"(a), "=r"(b) : "l"(v));
    lo = __uint_as_float(a); hi = __uint_as_float(b);
}
__device__ __forceinline__ float gelu_tanh(float v) {
    float u = 0.7978845608028654f * (v + 0.044715f * v * v * v);
    return 0.5f * v * (1.f + tanhf(u));
}
__device__ __forceinline__ int batch_of(int q, const int* qbo, int n_off) {
    int b = 0;
    for (int t = 1; t < n_off - 1; t++) if (q >= qbo[t]) b = t;
    return b;
}
__device__ __forceinline__ uint32_t smem_u32(const void* p) {
    uint32_t a;
    asm("{ .reg .u64 t; cvta.to.shared.u64 t, %1; cvt.u32.u64 %0, t; }" : "=r"(a) : "l"(p));
    return a;
}
__device__ __forceinline__ uint32_t bf2(float a, float b) {
    __nv_bfloat162 h = __floats2bfloat162_rn(a, b);
    return *(uint32_t*)&h;
}
__device__ __forceinline__ float bflo(float x, __nv_bfloat16 hi) {
    return x - __bfloat162float(hi);
}
__device__ __forceinline__ void ldsm_x4(uint32_t addr, uint32_t& r0, uint32_t& r1, uint32_t& r2, uint32_t& r3) {
    asm volatile("ldmatrix.sync.aligned.m8n8.x4.shared.b16 {%0,%1,%2,%3}, [%4];"
                 : "=r"(r0), "=r"(r1), "=r"(r2), "=r"(r3) : "r"(addr));
}
__device__ __forceinline__ void mma_bf16(float* c, uint32_t a0, uint32_t a1, uint32_t a2, uint32_t a3,
                                         uint32_t b0, uint32_t b1) {
    asm volatile("mma.sync.aligned.m16n8k16.row.col.f32.bf16.bf16.f32 "
                 "{%0,%1,%2,%3}, {%4,%5,%6,%7}, {%8,%9}, {%0,%1,%2,%3};"
                 : "+f"(c[0]), "+f"(c[1]), "+f"(c[2]), "+f"(c[3])
                 : "r"(a0), "r"(a1), "r"(a2), "r"(a3), "r"(b0), "r"(b1));
}
__device__ __forceinline__ void cpa16(uint32_t saddr, const void* gaddr) {
    asm volatile("cp.async.cg.shared.global [%0], [%1], 16;" :: "r"(saddr), "l"(gaddr));
}
__device__ __forceinline__ void cp_commit() { asm volatile("cp.async.commit_group;" ::: "memory"); }
__device__ __forceinline__ void cp_wait1()  { asm volatile("cp.async.wait_group 1;" ::: "memory"); }
__device__ __forceinline__ void cp_wait0()  { asm volatile("cp.async.wait_group 0;" ::: "memory"); }

// ---------------- LN1 + Qproj + RoPE body (per-query, 128 threads) ----------------
__device__ void ln_qproj_body(int q, const float* __restrict__ lg, const float* __restrict__ lb,
                              const float* __restrict__ Wq) {
    int tid = threadIdx.x;
    int lane = tid & 31, w = tid >> 5;
    __shared__ float sh[128];
    __shared__ float sraw[128];
    __shared__ float red[8];
    float x = g_x[q*DM + tid];
    float s1 = x, s2 = x * x;
    #pragma unroll
    for (int o = 16; o; o >>= 1) {
        s1 += __shfl_xor_sync(0xffffffffu, s1, o);
        s2 += __shfl_xor_sync(0xffffffffu, s2, o);
    }
    if (lane == 0) { red[w] = s1; red[4 + w] = s2; }
    __syncthreads();
    float mean = (red[0] + red[1] + red[2] + red[3]) * (1.f / 128.f);
    float var  = (red[4] + red[5] + red[6] + red[7]) * (1.f / 128.f) - mean * mean;
    sh[tid] = (x - mean) * rsqrtf(var + 1e-5f) * lg[tid] + lb[tid];
    __syncthreads();
    float acc = 0.f;
    #pragma unroll 8
    for (int i = 0; i < 128; i++) acc += sh[i] * Wq[i * DM + tid];
    sraw[tid] = acc;
    __syncthreads();
    int p = (tid >> 1) & 7;
    float c = g_qcs[q*16 + p], s = g_qcs[q*16 + 8 + p];
    float x1 = sraw[tid & ~1];
    float x2 = sraw[tid |  1];
    g_q[q*DM + tid] = (tid & 1) ? (x1 * s + x2 * c) : (x1 * c - x2 * s);
}

// ---------------- fused prep kernel #1 (256 threads) ----------------
__global__ void prep1_kernel(const float* __restrict__ queries,
                             const float* __restrict__ qpos,
                             const int* __restrict__ qbo, int n_off,
                             const int* __restrict__ shapes,
                             const float* __restrict__ Wk, const float* __restrict__ Wv,
                             int N, int nl, int R123, int R,
                             int o1, int o2, int o3, int o4) {
    int bid = blockIdx.x, tid = threadIdx.x;
    if (bid < o1) {                                      // copy_x
        int i = bid * 256 + tid;
        if (i < N * DM) g_x[i] = queries[i];
    } else if (bid < o2) {                               // rowsrc
        int e = (bid - o1) * 256 + tid;
        if (e >= R) return;
        int src;
        if (e < R123) {
            int b = e / PER_B, r = e % PER_B;
            int l, i, j;
            if (r < 16384)      { l = 1; i = r >> 7; j = r & 127; }
            else if (r < 20480) { int rr = r - 16384; l = 2; i = rr >> 6; j = rr & 63; }
            else                { int rr = r - 20480; l = 3; i = rr >> 5; j = rr & 31; }
            src = ((b * 256 + i) * 256 + j) * 4 + l;
        } else {
            int e2 = e - R123;
            int q = e2 / 9, t = e2 % 9;
            int b = batch_of(q, qbo, n_off);
            int c0 = (int)floorf(qpos[2*q]), c1 = (int)floorf(qpos[2*q+1]);
            int gi = min(max(c0 + t / 3 - 1, 0), 255);
            int gj = min(max(c1 + t % 3 - 1, 0), 255);
            src = ((b * 256 + gi) * 256 + gj) * 4 + 0;
        }
        g_rowsrc[e] = src;
    } else if (bid < o3) {                               // wt split
        int id = (bid - o2) * 256 + tid;
        if (id >= nl * 256 * 128) return;
        int li = id / (256 * 128);
        int r  = id % (256 * 128);
        int n = r / 128, k = r % 128;
        float w = (n < 128) ? Wk[li*DM*DM + k*DM + n] : Wv[li*DM*DM + k*DM + (n - 128)];
        __nv_bfloat16 hi = __float2bfloat16(w);
        g_WBhi[id] = hi;
        g_WBlo[id] = __float2bfloat16(w - __bfloat162float(hi));
    } else if (bid < o4) {                               // ktab
        int id = (bid - o3) * 256 + tid;
        if (id >= 4 * 2 * 264) return;
        int l = id / (2 * 264);
        int axis = (id / 264) & 1;
        int g = (id % 264) - 4;
        float scale = (float)shapes[2*l + axis] / (float)shapes[axis];
        float kp = ((float)g + 0.5f) / scale;
        float* t = &g_ktab[(size_t)id * 8];
        #pragma unroll
        for (int f = 0; f < 4; f++) {
            float a = kp * c_invfreq[f];
            t[f] = cosf(a);
            t[4 + f] = sinf(a);
        }
    } else {                                             // qcs
        int q = (bid - o4) * 256 + tid;
        if (q >= N) return;
        float p0 = qpos[2*q], p1 = qpos[2*q+1];
        float* cs = &g_qcs[q * 16];
        #pragma unroll
        for (int f = 0; f < 4; f++) {
            float a0 = p0 * c_invfreq[f];
            float a1 = p1 * c_invfreq[f];
            cs[f]      = cosf(a0);  cs[8  + f] = sinf(a0);
            cs[4 + f]  = cosf(a1);  cs[12 + f] = sinf(a1);
        }
    }
}

// ---------------- fused prep kernel #2 (128 threads) ----------------
__global__ void prep2_kernel(const float* __restrict__ lg, const float* __restrict__ lb,
                             const float* __restrict__ Wq,
                             const float* __restrict__ qpos,
                             const int* __restrict__ qbo, int n_off,
                             const int* __restrict__ shapes,
                             int N, int R123, int R, int KB) {
    int bid = blockIdx.x, tid = threadIdx.x;
    if (bid < N) {
        ln_qproj_body(bid, lg, lb, Wq);
    } else if (bid < N + KB) {                           // build_keys (idx + valid only)
        int id = (bid - N) * 128 + tid;
        if (id >= N * KTOT) return;
        int q = id / KTOT, k = id % KTOT;
        int l, t, d;
        if      (k < 9)  { l = 0; t = k;      d = 3; }
        else if (k < 34) { l = 1; t = k - 9;  d = 5; }
        else if (k < 83) { l = 2; t = k - 34; d = 7; }
        else             { l = 3; t = k - 83; d = 9; }
        int Hl = shapes[2*l], Wl = shapes[2*l+1];
        float sh = (float)Hl / (float)shapes[0];
        float sw = (float)Wl / (float)shapes[1];
        int c0 = (int)floorf(qpos[2*q] * sh), c1 = (int)floorf(qpos[2*q+1] * sw);
        int gi = c0 + t / d - d / 2;
        int gj = c1 + t % d - d / 2;
        int valid = (gi >= 0 && gi < Hl && gj >= 0 && gj < Wl);
        int ci = min(max(gi, 0), Hl - 1), cj = min(max(gj, 0), Wl - 1);
        int b = batch_of(q, qbo, n_off);
        int idx;
        if (l == 0) idx = R123 + q * 9 + t;
        else {
            int base = (l == 1) ? 0 : (l == 2) ? 16384 : 20480;
            idx = b * PER_B + base + ci * Wl + cj;
        }
        g_kidx[id] = idx;
        g_kval[id] = valid;
    } else {                                             // build_rcs
        int e = (bid - N - KB) * 128 + tid;
        if (e >= R * 16) return;
        int row = e >> 4, idx = e & 15;
        int l, gi, gj;
        if (row < R123) {
            int r = row % PER_B;
            if (r < 16384)      { l = 1; gi = r >> 7; gj = r & 127; }
            else if (r < 20480) { int rr = r - 16384; l = 2; gi = rr >> 6; gj = rr & 63; }
            else                { int rr = r - 20480; l = 3; gi = rr >> 5; gj = rr & 31; }
        } else {
            int e2 = row - R123;
            int q = e2 / 9, t = e2 % 9;
            l = 0;
            gi = min(max((int)floorf(qpos[2*q])   + t / 3 - 1, 0), 255);
            gj = min(max((int)floorf(qpos[2*q+1]) + t % 3 - 1, 0), 255);
        }
        int trig = idx >> 3, p = idx & 7, axis = p >> 2, f = p & 3;
        int g = axis ? gj : gi;
        g_rcs[e] = g_ktab[(size_t)((l * 2 + axis) * 264 + (g + 4)) * 8 + trig * 4 + f];
    }
}

__global__ void ln_qproj_kernel(const float* __restrict__ lg, const float* __restrict__ lb,
                                const float* __restrict__ Wq) {
    ln_qproj_body(blockIdx.x, lg, lb, Wq);
}

// ---------------- mma.sync KV projection (cp.async double-buffered B; rope fused) ----------------
#define A_STR 136
#define B_STR 40
#define OFF_AHI 0
#define OFF_ALO 34816
#define OFF_B   69632
#define BUF_SZ  20480            // one buffer: BHI 10240 + BLO 10240
#define SM_MMA_TOTAL (OFF_B + 2*BUF_SZ)   // 110592

__device__ __forceinline__ void kv_issue_chunk(uint32_t sbase,
                                               const __nv_bfloat16* __restrict__ wbh,
                                               const __nv_bfloat16* __restrict__ wbl,
                                               int h, int c, int b, int tid) {
    #pragma unroll
    for (int it = 0; it < 2; it++) {
        int idx = tid + 256 * it;            // 0..511
        int n = idx >> 2, kk = (idx & 3) * 8;
        const __nv_bfloat16* gh = wbh + ((size_t)(h * 128 + n)) * 128 + c * 32 + kk;
        const __nv_bfloat16* gl = wbl + ((size_t)(h * 128 + n)) * 128 + c * 32 + kk;
        uint32_t so_ = sbase + OFF_B + b * BUF_SZ + (uint32_t)(n * B_STR + kk) * 2;
        cpa16(so_, gh);
        cpa16(so_ + 10240, gl);
    }
}

__global__ void __launch_bounds__(256, 2)
kvproj_mma_kernel(const float* __restrict__ fm, int li, int R) {
    extern __shared__ char smem[];
    uint32_t sbase = smem_u32(smem);
    int tid = threadIdx.x;
    int wid = tid >> 5, lane = tid & 31;
    int wm = wid & 3, wn = wid >> 2;
    int row0 = blockIdx.x * 128;

    // ---- A gather + bf16 hi/lo split ----
    #pragma unroll
    for (int it = 0; it < 16; it++) {
        int idx = tid + 256 * it;
        int r = idx >> 5, c4 = idx & 31;
        int row = row0 + r; if (row >= R) row = R - 1;
        int src = g_rowsrc[row];
        float4 v = *(const float4*)(fm + (size_t)src * 128 + c4 * 4);
        __nv_bfloat16 hx = __float2bfloat16(v.x);
        __nv_bfloat16 hy = __float2bfloat16(v.y);
        __nv_bfloat16 hz = __float2bfloat16(v.z);
        __nv_bfloat16 hw = __float2bfloat16(v.w);
        uint32_t h01 = ((uint32_t)*(uint16_t*)&hy << 16) | *(uint16_t*)&hx;
        uint32_t h23 = ((uint32_t)*(uint16_t*)&hw << 16) | *(uint16_t*)&hz;
        uint32_t l01 = bf2(bflo(v.x, hx), bflo(v.y, hy));
        uint32_t l23 = bf2(bflo(v.z, hz), bflo(v.w, hw));
        uint32_t off = (uint32_t)(r * A_STR + c4 * 4) * 2;
        *(uint2*)(smem + OFF_AHI + off) = make_uint2(h01, h23);
        *(uint2*)(smem + OFF_ALO + off) = make_uint2(l01, l23);
    }

    const __nv_bfloat16* wbh = g_WBhi + (size_t)li * 256 * 128;
    const __nv_bfloat16* wbl = g_WBlo + (size_t)li * 256 * 128;

    float acc[2][8][4];
    #pragma unroll
    for (int i = 0; i < 2; i++)
        #pragma unroll
        for (int j = 0; j < 8; j++)
            #pragma unroll
            for (int e = 0; e < 4; e++) acc[i][j][e] = 0.f;

    kv_issue_chunk(sbase, wbh, wbl, 0, 0, 0, tid);
    cp_commit();

    for (int ch = 0; ch < 8; ch++) {
        int h = ch >> 2, c = ch & 3, b = ch & 1;
        if (ch < 7) {
            kv_issue_chunk(sbase, wbh, wbl, (ch + 1) >> 2, (ch + 1) & 3, (ch + 1) & 1, tid);
            cp_commit();
            cp_wait1();
        } else {
            cp_wait0();
        }
        __syncthreads();

        uint32_t bhi = OFF_B + b * BUF_SZ;
        uint32_t blo = bhi + 10240;
        #pragma unroll
        for (int s = 0; s < 2; s++) {
            uint32_t ah[2][4], al[2][4];
            #pragma unroll
            for (int i = 0; i < 2; i++) {
                uint32_t arow = wm * 32 + i * 16 + (lane & 15);
                uint32_t akol = c * 32 + s * 16 + ((lane >> 4) << 3);
                uint32_t aoff = (arow * A_STR + akol) * 2;
                ldsm_x4(sbase + OFF_AHI + aoff, ah[i][0], ah[i][1], ah[i][2], ah[i][3]);
                ldsm_x4(sbase + OFF_ALO + aoff, al[i][0], al[i][1], al[i][2], al[i][3]);
            }
            #pragma unroll
            for (int jj = 0; jj < 4; jj++) {
                int m = lane >> 3, w8 = lane & 7;
                uint32_t bn = wn * 64 + (2 * jj + (m >> 1)) * 8 + w8;
                uint32_t bk = s * 16 + (m & 1) * 8;
                uint32_t boff = (bn * B_STR + bk) * 2;
                uint32_t bh0, bh1, bh2, bh3, bl0, bl1, bl2, bl3;
                ldsm_x4(sbase + bhi + boff, bh0, bh1, bh2, bh3);
                ldsm_x4(sbase + blo + boff, bl0, bl1, bl2, bl3);
                #pragma unroll
                for (int i = 0; i < 2; i++) {
                    mma_bf16(acc[i][2*jj],   ah[i][0], ah[i][1], ah[i][2], ah[i][3], bh0, bh1);
                    mma_bf16(acc[i][2*jj],   ah[i][0], ah[i][1], ah[i][2], ah[i][3], bl0, bl1);
                    mma_bf16(acc[i][2*jj],   al[i][0], al[i][1], al[i][2], al[i][3], bh0, bh1);
                    mma_bf16(acc[i][2*jj+1], ah[i][0], ah[i][1], ah[i][2], ah[i][3], bh2, bh3);
                    mma_bf16(acc[i][2*jj+1], ah[i][0], ah[i][1], ah[i][2], ah[i][3], bl2, bl3);
                    mma_bf16(acc[i][2*jj+1], al[i][0], al[i][1], al[i][2], al[i][3], bh2, bh3);
                }
            }
        }

        if (c == 3) {
            float* dstbase = h ? g_Vc : g_Kc;
            int pb = lane & 3;
            #pragma unroll
            for (int i = 0; i < 2; i++) {
                int rA = row0 + wm * 32 + i * 16 + (lane >> 2);
                int rB = rA + 8;
                if (h == 0) {
                    float cA0 = g_rcs[rA*16 + pb],     sA0 = g_rcs[rA*16 + 8 + pb];
                    float cA1 = g_rcs[rA*16 + 4 + pb], sA1 = g_rcs[rA*16 + 12 + pb];
                    float cB0 = g_rcs[rB*16 + pb],     sB0 = g_rcs[rB*16 + 8 + pb];
                    float cB1 = g_rcs[rB*16 + 4 + pb], sB1 = g_rcs[rB*16 + 12 + pb];
                    #pragma unroll
                    for (int j = 0; j < 8; j++) {
                        int col = wn * 64 + j * 8 + pb * 2;
                        float cc = (j & 1) ? cA1 : cA0, ss = (j & 1) ? sA1 : sA0;
                        float a0 = acc[i][j][0], a1 = acc[i][j][1];
                        if (rA < R) *(float2*)(dstbase + (size_t)rA * 128 + col) =
                            make_float2(a0 * cc - a1 * ss, a0 * ss + a1 * cc);
                        float cc2 = (j & 1) ? cB1 : cB0, ss2 = (j & 1) ? sB1 : sB0;
                        float b0 = acc[i][j][2], b1 = acc[i][j][3];
                        if (rB < R) *(float2*)(dstbase + (size_t)rB * 128 + col) =
                            make_float2(b0 * cc2 - b1 * ss2, b0 * ss2 + b1 * cc2);
                    }
                } else {
                    #pragma unroll
                    for (int j = 0; j < 8; j++) {
                        int col = wn * 64 + j * 8 + pb * 2;
                        if (rA < R) *(float2*)(dstbase + (size_t)rA * 128 + col) = make_float2(acc[i][j][0], acc[i][j][1]);
                        if (rB < R) *(float2*)(dstbase + (size_t)rB * 128 + col) = make_float2(acc[i][j][2], acc[i][j][3]);
                    }
                }
            }
            if (h == 0) {
                #pragma unroll
                for (int i = 0; i < 2; i++)
                    #pragma unroll
                    for (int j = 0; j < 8; j++)
                        #pragma unroll
                        for (int e = 0; e < 4; e++) acc[i][j][e] = 0.f;
            }
        }
        __syncthreads();
    }
}

// ---------------- attention (R10 version: K pre-rotated, scalar V loop) ----------------
__global__ void attn_kernel() {
    int q = blockIdx.x, tid = threadIdx.x;
    int lane = tid & 31, w = tid >> 5;
    __shared__ float sq[128];
    __shared__ float ssc[8 * KTOT];
    __shared__ int   skidx[KTOT];
    sq[tid] = g_q[q*DM + tid];
    for (int k = tid; k < KTOT; k += 128) skidx[k] = g_kidx[q*KTOT + k];
    __syncthreads();
    float4 qv = *(const float4*)&sq[lane * 4];
    for (int k = w; k < KTOT; k += 4) {
        int idx = skidx[k];
        float4 kv = *(const float4*)&g_Kc[(size_t)idx*DM + lane*4];
        float ps = kv.x*qv.x + kv.y*qv.y + kv.z*qv.z + kv.w*qv.w;
        ps += __shfl_xor_sync(0xffffffffu, ps, 1);
        ps += __shfl_xor_sync(0xffffffffu, ps, 2);
        if ((lane & 3) == 0) {
            int h = lane >> 2;
            int val = g_kval[q*KTOT + k];
            ssc[h*KTOT + k] = val ? ps * 0.25f : -1.0e9f;
        }
    }
    __syncthreads();
    #pragma unroll
    for (int hh = 0; hh < 2; hh++) {
        int h = w * 2 + hh;
        float mx = -3.0e38f;
        for (int k = lane; k < KTOT; k += 32) mx = fmaxf(mx, ssc[h*KTOT + k]);
        #pragma unroll
        for (int o = 16; o; o >>= 1) mx = fmaxf(mx, __shfl_xor_sync(0xffffffffu, mx, o));
        float sum = 0.f;
        for (int k = lane; k < KTOT; k += 32) {
            float e = expf(ssc[h*KTOT + k] - mx);
            ssc[h*KTOT + k] = e;
            sum += e;
        }
        #pragma unroll
        for (int o = 16; o; o >>= 1) sum += __shfl_xor_sync(0xffffffffu, sum, o);
        float inv = 1.f / sum;
        for (int k = lane; k < KTOT; k += 32) ssc[h*KTOT + k] *= inv;
    }
    __syncthreads();
    int h = tid >> 4;
    float acc = 0.f;
    #pragma unroll 4
    for (int k = 0; k < KTOT; k++)
        acc += ssc[h*KTOT + k] * g_Vc[(size_t)skidx[k]*DM + tid];
    g_o[q*DM + tid] = acc;
}

// ---------------- fused oproj + LN2 + FFN.  8 q/block, 256 threads ----------------
__global__ void ffn_kernel(const float* __restrict__ Wo,
                           const float* __restrict__ lg, const float* __restrict__ lb,
                           const float* __restrict__ W1, const float* __restrict__ b1v,
                           const float* __restrict__ W2, const float* __restrict__ b2v, int N) {
    int q0 = blockIdx.x * 8, tid = threadIdx.x;
    int col = tid & 127, half = tid >> 7;
    int lane = tid & 31, w = tid >> 5;       // w: 0..7; warps 0-3 = half 0
    __shared__ float so[8][128];
    __shared__ float sh2[8][128];
    __shared__ float st[8][512];
    __shared__ float red1[8][4], red2[8][4];
    for (int i = tid; i < 1024; i += 256) {
        int r = i >> 7, c = i & 127;
        int q = q0 + r;
        so[r][c] = (q < N) ? g_o[q*DM + c] : 0.f;
    }
    __syncthreads();
    float xn[4];
    {
        ull a01 = 0ull, a23 = 0ull;
        #pragma unroll 4
        for (int i = 0; i < 128; i++) {
            ull wv = pack2(Wo[i*128 + col]);
            a01 = fma2(packab(so[half*4 + 0][i], so[half*4 + 1][i]), wv, a01);
            a23 = fma2(packab(so[half*4 + 2][i], so[half*4 + 3][i]), wv, a23);
        }
        float v[4];
        unpack2(a01, v[0], v[1]);
        unpack2(a23, v[2], v[3]);
        #pragma unroll
        for (int j = 0; j < 4; j++) {
            int q = q0 + half*4 + j;
            xn[j] = v[j] + ((q < N) ? g_x[q*DM + col] : 0.f);
            if (q < N) g_x[q*DM + col] = xn[j];
        }
    }
    #pragma unroll
    for (int j = 0; j < 4; j++) {
        float s1 = xn[j], s2 = xn[j]*xn[j];
        #pragma unroll
        for (int o = 16; o; o >>= 1) {
            s1 += __shfl_xor_sync(0xffffffffu, s1, o);
            s2 += __shfl_xor_sync(0xffffffffu, s2, o);
        }
        if (lane == 0) { red1[half*4 + j][w & 3] = s1; red2[half*4 + j][w & 3] = s2; }
    }
    __syncthreads();
    float lgv = lg[col], lbv = lb[col];
    #pragma unroll
    for (int j = 0; j < 4; j++) {
        int qr = half*4 + j;
        float s1 = red1[qr][0] + red1[qr][1] + red1[qr][2] + red1[qr][3];
        float s2 = red2[qr][0] + red2[qr][1] + red2[qr][2] + red2[qr][3];
        float mean = s1 * (1.f / 128.f);
        float var  = s2 * (1.f / 128.f) - mean * mean;
        sh2[qr][col] = (xn[j] - mean) * rsqrtf(var + 1e-5f) * lgv + lbv;
    }
    __syncthreads();
    {
        ull acc0[4], acc1[4];
        #pragma unroll
        for (int p = 0; p < 4; p++) { acc0[p] = 0ull; acc1[p] = 0ull; }
        #pragma unroll 4
        for (int i = 0; i < 128; i++) {
            ull w0 = pack2(W1[i*512 + tid]);
            ull w1 = pack2(W1[i*512 + 256 + tid]);
            #pragma unroll
            for (int p = 0; p < 4; p++) {
                ull hp = packab(sh2[2*p][i], sh2[2*p+1][i]);
                acc0[p] = fma2(hp, w0, acc0[p]);
                acc1[p] = fma2(hp, w1, acc1[p]);
            }
        }
        float bb0 = b1v[tid], bb1 = b1v[256 + tid];
        #pragma unroll
        for (int p = 0; p < 4; p++) {
            float a0, a1, c0, c1;
            unpack2(acc0[p], a0, a1);
            unpack2(acc1[p], c0, c1);
            st[2*p][tid]           = gelu_tanh(a0 + bb0);
            st[2*p][256 + tid]     = gelu_tanh(c0 + bb1);
            st[2*p + 1][tid]       = gelu_tanh(a1 + bb0);
            st[2*p + 1][256 + tid] = gelu_tanh(c1 + bb1);
        }
    }
    __syncthreads();
    {
        ull a01 = 0ull, a23 = 0ull;
        #pragma unroll 4
        for (int i = 0; i < 512; i++) {
            ull wv = pack2(W2[i*128 + col]);
            a01 = fma2(packab(st[half*4 + 0][i], st[half*4 + 1][i]), wv, a01);
            a23 = fma2(packab(st[half*4 + 2][i], st[half*4 + 3][i]), wv, a23);
        }
        float v0, v1, v2, v3;
        unpack2(a01, v0, v1);
        unpack2(a23, v2, v3);
        float bb = b2v[col];
        int qb = q0 + half * 4;
        if (qb + 0 < N) g_x[(qb+0)*DM + col] += v0 + bb;
        if (qb + 1 < N) g_x[(qb+1)*DM + col] += v1 + bb;
        if (qb + 2 < N) g_x[(qb+2)*DM + col] += v2 + bb;
        if (qb + 3 < N) g_x[(qb+3)*DM + col] += v3 + bb;
    }
}

__global__ void logits_kernel(const float* __restrict__ fm, const float* __restrict__ qpos,
                              const int* __restrict__ qbo, int n_off,
                              const int* __restrict__ shapes, float* __restrict__ out) {
    int q = blockIdx.x, tid = threadIdx.x;
    int lane = tid & 31, w = tid >> 5;
    __shared__ float sx[128];
    __shared__ int sb;
    if (tid < 128) sx[tid] = g_x[q*DM + tid];
    if (tid == 0) sb = batch_of(q, qbo, n_off);
    __syncthreads();
    int H0 = shapes[0], W0 = shapes[1];
    float p0 = qpos[2*q], p1 = qpos[2*q+1];
    int c0 = (int)floorf(p0), c1 = (int)floorf(p1);
    float4 xv = *(const float4*)&sx[lane * 4];
    int b = sb;
    for (int pp = w; pp < 49; pp += 8) {
        int gi = c0 + pp / 7 - 3;
        int gj = c1 + pp % 7 - 3;
        bool valid = (gi >= 0 && gi < H0 && gj >= 0 && gj < W0);
        int ci = min(max(gi, 0), H0 - 1), cj = min(max(gj, 0), W0 - 1);
        const float* f = fm + ((((size_t)b * 256 + ci) * 256 + cj) * 4 + 0) * 128;
        float4 fv = *(const float4*)(f + lane * 4);
        float d = fv.x*xv.x + fv.y*xv.y + fv.z*xv.z + fv.w*xv.w;
        #pragma unroll
        for (int o = 16; o; o >>= 1) d += __shfl_xor_sync(0xffffffffu, d, o);
        if (lane == 0) out[q*49 + pp] = valid ? d : 0.f;
    }
}

// ---------------- launch ----------------
extern "C" void kernel_launch(void* const* d_in, const int* in_sizes, int n_in,
                              void* d_out, int out_size) {
    const float* queries = (const float*)d_in[0];
    const int*   qbo     = (const int*)  d_in[1];
    const float* qpos    = (const float*)d_in[2];
    const float* fm      = (const float*)d_in[3];
    const int*   shapes  = (const int*)  d_in[4];
    const float* Wq      = (const float*)d_in[5];
    const float* Wk      = (const float*)d_in[6];
    const float* Wv      = (const float*)d_in[7];
    const float* Wo      = (const float*)d_in[8];
    const float* ln1g    = (const float*)d_in[9];
    const float* ln1b    = (const float*)d_in[10];
    const float* ln2g    = (const float*)d_in[11];
    const float* ln2b    = (const float*)d_in[12];
    const float* W1      = (const float*)d_in[13];
    const float* b1      = (const float*)d_in[14];
    const float* W2      = (const float*)d_in[15];
    const float* b2      = (const float*)d_in[16];

    int N     = in_sizes[0] / DM;
    int n_off = in_sizes[1];
    int nl    = in_sizes[5] / (DM * DM);
    int B     = in_sizes[3] / (256 * 256 * 4 * DM);
    int R123  = B * PER_B;
    int R     = R123 + N * 9;
    int gridR = (R + 127) / 128;

    cudaFuncSetAttribute(kvproj_mma_kernel, cudaFuncAttributeMaxDynamicSharedMemorySize, SM_MMA_TOTAL);

    int s0 = (N * DM + 255) / 256;
    int s1 = (R + 255) / 256;
    int s2 = (nl * 256 * 128 + 255) / 256;
    int s3 = (4 * 2 * 264 + 255) / 256;
    int s4 = (N + 255) / 256;
    int o1 = s0, o2 = o1 + s1, o3 = o2 + s2, o4 = o3 + s3;
    int gridP1 = o4 + s4;

    int KB = (N * KTOT + 127) / 128;
    int RB = (R * 16 + 127) / 128;
    int gridP2 = N + KB + RB;

    prep1_kernel<<<gridP1, 256>>>(queries, qpos, qbo, n_off, shapes, Wk, Wv,
                                  N, nl, R123, R, o1, o2, o3, o4);
    prep2_kernel<<<gridP2, 128>>>(ln1g, ln1b, Wq, qpos, qbo, n_off, shapes, N, R123, R, KB);
    kvproj_mma_kernel<<<gridR, 256, SM_MMA_TOTAL>>>(fm, 0, R);
    attn_kernel<<<N, 128>>>();                      // my-index 3 -> profiled
    ffn_kernel<<<(N + 7) / 8, 256>>>(Wo, ln2g, ln2b, W1, b1, W2, b2, N);

    for (int li = 1; li < nl; li++) {
        kvproj_mma_kernel<<<gridR, 256, SM_MMA_TOTAL>>>(fm, li, R);
        ln_qproj_kernel<<<N, 128>>>(ln1g + li*DM, ln1b + li*DM, Wq + li*DM*DM);
        attn_kernel<<<N, 128>>>();
        ffn_kernel<<<(N + 7) / 8, 256>>>(Wo + li*DM*DM, ln2g + li*DM, ln2b + li*DM,
                                         W1 + li*DM*512, b1 + li*512, W2 + li*512*DM, b2 + li*DM, N);
    }
    logits_kernel<<<N, 256>>>(fm, qpos, qbo, n_off, shapes, (float*)d_out);
}

// round 13
// speedup vs baseline: 1.0345x; 1.0131x over previous
#include <cuda_runtime.h>
#include <cuda_bf16.h>
#include <math.h>
#include <stdint.h>

#define DM   128
#define NH   8
#define HD   16
#define KTOT 164          // 9 + 25 + 49 + 81
#define PER_B 21504       // 128*128 + 64*64 + 32*32
#define MAXN 2048
#define MAXROWS (2*PER_B + MAXN*9)
#define MAXL 4

typedef unsigned long long ull;

// ---------------- device scratch ----------------
__device__ float g_x  [MAXN*DM];
__device__ float g_q  [MAXN*DM];
__device__ float g_o  [MAXN*DM];
__device__ float g_h  [MAXN*DM];
__device__ float g_t  [MAXN*512];
__device__ float g_qcs[MAXN*16];
__device__ int   g_kidx[MAXN*KTOT];              // bit31 set = INVALID key
__device__ int   g_rowsrc[MAXROWS];
__device__ float g_rcs[MAXROWS*16];              // per-row RoPE cos/sin
__device__ float g_Kc[(size_t)MAXROWS*DM];
__device__ float g_Vc[(size_t)MAXROWS*DM];
__device__ __align__(16) __nv_bfloat16 g_WBhi[MAXL*256*128];   // [layer][n: Wk|Wv][k]
__device__ __align__(16) __nv_bfloat16 g_WBlo[MAXL*256*128];
__device__ float g_ktab[4*2*264*8];              // [level][axis][g+4][4cos,4sin]

__device__ __constant__ float c_invfreq[4] = {1.0f, 0.56234132519f, 0.316227766017f, 0.177827941004f};

// ---------------- helpers ----------------
__device__ __forceinline__ ull fma2(ull a, ull b, ull c) {
    ull d; asm("fma.rn.f32x2 %0, %1, %2, %3;" : "=l"(d) : "l"(a), "l"(b), "l"(c)); return d;
}
__device__ __forceinline__ ull pack2(float f) {
    ull r; asm("mov.b64 %0, {%1, %1};" : "=l"(r) : "r"(__float_as_uint(f))); return r;
}
__device__ __forceinline__ ull packab(float a, float b) {
    ull r; asm("mov.b64 %0, {%1, %2};" : "=l"(r) : "r"(__float_as_uint(a)), "r"(__float_as_uint(b))); return r;
}
__device__ __forceinline__ void unpack2(ull v, float& lo, float& hi) {
    unsigned int a, b; asm("mov.b64 {%0, %1}, %2;" : "=r"(a), "=r"(b) : "l"(v));
    lo = __uint_as_float(a); hi = __uint_as_float(b);
}
__device__ __forceinline__ float gelu_tanh(float v) {
    float u = 0.7978845608028654f * (v + 0.044715f * v * v * v);
    return 0.5f * v * (1.f + tanhf(u));
}
__device__ __forceinline__ int batch_of(int q, const int* qbo, int n_off) {
    int b = 0;
    for (int t = 1; t < n_off - 1; t++) if (q >= qbo[t]) b = t;
    return b;
}
__device__ __forceinline__ uint32_t smem_u32(const void* p) {
    uint32_t a;
    asm("{ .reg .u64 t; cvta.to.shared.u64 t, %1; cvt.u32.u64 %0, t; }" : "=r"(a) : "l"(p));
    return a;
}
__device__ __forceinline__ uint32_t bf2(float a, float b) {
    __nv_bfloat162 h = __floats2bfloat162_rn(a, b);
    return *(uint32_t*)&h;
}
__device__ __forceinline__ float bflo(float x, __nv_bfloat16 hi) {
    return x - __bfloat162float(hi);
}
__device__ __forceinline__ void ldsm_x4(uint32_t addr, uint32_t& r0, uint32_t& r1, uint32_t& r2, uint32_t& r3) {
    asm volatile("ldmatrix.sync.aligned.m8n8.x4.shared.b16 {%0,%1,%2,%3}, [%4];"
                 : "=r"(r0), "=r"(r1), "=r"(r2), "=r"(r3) : "r"(addr));
}
__device__ __forceinline__ void mma_bf16(float* c, uint32_t a0, uint32_t a1, uint32_t a2, uint32_t a3,
                                         uint32_t b0, uint32_t b1) {
    asm volatile("mma.sync.aligned.m16n8k16.row.col.f32.bf16.bf16.f32 "
                 "{%0,%1,%2,%3}, {%4,%5,%6,%7}, {%8,%9}, {%0,%1,%2,%3};"
                 : "+f"(c[0]), "+f"(c[1]), "+f"(c[2]), "+f"(c[3])
                 : "r"(a0), "r"(a1), "r"(a2), "r"(a3), "r"(b0), "r"(b1));
}

// ---------------- LN1 + Qproj + RoPE body (per-query, 128 threads) ----------------
__device__ void ln_qproj_body(int q, const float* __restrict__ lg, const float* __restrict__ lb,
                              const float* __restrict__ Wq) {
    int tid = threadIdx.x;
    int lane = tid & 31, w = tid >> 5;
    __shared__ float sh[128];
    __shared__ float sraw[128];
    __shared__ float red[8];
    float x = g_x[q*DM + tid];
    float s1 = x, s2 = x * x;
    #pragma unroll
    for (int o = 16; o; o >>= 1) {
        s1 += __shfl_xor_sync(0xffffffffu, s1, o);
        s2 += __shfl_xor_sync(0xffffffffu, s2, o);
    }
    if (lane == 0) { red[w] = s1; red[4 + w] = s2; }
    __syncthreads();
    float mean = (red[0] + red[1] + red[2] + red[3]) * (1.f / 128.f);
    float var  = (red[4] + red[5] + red[6] + red[7]) * (1.f / 128.f) - mean * mean;
    sh[tid] = (x - mean) * rsqrtf(var + 1e-5f) * lg[tid] + lb[tid];
    __syncthreads();
    float acc = 0.f;
    #pragma unroll 8
    for (int i = 0; i < 128; i++) acc += sh[i] * Wq[i * DM + tid];
    sraw[tid] = acc;
    __syncthreads();
    int p = (tid >> 1) & 7;
    float c = g_qcs[q*16 + p], s = g_qcs[q*16 + 8 + p];
    float x1 = sraw[tid & ~1];
    float x2 = sraw[tid |  1];
    g_q[q*DM + tid] = (tid & 1) ? (x1 * s + x2 * c) : (x1 * c - x2 * s);
}

// ---------------- fused prep kernel #1 (256 threads) ----------------
__global__ void prep1_kernel(const float* __restrict__ queries,
                             const float* __restrict__ qpos,
                             const int* __restrict__ qbo, int n_off,
                             const int* __restrict__ shapes,
                             const float* __restrict__ Wk, const float* __restrict__ Wv,
                             int N, int nl, int R123, int R,
                             int o1, int o2, int o3, int o4) {
    int bid = blockIdx.x, tid = threadIdx.x;
    if (bid < o1) {                                      // copy_x
        int i = bid * 256 + tid;
        if (i < N * DM) g_x[i] = queries[i];
    } else if (bid < o2) {                               // rowsrc
        int e = (bid - o1) * 256 + tid;
        if (e >= R) return;
        int src;
        if (e < R123) {
            int b = e / PER_B, r = e % PER_B;
            int l, i, j;
            if (r < 16384)      { l = 1; i = r >> 7; j = r & 127; }
            else if (r < 20480) { int rr = r - 16384; l = 2; i = rr >> 6; j = rr & 63; }
            else                { int rr = r - 20480; l = 3; i = rr >> 5; j = rr & 31; }
            src = ((b * 256 + i) * 256 + j) * 4 + l;
        } else {
            int e2 = e - R123;
            int q = e2 / 9, t = e2 % 9;
            int b = batch_of(q, qbo, n_off);
            int c0 = (int)floorf(qpos[2*q]), c1 = (int)floorf(qpos[2*q+1]);
            int gi = min(max(c0 + t / 3 - 1, 0), 255);
            int gj = min(max(c1 + t % 3 - 1, 0), 255);
            src = ((b * 256 + gi) * 256 + gj) * 4 + 0;
        }
        g_rowsrc[e] = src;
    } else if (bid < o3) {                               // wt split
        int id = (bid - o2) * 256 + tid;
        if (id >= nl * 256 * 128) return;
        int li = id / (256 * 128);
        int r  = id % (256 * 128);
        int n = r / 128, k = r % 128;
        float w = (n < 128) ? Wk[li*DM*DM + k*DM + n] : Wv[li*DM*DM + k*DM + (n - 128)];
        __nv_bfloat16 hi = __float2bfloat16(w);
        g_WBhi[id] = hi;
        g_WBlo[id] = __float2bfloat16(w - __bfloat162float(hi));
    } else if (bid < o4) {                               // ktab
        int id = (bid - o3) * 256 + tid;
        if (id >= 4 * 2 * 264) return;
        int l = id / (2 * 264);
        int axis = (id / 264) & 1;
        int g = (id % 264) - 4;
        float scale = (float)shapes[2*l + axis] / (float)shapes[axis];
        float kp = ((float)g + 0.5f) / scale;
        float* t = &g_ktab[(size_t)id * 8];
        #pragma unroll
        for (int f = 0; f < 4; f++) {
            float a = kp * c_invfreq[f];
            t[f] = cosf(a);
            t[4 + f] = sinf(a);
        }
    } else {                                             // qcs
        int q = (bid - o4) * 256 + tid;
        if (q >= N) return;
        float p0 = qpos[2*q], p1 = qpos[2*q+1];
        float* cs = &g_qcs[q * 16];
        #pragma unroll
        for (int f = 0; f < 4; f++) {
            float a0 = p0 * c_invfreq[f];
            float a1 = p1 * c_invfreq[f];
            cs[f]      = cosf(a0);  cs[8  + f] = sinf(a0);
            cs[4 + f]  = cosf(a1);  cs[12 + f] = sinf(a1);
        }
    }
}

// ---------------- fused prep kernel #2 (128 threads) ----------------
__global__ void prep2_kernel(const float* __restrict__ lg, const float* __restrict__ lb,
                             const float* __restrict__ Wq,
                             const float* __restrict__ qpos,
                             const int* __restrict__ qbo, int n_off,
                             const int* __restrict__ shapes,
                             int N, int R123, int R, int KB) {
    int bid = blockIdx.x, tid = threadIdx.x;
    if (bid < N) {
        ln_qproj_body(bid, lg, lb, Wq);
    } else if (bid < N + KB) {                           // build_keys (idx with valid in bit31)
        int id = (bid - N) * 128 + tid;
        if (id >= N * KTOT) return;
        int q = id / KTOT, k = id % KTOT;
        int l, t, d;
        if      (k < 9)  { l = 0; t = k;      d = 3; }
        else if (k < 34) { l = 1; t = k - 9;  d = 5; }
        else if (k < 83) { l = 2; t = k - 34; d = 7; }
        else             { l = 3; t = k - 83; d = 9; }
        int Hl = shapes[2*l], Wl = shapes[2*l+1];
        float sh = (float)Hl / (float)shapes[0];
        float sw = (float)Wl / (float)shapes[1];
        int c0 = (int)floorf(qpos[2*q] * sh), c1 = (int)floorf(qpos[2*q+1] * sw);
        int gi = c0 + t / d - d / 2;
        int gj = c1 + t % d - d / 2;
        int valid = (gi >= 0 && gi < Hl && gj >= 0 && gj < Wl);
        int ci = min(max(gi, 0), Hl - 1), cj = min(max(gj, 0), Wl - 1);
        int b = batch_of(q, qbo, n_off);
        int idx;
        if (l == 0) idx = R123 + q * 9 + t;
        else {
            int base = (l == 1) ? 0 : (l == 2) ? 16384 : 20480;
            idx = b * PER_B + base + ci * Wl + cj;
        }
        g_kidx[id] = (int)((unsigned)idx | (valid ? 0u : 0x80000000u));
    } else {                                             // build_rcs
        int e = (bid - N - KB) * 128 + tid;
        if (e >= R * 16) return;
        int row = e >> 4, idx = e & 15;
        int l, gi, gj;
        if (row < R123) {
            int r = row % PER_B;
            if (r < 16384)      { l = 1; gi = r >> 7; gj = r & 127; }
            else if (r < 20480) { int rr = r - 16384; l = 2; gi = rr >> 6; gj = rr & 63; }
            else                { int rr = r - 20480; l = 3; gi = rr >> 5; gj = rr & 31; }
        } else {
            int e2 = row - R123;
            int q = e2 / 9, t = e2 % 9;
            l = 0;
            gi = min(max((int)floorf(qpos[2*q])   + t / 3 - 1, 0), 255);
            gj = min(max((int)floorf(qpos[2*q+1]) + t % 3 - 1, 0), 255);
        }
        int trig = idx >> 3, p = idx & 7, axis = p >> 2, f = p & 3;
        int g = axis ? gj : gi;
        g_rcs[e] = g_ktab[(size_t)((l * 2 + axis) * 264 + (g + 4)) * 8 + trig * 4 + f];
    }
}

__global__ void ln_qproj_kernel(const float* __restrict__ lg, const float* __restrict__ lb,
                                const float* __restrict__ Wq) {
    ln_qproj_body(blockIdx.x, lg, lb, Wq);
}

// ---------------- mma.sync KV projection (rope fused into K epilogue) ----------------
#define A_STR 136
#define B_STR 40
#define OFF_AHI 0
#define OFF_ALO 34816
#define OFF_BHI 69632
#define OFF_BLO 79872
#define SM_MMA_TOTAL 90112

__global__ void __launch_bounds__(256, 2)
kvproj_mma_kernel(const float* __restrict__ fm, int li, int R) {
    extern __shared__ char smem[];
    uint32_t sbase = smem_u32(smem);
    int tid = threadIdx.x;
    int wid = tid >> 5, lane = tid & 31;
    int wm = wid & 3, wn = wid >> 2;
    int row0 = blockIdx.x * 128;

    #pragma unroll
    for (int it = 0; it < 16; it++) {
        int idx = tid + 256 * it;
        int r = idx >> 5, c4 = idx & 31;
        int row = row0 + r; if (row >= R) row = R - 1;
        int src = g_rowsrc[row];
        float4 v = *(const float4*)(fm + (size_t)src * 128 + c4 * 4);
        __nv_bfloat16 hx = __float2bfloat16(v.x);
        __nv_bfloat16 hy = __float2bfloat16(v.y);
        __nv_bfloat16 hz = __float2bfloat16(v.z);
        __nv_bfloat16 hw = __float2bfloat16(v.w);
        uint32_t h01 = ((uint32_t)*(uint16_t*)&hy << 16) | *(uint16_t*)&hx;
        uint32_t h23 = ((uint32_t)*(uint16_t*)&hw << 16) | *(uint16_t*)&hz;
        uint32_t l01 = bf2(bflo(v.x, hx), bflo(v.y, hy));
        uint32_t l23 = bf2(bflo(v.z, hz), bflo(v.w, hw));
        uint32_t off = (uint32_t)(r * A_STR + c4 * 4) * 2;
        *(uint2*)(smem + OFF_AHI + off) = make_uint2(h01, h23);
        *(uint2*)(smem + OFF_ALO + off) = make_uint2(l01, l23);
    }

    const __nv_bfloat16* wbh = g_WBhi + (size_t)li * 256 * 128;
    const __nv_bfloat16* wbl = g_WBlo + (size_t)li * 256 * 128;

    for (int h = 0; h < 2; h++) {
        float acc[2][8][4];
        #pragma unroll
        for (int i = 0; i < 2; i++)
            #pragma unroll
            for (int j = 0; j < 8; j++)
                #pragma unroll
                for (int e = 0; e < 4; e++) acc[i][j][e] = 0.f;

        for (int c = 0; c < 4; c++) {
            __syncthreads();
            #pragma unroll
            for (int it = 0; it < 2; it++) {
                int idx = tid + 256 * it;
                int n = idx >> 2, kk = (idx & 3) * 8;
                const __nv_bfloat16* sh = wbh + ((size_t)(h * 128 + n)) * 128 + c * 32 + kk;
                const __nv_bfloat16* sl = wbl + ((size_t)(h * 128 + n)) * 128 + c * 32 + kk;
                uint32_t off = (uint32_t)(n * B_STR + kk) * 2;
                *(uint4*)(smem + OFF_BHI + off) = *(const uint4*)sh;
                *(uint4*)(smem + OFF_BLO + off) = *(const uint4*)sl;
            }
            __syncthreads();

            #pragma unroll
            for (int s = 0; s < 2; s++) {
                uint32_t ah[2][4], al[2][4];
                #pragma unroll
                for (int i = 0; i < 2; i++) {
                    uint32_t arow = wm * 32 + i * 16 + (lane & 15);
                    uint32_t akol = c * 32 + s * 16 + ((lane >> 4) << 3);
                    uint32_t aoff = (arow * A_STR + akol) * 2;
                    ldsm_x4(sbase + OFF_AHI + aoff, ah[i][0], ah[i][1], ah[i][2], ah[i][3]);
                    ldsm_x4(sbase + OFF_ALO + aoff, al[i][0], al[i][1], al[i][2], al[i][3]);
                }
                #pragma unroll
                for (int jj = 0; jj < 4; jj++) {
                    int m = lane >> 3, w8 = lane & 7;
                    uint32_t bn = wn * 64 + (2 * jj + (m >> 1)) * 8 + w8;
                    uint32_t bk = s * 16 + (m & 1) * 8;
                    uint32_t boff = (bn * B_STR + bk) * 2;
                    uint32_t bh0, bh1, bh2, bh3, bl0, bl1, bl2, bl3;
                    ldsm_x4(sbase + OFF_BHI + boff, bh0, bh1, bh2, bh3);
                    ldsm_x4(sbase + OFF_BLO + boff, bl0, bl1, bl2, bl3);
                    #pragma unroll
                    for (int i = 0; i < 2; i++) {
                        mma_bf16(acc[i][2*jj],   ah[i][0], ah[i][1], ah[i][2], ah[i][3], bh0, bh1);
                        mma_bf16(acc[i][2*jj],   ah[i][0], ah[i][1], ah[i][2], ah[i][3], bl0, bl1);
                        mma_bf16(acc[i][2*jj],   al[i][0], al[i][1], al[i][2], al[i][3], bh0, bh1);
                        mma_bf16(acc[i][2*jj+1], ah[i][0], ah[i][1], ah[i][2], ah[i][3], bh2, bh3);
                        mma_bf16(acc[i][2*jj+1], ah[i][0], ah[i][1], ah[i][2], ah[i][3], bl2, bl3);
                        mma_bf16(acc[i][2*jj+1], al[i][0], al[i][1], al[i][2], al[i][3], bh2, bh3);
                    }
                }
            }
        }
        float* dstbase = h ? g_Vc : g_Kc;
        int pb = lane & 3;
        #pragma unroll
        for (int i = 0; i < 2; i++) {
            int rA = row0 + wm * 32 + i * 16 + (lane >> 2);
            int rB = rA + 8;
            if (h == 0) {
                float cA0 = g_rcs[rA*16 + pb],     sA0 = g_rcs[rA*16 + 8 + pb];
                float cA1 = g_rcs[rA*16 + 4 + pb], sA1 = g_rcs[rA*16 + 12 + pb];
                float cB0 = g_rcs[rB*16 + pb],     sB0 = g_rcs[rB*16 + 8 + pb];
                float cB1 = g_rcs[rB*16 + 4 + pb], sB1 = g_rcs[rB*16 + 12 + pb];
                #pragma unroll
                for (int j = 0; j < 8; j++) {
                    int col = wn * 64 + j * 8 + pb * 2;
                    float cc = (j & 1) ? cA1 : cA0, ss = (j & 1) ? sA1 : sA0;
                    float a0 = acc[i][j][0], a1 = acc[i][j][1];
                    if (rA < R) *(float2*)(dstbase + (size_t)rA * 128 + col) =
                        make_float2(a0 * cc - a1 * ss, a0 * ss + a1 * cc);
                    float cc2 = (j & 1) ? cB1 : cB0, ss2 = (j & 1) ? sB1 : sB0;
                    float b0 = acc[i][j][2], b1 = acc[i][j][3];
                    if (rB < R) *(float2*)(dstbase + (size_t)rB * 128 + col) =
                        make_float2(b0 * cc2 - b1 * ss2, b0 * ss2 + b1 * cc2);
                }
            } else {
                #pragma unroll
                for (int j = 0; j < 8; j++) {
                    int col = wn * 64 + j * 8 + pb * 2;
                    if (rA < R) *(float2*)(dstbase + (size_t)rA * 128 + col) = make_float2(acc[i][j][0], acc[i][j][1]);
                    if (rB < R) *(float2*)(dstbase + (size_t)rB * 128 + col) = make_float2(acc[i][j][2], acc[i][j][3]);
                }
            }
        }
    }
}

// ---------------- attention (K pre-rotated; validity folded into kidx bit31) ----------------
__global__ void attn_kernel() {
    int q = blockIdx.x, tid = threadIdx.x;
    int lane = tid & 31, w = tid >> 5;
    __shared__ float sq[128];
    __shared__ float ssc[8 * KTOT];
    __shared__ int   skidx[KTOT];
    __shared__ float smask[KTOT];
    sq[tid] = g_q[q*DM + tid];
    for (int k = tid; k < KTOT; k += 128) {
        unsigned e = (unsigned)g_kidx[q*KTOT + k];
        skidx[k] = (int)(e & 0x7FFFFFFFu);
        smask[k] = (e & 0x80000000u) ? -1.0e9f : 0.f;
    }
    __syncthreads();
    float4 qv = *(const float4*)&sq[lane * 4];
    for (int k = w; k < KTOT; k += 4) {
        int idx = skidx[k];
        float4 kv = *(const float4*)&g_Kc[(size_t)idx*DM + lane*4];
        float ps = kv.x*qv.x + kv.y*qv.y + kv.z*qv.z + kv.w*qv.w;
        ps += __shfl_xor_sync(0xffffffffu, ps, 1);
        ps += __shfl_xor_sync(0xffffffffu, ps, 2);
        if ((lane & 3) == 0) {
            int h = lane >> 2;
            ssc[h*KTOT + k] = ps * 0.25f + smask[k];
        }
    }
    __syncthreads();
    #pragma unroll
    for (int hh = 0; hh < 2; hh++) {
        int h = w * 2 + hh;
        float mx = -3.0e38f;
        for (int k = lane; k < KTOT; k += 32) mx = fmaxf(mx, ssc[h*KTOT + k]);
        #pragma unroll
        for (int o = 16; o; o >>= 1) mx = fmaxf(mx, __shfl_xor_sync(0xffffffffu, mx, o));
        float sum = 0.f;
        for (int k = lane; k < KTOT; k += 32) {
            float e = expf(ssc[h*KTOT + k] - mx);
            ssc[h*KTOT + k] = e;
            sum += e;
        }
        #pragma unroll
        for (int o = 16; o; o >>= 1) sum += __shfl_xor_sync(0xffffffffu, sum, o);
        float inv = 1.f / sum;
        for (int k = lane; k < KTOT; k += 32) ssc[h*KTOT + k] *= inv;
    }
    __syncthreads();
    int h = tid >> 4;
    float acc = 0.f;
    #pragma unroll 4
    for (int k = 0; k < KTOT; k++)
        acc += ssc[h*KTOT + k] * g_Vc[(size_t)skidx[k]*DM + tid];
    g_o[q*DM + tid] = acc;
}

__global__ void oproj_ln2_kernel(const float* __restrict__ Wo,
                                 const float* __restrict__ lg, const float* __restrict__ lb) {
    int q = blockIdx.x, tid = threadIdx.x;
    int lane = tid & 31, w = tid >> 5;
    __shared__ float so[128];
    __shared__ float red[8];
    so[tid] = g_o[q*DM + tid];
    __syncthreads();
    float acc = 0.f;
    #pragma unroll 8
    for (int i = 0; i < 128; i++) acc += so[i] * Wo[i * DM + tid];
    float x = g_x[q*DM + tid] + acc;
    g_x[q*DM + tid] = x;
    float s1 = x, s2 = x * x;
    #pragma unroll
    for (int o = 16; o; o >>= 1) {
        s1 += __shfl_xor_sync(0xffffffffu, s1, o);
        s2 += __shfl_xor_sync(0xffffffffu, s2, o);
    }
    if (lane == 0) { red[w] = s1; red[4 + w] = s2; }
    __syncthreads();
    float mean = (red[0] + red[1] + red[2] + red[3]) * (1.f / 128.f);
    float var  = (red[4] + red[5] + red[6] + red[7]) * (1.f / 128.f) - mean * mean;
    g_h[q*DM + tid] = (x - mean) * rsqrtf(var + 1e-5f) * lg[tid] + lb[tid];
}

// t = gelu(h @ W1 + b1), then x += t @ W2 + b2.  8 q/block, 256 thr (R10 config)
__global__ void ffn_kernel(const float* __restrict__ W1, const float* __restrict__ b1v,
                           const float* __restrict__ W2, const float* __restrict__ b2v, int N) {
    int q0 = blockIdx.x * 8, tid = threadIdx.x;
    __shared__ float sh2[8][128];
    __shared__ float st[8][512];
    for (int i = tid; i < 1024; i += 256) {
        int r = i >> 7, c = i & 127;
        int q = q0 + r;
        sh2[r][c] = (q < N) ? g_h[q*DM + c] : 0.f;
    }
    __syncthreads();
    {
        ull acc0[4], acc1[4];
        #pragma unroll
        for (int p = 0; p < 4; p++) { acc0[p] = 0ull; acc1[p] = 0ull; }
        #pragma unroll 4
        for (int i = 0; i < 128; i++) {
            ull w0 = pack2(W1[i*512 + tid]);
            ull w1 = pack2(W1[i*512 + 256 + tid]);
            #pragma unroll
            for (int p = 0; p < 4; p++) {
                ull hp = packab(sh2[2*p][i], sh2[2*p+1][i]);
                acc0[p] = fma2(hp, w0, acc0[p]);
                acc1[p] = fma2(hp, w1, acc1[p]);
            }
        }
        float bb0 = b1v[tid], bb1 = b1v[256 + tid];
        #pragma unroll
        for (int p = 0; p < 4; p++) {
            float a0, a1, c0, c1;
            unpack2(acc0[p], a0, a1);
            unpack2(acc1[p], c0, c1);
            st[2*p][tid]           = gelu_tanh(a0 + bb0);
            st[2*p][256 + tid]     = gelu_tanh(c0 + bb1);
            st[2*p + 1][tid]       = gelu_tanh(a1 + bb0);
            st[2*p + 1][256 + tid] = gelu_tanh(c1 + bb1);
        }
    }
    __syncthreads();
    {
        int col = tid & 127, half = tid >> 7;
        ull a01 = 0ull, a23 = 0ull;
        #pragma unroll 4
        for (int i = 0; i < 512; i++) {
            ull wv = pack2(W2[i*128 + col]);
            a01 = fma2(packab(st[half*4 + 0][i], st[half*4 + 1][i]), wv, a01);
            a23 = fma2(packab(st[half*4 + 2][i], st[half*4 + 3][i]), wv, a23);
        }
        float v0, v1, v2, v3;
        unpack2(a01, v0, v1);
        unpack2(a23, v2, v3);
        float bb = b2v[col];
        int qb = q0 + half * 4;
        if (qb + 0 < N) g_x[(qb+0)*DM + col] += v0 + bb;
        if (qb + 1 < N) g_x[(qb+1)*DM + col] += v1 + bb;
        if (qb + 2 < N) g_x[(qb+2)*DM + col] += v2 + bb;
        if (qb + 3 < N) g_x[(qb+3)*DM + col] += v3 + bb;
    }
}

__global__ void logits_kernel(const float* __restrict__ fm, const float* __restrict__ qpos,
                              const int* __restrict__ qbo, int n_off,
                              const int* __restrict__ shapes, float* __restrict__ out) {
    int q = blockIdx.x, tid = threadIdx.x;
    int lane = tid & 31, w = tid >> 5;
    __shared__ float sx[128];
    __shared__ int sb;
    if (tid < 128) sx[tid] = g_x[q*DM + tid];
    if (tid == 0) sb = batch_of(q, qbo, n_off);
    __syncthreads();
    int H0 = shapes[0], W0 = shapes[1];
    float p0 = qpos[2*q], p1 = qpos[2*q+1];
    int c0 = (int)floorf(p0), c1 = (int)floorf(p1);
    float4 xv = *(const float4*)&sx[lane * 4];
    int b = sb;
    for (int pp = w; pp < 49; pp += 8) {
        int gi = c0 + pp / 7 - 3;
        int gj = c1 + pp % 7 - 3;
        bool valid = (gi >= 0 && gi < H0 && gj >= 0 && gj < W0);
        int ci = min(max(gi, 0), H0 - 1), cj = min(max(gj, 0), W0 - 1);
        const float* f = fm + ((((size_t)b * 256 + ci) * 256 + cj) * 4 + 0) * 128;
        float4 fv = *(const float4*)(f + lane * 4);
        float d = fv.x*xv.x + fv.y*xv.y + fv.z*xv.z + fv.w*xv.w;
        #pragma unroll
        for (int o = 16; o; o >>= 1) d += __shfl_xor_sync(0xffffffffu, d, o);
        if (lane == 0) out[q*49 + pp] = valid ? d : 0.f;
    }
}

// ---------------- launch ----------------
extern "C" void kernel_launch(void* const* d_in, const int* in_sizes, int n_in,
                              void* d_out, int out_size) {
    const float* queries = (const float*)d_in[0];
    const int*   qbo     = (const int*)  d_in[1];
    const float* qpos    = (const float*)d_in[2];
    const float* fm      = (const float*)d_in[3];
    const int*   shapes  = (const int*)  d_in[4];
    const float* Wq      = (const float*)d_in[5];
    const float* Wk      = (const float*)d_in[6];
    const float* Wv      = (const float*)d_in[7];
    const float* Wo      = (const float*)d_in[8];
    const float* ln1g    = (const float*)d_in[9];
    const float* ln1b    = (const float*)d_in[10];
    const float* ln2g    = (const float*)d_in[11];
    const float* ln2b    = (const float*)d_in[12];
    const float* W1      = (const float*)d_in[13];
    const float* b1      = (const float*)d_in[14];
    const float* W2      = (const float*)d_in[15];
    const float* b2      = (const float*)d_in[16];

    int N     = in_sizes[0] / DM;
    int n_off = in_sizes[1];
    int nl    = in_sizes[5] / (DM * DM);
    int B     = in_sizes[3] / (256 * 256 * 4 * DM);
    int R123  = B * PER_B;
    int R     = R123 + N * 9;
    int gridR = (R + 127) / 128;

    cudaFuncSetAttribute(kvproj_mma_kernel, cudaFuncAttributeMaxDynamicSharedMemorySize, SM_MMA_TOTAL);

    int s0 = (N * DM + 255) / 256;
    int s1 = (R + 255) / 256;
    int s2 = (nl * 256 * 128 + 255) / 256;
    int s3 = (4 * 2 * 264 + 255) / 256;
    int s4 = (N + 255) / 256;
    int o1 = s0, o2 = o1 + s1, o3 = o2 + s2, o4 = o3 + s3;
    int gridP1 = o4 + s4;

    int KB = (N * KTOT + 127) / 128;
    int RB = (R * 16 + 127) / 128;
    int gridP2 = N + KB + RB;

    prep1_kernel<<<gridP1, 256>>>(queries, qpos, qbo, n_off, shapes, Wk, Wv,
                                  N, nl, R123, R, o1, o2, o3, o4);
    prep2_kernel<<<gridP2, 128>>>(ln1g, ln1b, Wq, qpos, qbo, n_off, shapes, N, R123, R, KB);
    kvproj_mma_kernel<<<gridR, 256, SM_MMA_TOTAL>>>(fm, 0, R);
    attn_kernel<<<N, 128>>>();                      // my-index 3 -> profiled
    oproj_ln2_kernel<<<N, 128>>>(Wo, ln2g, ln2b);
    ffn_kernel<<<(N + 7) / 8, 256>>>(W1, b1, W2, b2, N);

    for (int li = 1; li < nl; li++) {
        kvproj_mma_kernel<<<gridR, 256, SM_MMA_TOTAL>>>(fm, li, R);
        ln_qproj_kernel<<<N, 128>>>(ln1g + li*DM, ln1b + li*DM, Wq + li*DM*DM);
        attn_kernel<<<N, 128>>>();
        oproj_ln2_kernel<<<N, 128>>>(Wo + li*DM*DM, ln2g + li*DM, ln2b + li*DM);
        ffn_kernel<<<(N + 7) / 8, 256>>>(W1 + li*DM*512, b1 + li*512, W2 + li*512*DM, b2 + li*DM, N);
    }
    logits_kernel<<<N, 256>>>(fm, qpos, qbo, n_off, shapes, (float*)d_out);
}

// round 14
// speedup vs baseline: 1.0574x; 1.0221x over previous
#include <cuda_runtime.h>
#include <cuda_bf16.h>
#include <math.h>
#include <stdint.h>

#define DM   128
#define NH   8
#define HD   16
#define KTOT 164          // 9 + 25 + 49 + 81
#define PER_B 21504       // 128*128 + 64*64 + 32*32
#define MAXN 2048
#define MAXROWS (2*PER_B + MAXN*9)
#define MAXL 4

typedef unsigned long long ull;

// ---------------- device scratch ----------------
__device__ float g_x  [MAXN*DM];
__device__ float g_q  [MAXN*DM];
__device__ float g_o  [MAXN*DM];
__device__ float g_h  [MAXN*DM];
__device__ float g_qcs[MAXN*16];
__device__ int   g_kidx[MAXN*KTOT];              // bit31 set = INVALID key
__device__ int   g_rowsrc[MAXROWS];
__device__ float g_rcs[MAXROWS*16];              // per-row RoPE cos/sin
__device__ float g_Kc[2][(size_t)MAXROWS*DM];    // ping-pong buffers
__device__ float g_Vc[2][(size_t)MAXROWS*DM];
__device__ __align__(16) __nv_bfloat16 g_WBhi[MAXL*256*128];   // [layer][n: Wk|Wv][k]
__device__ __align__(16) __nv_bfloat16 g_WBlo[MAXL*256*128];
__device__ float g_ktab[4*2*264*8];              // [level][axis][g+4][4cos,4sin]

__device__ __constant__ float c_invfreq[4] = {1.0f, 0.56234132519f, 0.316227766017f, 0.177827941004f};

// ---------------- helpers ----------------
__device__ __forceinline__ ull fma2(ull a, ull b, ull c) {
    ull d; asm("fma.rn.f32x2 %0, %1, %2, %3;" : "=l"(d) : "l"(a), "l"(b), "l"(c)); return d;
}
__device__ __forceinline__ ull pack2(float f) {
    ull r; asm("mov.b64 %0, {%1, %1};" : "=l"(r) : "r"(__float_as_uint(f))); return r;
}
__device__ __forceinline__ ull packab(float a, float b) {
    ull r; asm("mov.b64 %0, {%1, %2};" : "=l"(r) : "r"(__float_as_uint(a)), "r"(__float_as_uint(b))); return r;
}
__device__ __forceinline__ void unpack2(ull v, float& lo, float& hi) {
    unsigned int a, b; asm("mov.b64 {%0, %1}, %2;" : "=r"(a), "=r"(b) : "l"(v));
    lo = __uint_as_float(a); hi = __uint_as_float(b);
}
__device__ __forceinline__ float gelu_tanh(float v) {
    float u = 0.7978845608028654f * (v + 0.044715f * v * v * v);
    return 0.5f * v * (1.f + tanhf(u));
}
__device__ __forceinline__ int batch_of(int q, const int* qbo, int n_off) {
    int b = 0;
    for (int t = 1; t < n_off - 1; t++) if (q >= qbo[t]) b = t;
    return b;
}
__device__ __forceinline__ uint32_t smem_u32(const void* p) {
    uint32_t a;
    asm("{ .reg .u64 t; cvta.to.shared.u64 t, %1; cvt.u32.u64 %0, t; }" : "=r"(a) : "l"(p));
    return a;
}
__device__ __forceinline__ uint32_t bf2(float a, float b) {
    __nv_bfloat162 h = __floats2bfloat162_rn(a, b);
    return *(uint32_t*)&h;
}
__device__ __forceinline__ float bflo(float x, __nv_bfloat16 hi) {
    return x - __bfloat162float(hi);
}
__device__ __forceinline__ void ldsm_x4(uint32_t addr, uint32_t& r0, uint32_t& r1, uint32_t& r2, uint32_t& r3) {
    asm volatile("ldmatrix.sync.aligned.m8n8.x4.shared.b16 {%0,%1,%2,%3}, [%4];"
                 : "=r"(r0), "=r"(r1), "=r"(r2), "=r"(r3) : "r"(addr));
}
__device__ __forceinline__ void mma_bf16(float* c, uint32_t a0, uint32_t a1, uint32_t a2, uint32_t a3,
                                         uint32_t b0, uint32_t b1) {
    asm volatile("mma.sync.aligned.m16n8k16.row.col.f32.bf16.bf16.f32 "
                 "{%0,%1,%2,%3}, {%4,%5,%6,%7}, {%8,%9}, {%0,%1,%2,%3};"
                 : "+f"(c[0]), "+f"(c[1]), "+f"(c[2]), "+f"(c[3])
                 : "r"(a0), "r"(a1), "r"(a2), "r"(a3), "r"(b0), "r"(b1));
}

// ---------------- LN1 + Qproj + RoPE body (per-query, 128 threads) ----------------
__device__ void ln_qproj_body(int q, const float* __restrict__ lg, const float* __restrict__ lb,
                              const float* __restrict__ Wq) {
    int tid = threadIdx.x;
    int lane = tid & 31, w = tid >> 5;
    __shared__ float sh[128];
    __shared__ float sraw[128];
    __shared__ float red[8];
    float x = g_x[q*DM + tid];
    float s1 = x, s2 = x * x;
    #pragma unroll
    for (int o = 16; o; o >>= 1) {
        s1 += __shfl_xor_sync(0xffffffffu, s1, o);
        s2 += __shfl_xor_sync(0xffffffffu, s2, o);
    }
    if (lane == 0) { red[w] = s1; red[4 + w] = s2; }
    __syncthreads();
    float mean = (red[0] + red[1] + red[2] + red[3]) * (1.f / 128.f);
    float var  = (red[4] + red[5] + red[6] + red[7]) * (1.f / 128.f) - mean * mean;
    sh[tid] = (x - mean) * rsqrtf(var + 1e-5f) * lg[tid] + lb[tid];
    __syncthreads();
    float acc = 0.f;
    #pragma unroll 8
    for (int i = 0; i < 128; i++) acc += sh[i] * Wq[i * DM + tid];
    sraw[tid] = acc;
    __syncthreads();
    int p = (tid >> 1) & 7;
    float c = g_qcs[q*16 + p], s = g_qcs[q*16 + 8 + p];
    float x1 = sraw[tid & ~1];
    float x2 = sraw[tid |  1];
    g_q[q*DM + tid] = (tid & 1) ? (x1 * s + x2 * c) : (x1 * c - x2 * s);
}

// ---------------- fused prep kernel #1 (256 threads) ----------------
__global__ void prep1_kernel(const float* __restrict__ queries,
                             const float* __restrict__ qpos,
                             const int* __restrict__ qbo, int n_off,
                             const int* __restrict__ shapes,
                             const float* __restrict__ Wk, const float* __restrict__ Wv,
                             int N, int nl, int R123, int R,
                             int o1, int o2, int o3, int o4) {
    int bid = blockIdx.x, tid = threadIdx.x;
    if (bid < o1) {                                      // copy_x
        int i = bid * 256 + tid;
        if (i < N * DM) g_x[i] = queries[i];
    } else if (bid < o2) {                               // rowsrc
        int e = (bid - o1) * 256 + tid;
        if (e >= R) return;
        int src;
        if (e < R123) {
            int b = e / PER_B, r = e % PER_B;
            int l, i, j;
            if (r < 16384)      { l = 1; i = r >> 7; j = r & 127; }
            else if (r < 20480) { int rr = r - 16384; l = 2; i = rr >> 6; j = rr & 63; }
            else                { int rr = r - 20480; l = 3; i = rr >> 5; j = rr & 31; }
            src = ((b * 256 + i) * 256 + j) * 4 + l;
        } else {
            int e2 = e - R123;
            int q = e2 / 9, t = e2 % 9;
            int b = batch_of(q, qbo, n_off);
            int c0 = (int)floorf(qpos[2*q]), c1 = (int)floorf(qpos[2*q+1]);
            int gi = min(max(c0 + t / 3 - 1, 0), 255);
            int gj = min(max(c1 + t % 3 - 1, 0), 255);
            src = ((b * 256 + gi) * 256 + gj) * 4 + 0;
        }
        g_rowsrc[e] = src;
    } else if (bid < o3) {                               // wt split
        int id = (bid - o2) * 256 + tid;
        if (id >= nl * 256 * 128) return;
        int li = id / (256 * 128);
        int r  = id % (256 * 128);
        int n = r / 128, k = r % 128;
        float w = (n < 128) ? Wk[li*DM*DM + k*DM + n] : Wv[li*DM*DM + k*DM + (n - 128)];
        __nv_bfloat16 hi = __float2bfloat16(w);
        g_WBhi[id] = hi;
        g_WBlo[id] = __float2bfloat16(w - __bfloat162float(hi));
    } else if (bid < o4) {                               // ktab
        int id = (bid - o3) * 256 + tid;
        if (id >= 4 * 2 * 264) return;
        int l = id / (2 * 264);
        int axis = (id / 264) & 1;
        int g = (id % 264) - 4;
        float scale = (float)shapes[2*l + axis] / (float)shapes[axis];
        float kp = ((float)g + 0.5f) / scale;
        float* t = &g_ktab[(size_t)id * 8];
        #pragma unroll
        for (int f = 0; f < 4; f++) {
            float a = kp * c_invfreq[f];
            t[f] = cosf(a);
            t[4 + f] = sinf(a);
        }
    } else {                                             // qcs
        int q = (bid - o4) * 256 + tid;
        if (q >= N) return;
        float p0 = qpos[2*q], p1 = qpos[2*q+1];
        float* cs = &g_qcs[q * 16];
        #pragma unroll
        for (int f = 0; f < 4; f++) {
            float a0 = p0 * c_invfreq[f];
            float a1 = p1 * c_invfreq[f];
            cs[f]      = cosf(a0);  cs[8  + f] = sinf(a0);
            cs[4 + f]  = cosf(a1);  cs[12 + f] = sinf(a1);
        }
    }
}

// ---------------- fused prep kernel #2 (128 threads) ----------------
__global__ void prep2_kernel(const float* __restrict__ lg, const float* __restrict__ lb,
                             const float* __restrict__ Wq,
                             const float* __restrict__ qpos,
                             const int* __restrict__ qbo, int n_off,
                             const int* __restrict__ shapes,
                             int N, int R123, int R, int KB) {
    int bid = blockIdx.x, tid = threadIdx.x;
    if (bid < N) {
        ln_qproj_body(bid, lg, lb, Wq);
    } else if (bid < N + KB) {                           // build_keys (idx with valid in bit31)
        int id = (bid - N) * 128 + tid;
        if (id >= N * KTOT) return;
        int q = id / KTOT, k = id % KTOT;
        int l, t, d;
        if      (k < 9)  { l = 0; t = k;      d = 3; }
        else if (k < 34) { l = 1; t = k - 9;  d = 5; }
        else if (k < 83) { l = 2; t = k - 34; d = 7; }
        else             { l = 3; t = k - 83; d = 9; }
        int Hl = shapes[2*l], Wl = shapes[2*l+1];
        float sh = (float)Hl / (float)shapes[0];
        float sw = (float)Wl / (float)shapes[1];
        int c0 = (int)floorf(qpos[2*q] * sh), c1 = (int)floorf(qpos[2*q+1] * sw);
        int gi = c0 + t / d - d / 2;
        int gj = c1 + t % d - d / 2;
        int valid = (gi >= 0 && gi < Hl && gj >= 0 && gj < Wl);
        int ci = min(max(gi, 0), Hl - 1), cj = min(max(gj, 0), Wl - 1);
        int b = batch_of(q, qbo, n_off);
        int idx;
        if (l == 0) idx = R123 + q * 9 + t;
        else {
            int base = (l == 1) ? 0 : (l == 2) ? 16384 : 20480;
            idx = b * PER_B + base + ci * Wl + cj;
        }
        g_kidx[id] = (int)((unsigned)idx | (valid ? 0u : 0x80000000u));
    } else {                                             // build_rcs
        int e = (bid - N - KB) * 128 + tid;
        if (e >= R * 16) return;
        int row = e >> 4, idx = e & 15;
        int l, gi, gj;
        if (row < R123) {
            int r = row % PER_B;
            if (r < 16384)      { l = 1; gi = r >> 7; gj = r & 127; }
            else if (r < 20480) { int rr = r - 16384; l = 2; gi = rr >> 6; gj = rr & 63; }
            else                { int rr = r - 20480; l = 3; gi = rr >> 5; gj = rr & 31; }
        } else {
            int e2 = row - R123;
            int q = e2 / 9, t = e2 % 9;
            l = 0;
            gi = min(max((int)floorf(qpos[2*q])   + t / 3 - 1, 0), 255);
            gj = min(max((int)floorf(qpos[2*q+1]) + t % 3 - 1, 0), 255);
        }
        int trig = idx >> 3, p = idx & 7, axis = p >> 2, f = p & 3;
        int g = axis ? gj : gi;
        g_rcs[e] = g_ktab[(size_t)((l * 2 + axis) * 264 + (g + 4)) * 8 + trig * 4 + f];
    }
}

__global__ void ln_qproj_kernel(const float* __restrict__ lg, const float* __restrict__ lb,
                                const float* __restrict__ Wq) {
    ln_qproj_body(blockIdx.x, lg, lb, Wq);
}

// ---------------- mma.sync KV projection (rope fused into K epilogue) ----------------
#define A_STR 136
#define B_STR 40
#define OFF_AHI 0
#define OFF_ALO 34816
#define OFF_BHI 69632
#define OFF_BLO 79872
#define SM_MMA_TOTAL 90112

__global__ void __launch_bounds__(256, 2)
kvproj_mma_kernel(const float* __restrict__ fm, int li, int R, int buf) {
    extern __shared__ char smem[];
    uint32_t sbase = smem_u32(smem);
    int tid = threadIdx.x;
    int wid = tid >> 5, lane = tid & 31;
    int wm = wid & 3, wn = wid >> 2;
    int row0 = blockIdx.x * 128;

    #pragma unroll
    for (int it = 0; it < 16; it++) {
        int idx = tid + 256 * it;
        int r = idx >> 5, c4 = idx & 31;
        int row = row0 + r; if (row >= R) row = R - 1;
        int src = g_rowsrc[row];
        float4 v = *(const float4*)(fm + (size_t)src * 128 + c4 * 4);
        __nv_bfloat16 hx = __float2bfloat16(v.x);
        __nv_bfloat16 hy = __float2bfloat16(v.y);
        __nv_bfloat16 hz = __float2bfloat16(v.z);
        __nv_bfloat16 hw = __float2bfloat16(v.w);
        uint32_t h01 = ((uint32_t)*(uint16_t*)&hy << 16) | *(uint16_t*)&hx;
        uint32_t h23 = ((uint32_t)*(uint16_t*)&hw << 16) | *(uint16_t*)&hz;
        uint32_t l01 = bf2(bflo(v.x, hx), bflo(v.y, hy));
        uint32_t l23 = bf2(bflo(v.z, hz), bflo(v.w, hw));
        uint32_t off = (uint32_t)(r * A_STR + c4 * 4) * 2;
        *(uint2*)(smem + OFF_AHI + off) = make_uint2(h01, h23);
        *(uint2*)(smem + OFF_ALO + off) = make_uint2(l01, l23);
    }

    const __nv_bfloat16* wbh = g_WBhi + (size_t)li * 256 * 128;
    const __nv_bfloat16* wbl = g_WBlo + (size_t)li * 256 * 128;

    for (int h = 0; h < 2; h++) {
        float acc[2][8][4];
        #pragma unroll
        for (int i = 0; i < 2; i++)
            #pragma unroll
            for (int j = 0; j < 8; j++)
                #pragma unroll
                for (int e = 0; e < 4; e++) acc[i][j][e] = 0.f;

        for (int c = 0; c < 4; c++) {
            __syncthreads();
            #pragma unroll
            for (int it = 0; it < 2; it++) {
                int idx = tid + 256 * it;
                int n = idx >> 2, kk = (idx & 3) * 8;
                const __nv_bfloat16* sh = wbh + ((size_t)(h * 128 + n)) * 128 + c * 32 + kk;
                const __nv_bfloat16* sl = wbl + ((size_t)(h * 128 + n)) * 128 + c * 32 + kk;
                uint32_t off = (uint32_t)(n * B_STR + kk) * 2;
                *(uint4*)(smem + OFF_BHI + off) = *(const uint4*)sh;
                *(uint4*)(smem + OFF_BLO + off) = *(const uint4*)sl;
            }
            __syncthreads();

            #pragma unroll
            for (int s = 0; s < 2; s++) {
                uint32_t ah[2][4], al[2][4];
                #pragma unroll
                for (int i = 0; i < 2; i++) {
                    uint32_t arow = wm * 32 + i * 16 + (lane & 15);
                    uint32_t akol = c * 32 + s * 16 + ((lane >> 4) << 3);
                    uint32_t aoff = (arow * A_STR + akol) * 2;
                    ldsm_x4(sbase + OFF_AHI + aoff, ah[i][0], ah[i][1], ah[i][2], ah[i][3]);
                    ldsm_x4(sbase + OFF_ALO + aoff, al[i][0], al[i][1], al[i][2], al[i][3]);
                }
                #pragma unroll
                for (int jj = 0; jj < 4; jj++) {
                    int m = lane >> 3, w8 = lane & 7;
                    uint32_t bn = wn * 64 + (2 * jj + (m >> 1)) * 8 + w8;
                    uint32_t bk = s * 16 + (m & 1) * 8;
                    uint32_t boff = (bn * B_STR + bk) * 2;
                    uint32_t bh0, bh1, bh2, bh3, bl0, bl1, bl2, bl3;
                    ldsm_x4(sbase + OFF_BHI + boff, bh0, bh1, bh2, bh3);
                    ldsm_x4(sbase + OFF_BLO + boff, bl0, bl1, bl2, bl3);
                    #pragma unroll
                    for (int i = 0; i < 2; i++) {
                        mma_bf16(acc[i][2*jj],   ah[i][0], ah[i][1], ah[i][2], ah[i][3], bh0, bh1);
                        mma_bf16(acc[i][2*jj],   ah[i][0], ah[i][1], ah[i][2], ah[i][3], bl0, bl1);
                        mma_bf16(acc[i][2*jj],   al[i][0], al[i][1], al[i][2], al[i][3], bh0, bh1);
                        mma_bf16(acc[i][2*jj+1], ah[i][0], ah[i][1], ah[i][2], ah[i][3], bh2, bh3);
                        mma_bf16(acc[i][2*jj+1], ah[i][0], ah[i][1], ah[i][2], ah[i][3], bl2, bl3);
                        mma_bf16(acc[i][2*jj+1], al[i][0], al[i][1], al[i][2], al[i][3], bh2, bh3);
                    }
                }
            }
        }
        float* dstbase = h ? g_Vc[buf] : g_Kc[buf];
        int pb = lane & 3;
        #pragma unroll
        for (int i = 0; i < 2; i++) {
            int rA = row0 + wm * 32 + i * 16 + (lane >> 2);
            int rB = rA + 8;
            if (h == 0) {
                float cA0 = g_rcs[rA*16 + pb],     sA0 = g_rcs[rA*16 + 8 + pb];
                float cA1 = g_rcs[rA*16 + 4 + pb], sA1 = g_rcs[rA*16 + 12 + pb];
                float cB0 = g_rcs[rB*16 + pb],     sB0 = g_rcs[rB*16 + 8 + pb];
                float cB1 = g_rcs[rB*16 + 4 + pb], sB1 = g_rcs[rB*16 + 12 + pb];
                #pragma unroll
                for (int j = 0; j < 8; j++) {
                    int col = wn * 64 + j * 8 + pb * 2;
                    float cc = (j & 1) ? cA1 : cA0, ss = (j & 1) ? sA1 : sA0;
                    float a0 = acc[i][j][0], a1 = acc[i][j][1];
                    if (rA < R) *(float2*)(dstbase + (size_t)rA * 128 + col) =
                        make_float2(a0 * cc - a1 * ss, a0 * ss + a1 * cc);
                    float cc2 = (j & 1) ? cB1 : cB0, ss2 = (j & 1) ? sB1 : sB0;
                    float b0 = acc[i][j][2], b1 = acc[i][j][3];
                    if (rB < R) *(float2*)(dstbase + (size_t)rB * 128 + col) =
                        make_float2(b0 * cc2 - b1 * ss2, b0 * ss2 + b1 * cc2);
                }
            } else {
                #pragma unroll
                for (int j = 0; j < 8; j++) {
                    int col = wn * 64 + j * 8 + pb * 2;
                    if (rA < R) *(float2*)(dstbase + (size_t)rA * 128 + col) = make_float2(acc[i][j][0], acc[i][j][1]);
                    if (rB < R) *(float2*)(dstbase + (size_t)rB * 128 + col) = make_float2(acc[i][j][2], acc[i][j][3]);
                }
            }
        }
    }
}

// ---------------- attention (K pre-rotated; validity folded into kidx bit31) ----------------
__global__ void attn_kernel(int buf) {
    int q = blockIdx.x, tid = threadIdx.x;
    int lane = tid & 31, w = tid >> 5;
    __shared__ float sq[128];
    __shared__ float ssc[8 * KTOT];
    __shared__ int   skidx[KTOT];
    __shared__ float smask[KTOT];
    const float* Kc = g_Kc[buf];
    const float* Vc = g_Vc[buf];
    sq[tid] = g_q[q*DM + tid];
    for (int k = tid; k < KTOT; k += 128) {
        unsigned e = (unsigned)g_kidx[q*KTOT + k];
        skidx[k] = (int)(e & 0x7FFFFFFFu);
        smask[k] = (e & 0x80000000u) ? -1.0e9f : 0.f;
    }
    __syncthreads();
    float4 qv = *(const float4*)&sq[lane * 4];
    for (int k = w; k < KTOT; k += 4) {
        int idx = skidx[k];
        float4 kv = *(const float4*)&Kc[(size_t)idx*DM + lane*4];
        float ps = kv.x*qv.x + kv.y*qv.y + kv.z*qv.z + kv.w*qv.w;
        ps += __shfl_xor_sync(0xffffffffu, ps, 1);
        ps += __shfl_xor_sync(0xffffffffu, ps, 2);
        if ((lane & 3) == 0) {
            int h = lane >> 2;
            ssc[h*KTOT + k] = ps * 0.25f + smask[k];
        }
    }
    __syncthreads();
    #pragma unroll
    for (int hh = 0; hh < 2; hh++) {
        int h = w * 2 + hh;
        float mx = -3.0e38f;
        for (int k = lane; k < KTOT; k += 32) mx = fmaxf(mx, ssc[h*KTOT + k]);
        #pragma unroll
        for (int o = 16; o; o >>= 1) mx = fmaxf(mx, __shfl_xor_sync(0xffffffffu, mx, o));
        float sum = 0.f;
        for (int k = lane; k < KTOT; k += 32) {
            float e = expf(ssc[h*KTOT + k] - mx);
            ssc[h*KTOT + k] = e;
            sum += e;
        }
        #pragma unroll
        for (int o = 16; o; o >>= 1) sum += __shfl_xor_sync(0xffffffffu, sum, o);
        float inv = 1.f / sum;
        for (int k = lane; k < KTOT; k += 32) ssc[h*KTOT + k] *= inv;
    }
    __syncthreads();
    int h = tid >> 4;
    float acc = 0.f;
    #pragma unroll 4
    for (int k = 0; k < KTOT; k++)
        acc += ssc[h*KTOT + k] * Vc[(size_t)skidx[k]*DM + tid];
    g_o[q*DM + tid] = acc;
}

__global__ void oproj_ln2_kernel(const float* __restrict__ Wo,
                                 const float* __restrict__ lg, const float* __restrict__ lb) {
    int q = blockIdx.x, tid = threadIdx.x;
    int lane = tid & 31, w = tid >> 5;
    __shared__ float so[128];
    __shared__ float red[8];
    so[tid] = g_o[q*DM + tid];
    __syncthreads();
    float acc = 0.f;
    #pragma unroll 8
    for (int i = 0; i < 128; i++) acc += so[i] * Wo[i * DM + tid];
    float x = g_x[q*DM + tid] + acc;
    g_x[q*DM + tid] = x;
    float s1 = x, s2 = x * x;
    #pragma unroll
    for (int o = 16; o; o >>= 1) {
        s1 += __shfl_xor_sync(0xffffffffu, s1, o);
        s2 += __shfl_xor_sync(0xffffffffu, s2, o);
    }
    if (lane == 0) { red[w] = s1; red[4 + w] = s2; }
    __syncthreads();
    float mean = (red[0] + red[1] + red[2] + red[3]) * (1.f / 128.f);
    float var  = (red[4] + red[5] + red[6] + red[7]) * (1.f / 128.f) - mean * mean;
    g_h[q*DM + tid] = (x - mean) * rsqrtf(var + 1e-5f) * lg[tid] + lb[tid];
}

// t = gelu(h @ W1 + b1), then x += t @ W2 + b2.  8 q/block, 256 thr
__global__ void ffn_kernel(const float* __restrict__ W1, const float* __restrict__ b1v,
                           const float* __restrict__ W2, const float* __restrict__ b2v, int N) {
    int q0 = blockIdx.x * 8, tid = threadIdx.x;
    __shared__ float sh2[8][128];
    __shared__ float st[8][512];
    for (int i = tid; i < 1024; i += 256) {
        int r = i >> 7, c = i & 127;
        int q = q0 + r;
        sh2[r][c] = (q < N) ? g_h[q*DM + c] : 0.f;
    }
    __syncthreads();
    {
        ull acc0[4], acc1[4];
        #pragma unroll
        for (int p = 0; p < 4; p++) { acc0[p] = 0ull; acc1[p] = 0ull; }
        #pragma unroll 4
        for (int i = 0; i < 128; i++) {
            ull w0 = pack2(W1[i*512 + tid]);
            ull w1 = pack2(W1[i*512 + 256 + tid]);
            #pragma unroll
            for (int p = 0; p < 4; p++) {
                ull hp = packab(sh2[2*p][i], sh2[2*p+1][i]);
                acc0[p] = fma2(hp, w0, acc0[p]);
                acc1[p] = fma2(hp, w1, acc1[p]);
            }
        }
        float bb0 = b1v[tid], bb1 = b1v[256 + tid];
        #pragma unroll
        for (int p = 0; p < 4; p++) {
            float a0, a1, c0, c1;
            unpack2(acc0[p], a0, a1);
            unpack2(acc1[p], c0, c1);
            st[2*p][tid]           = gelu_tanh(a0 + bb0);
            st[2*p][256 + tid]     = gelu_tanh(c0 + bb1);
            st[2*p + 1][tid]       = gelu_tanh(a1 + bb0);
            st[2*p + 1][256 + tid] = gelu_tanh(c1 + bb1);
        }
    }
    __syncthreads();
    {
        int col = tid & 127, half = tid >> 7;
        ull a01 = 0ull, a23 = 0ull;
        #pragma unroll 4
        for (int i = 0; i < 512; i++) {
            ull wv = pack2(W2[i*128 + col]);
            a01 = fma2(packab(st[half*4 + 0][i], st[half*4 + 1][i]), wv, a01);
            a23 = fma2(packab(st[half*4 + 2][i], st[half*4 + 3][i]), wv, a23);
        }
        float v0, v1, v2, v3;
        unpack2(a01, v0, v1);
        unpack2(a23, v2, v3);
        float bb = b2v[col];
        int qb = q0 + half * 4;
        if (qb + 0 < N) g_x[(qb+0)*DM + col] += v0 + bb;
        if (qb + 1 < N) g_x[(qb+1)*DM + col] += v1 + bb;
        if (qb + 2 < N) g_x[(qb+2)*DM + col] += v2 + bb;
        if (qb + 3 < N) g_x[(qb+3)*DM + col] += v3 + bb;
    }
}

__global__ void logits_kernel(const float* __restrict__ fm, const float* __restrict__ qpos,
                              const int* __restrict__ qbo, int n_off,
                              const int* __restrict__ shapes, float* __restrict__ out) {
    int q = blockIdx.x, tid = threadIdx.x;
    int lane = tid & 31, w = tid >> 5;
    __shared__ float sx[128];
    __shared__ int sb;
    if (tid < 128) sx[tid] = g_x[q*DM + tid];
    if (tid == 0) sb = batch_of(q, qbo, n_off);
    __syncthreads();
    int H0 = shapes[0], W0 = shapes[1];
    float p0 = qpos[2*q], p1 = qpos[2*q+1];
    int c0 = (int)floorf(p0), c1 = (int)floorf(p1);
    float4 xv = *(const float4*)&sx[lane * 4];
    int b = sb;
    for (int pp = w; pp < 49; pp += 8) {
        int gi = c0 + pp / 7 - 3;
        int gj = c1 + pp % 7 - 3;
        bool valid = (gi >= 0 && gi < H0 && gj >= 0 && gj < W0);
        int ci = min(max(gi, 0), H0 - 1), cj = min(max(gj, 0), W0 - 1);
        const float* f = fm + ((((size_t)b * 256 + ci) * 256 + cj) * 4 + 0) * 128;
        float4 fv = *(const float4*)(f + lane * 4);
        float d = fv.x*xv.x + fv.y*xv.y + fv.z*xv.z + fv.w*xv.w;
        #pragma unroll
        for (int o = 16; o; o >>= 1) d += __shfl_xor_sync(0xffffffffu, d, o);
        if (lane == 0) out[q*49 + pp] = valid ? d : 0.f;
    }
}

// ---------------- launch ----------------
extern "C" void kernel_launch(void* const* d_in, const int* in_sizes, int n_in,
                              void* d_out, int out_size) {
    const float* queries = (const float*)d_in[0];
    const int*   qbo     = (const int*)  d_in[1];
    const float* qpos    = (const float*)d_in[2];
    const float* fm      = (const float*)d_in[3];
    const int*   shapes  = (const int*)  d_in[4];
    const float* Wq      = (const float*)d_in[5];
    const float* Wk      = (const float*)d_in[6];
    const float* Wv      = (const float*)d_in[7];
    const float* Wo      = (const float*)d_in[8];
    const float* ln1g    = (const float*)d_in[9];
    const float* ln1b    = (const float*)d_in[10];
    const float* ln2g    = (const float*)d_in[11];
    const float* ln2b    = (const float*)d_in[12];
    const float* W1      = (const float*)d_in[13];
    const float* b1      = (const float*)d_in[14];
    const float* W2      = (const float*)d_in[15];
    const float* b2      = (const float*)d_in[16];

    int N     = in_sizes[0] / DM;
    int n_off = in_sizes[1];
    int nl    = in_sizes[5] / (DM * DM);
    int B     = in_sizes[3] / (256 * 256 * 4 * DM);
    int R123  = B * PER_B;
    int R     = R123 + N * 9;
    int gridR = (R + 127) / 128;

    cudaFuncSetAttribute(kvproj_mma_kernel, cudaFuncAttributeMaxDynamicSharedMemorySize, SM_MMA_TOTAL);

    int s0 = (N * DM + 255) / 256;
    int s1 = (R + 255) / 256;
    int s2s = (nl * 256 * 128 + 255) / 256;
    int s3 = (4 * 2 * 264 + 255) / 256;
    int s4 = (N + 255) / 256;
    int o1 = s0, o2 = o1 + s1, o3 = o2 + s2s, o4 = o3 + s3;
    int gridP1 = o4 + s4;

    int KB = (N * KTOT + 127) / 128;
    int RB = (R * 16 + 127) / 128;
    int gridP2 = N + KB + RB;

    prep1_kernel<<<gridP1, 256>>>(queries, qpos, qbo, n_off, shapes, Wk, Wv,
                                  N, nl, R123, R, o1, o2, o3, o4);
    prep2_kernel<<<gridP2, 128>>>(ln1g, ln1b, Wq, qpos, qbo, n_off, shapes, N, R123, R, KB);
    kvproj_mma_kernel<<<gridR, 256, SM_MMA_TOTAL>>>(fm, 0, R, 0);

    bool overlap = (nl == 2);
    cudaStream_t sKV = 0;
    cudaEvent_t evReady = 0, evKv = 0;
    if (overlap) {
        if (cudaStreamCreateWithFlags(&sKV, cudaStreamNonBlocking) != cudaSuccess ||
            cudaEventCreateWithFlags(&evReady, cudaEventDisableTiming) != cudaSuccess ||
            cudaEventCreateWithFlags(&evKv, cudaEventDisableTiming) != cudaSuccess) {
            overlap = false;
        }
    }

    if (overlap) {
        // fork: kvproj(L1) runs concurrently with layer-0 attn/oproj/ffn + ln_qproj(L1)
        cudaEventRecord(evReady, 0);
        cudaStreamWaitEvent(sKV, evReady, 0);
        kvproj_mma_kernel<<<gridR, 256, SM_MMA_TOTAL, sKV>>>(fm, 1, R, 1);
        cudaEventRecord(evKv, sKV);

        attn_kernel<<<N, 128>>>(0);
        oproj_ln2_kernel<<<N, 128>>>(Wo, ln2g, ln2b);
        ffn_kernel<<<(N + 7) / 8, 256>>>(W1, b1, W2, b2, N);
        ln_qproj_kernel<<<N, 128>>>(ln1g + DM, ln1b + DM, Wq + DM*DM);

        cudaStreamWaitEvent(0, evKv, 0);   // join before consuming buffer 1
        attn_kernel<<<N, 128>>>(1);
        oproj_ln2_kernel<<<N, 128>>>(Wo + DM*DM, ln2g + DM, ln2b + DM);
        ffn_kernel<<<(N + 7) / 8, 256>>>(W1 + DM*512, b1 + 512, W2 + 512*DM, b2 + DM, N);
    } else {
        attn_kernel<<<N, 128>>>(0);
        oproj_ln2_kernel<<<N, 128>>>(Wo, ln2g, ln2b);
        ffn_kernel<<<(N + 7) / 8, 256>>>(W1, b1, W2, b2, N);
        for (int li = 1; li < nl; li++) {
            int buf = li & 1;
            kvproj_mma_kernel<<<gridR, 256, SM_MMA_TOTAL>>>(fm, li, R, buf);
            ln_qproj_kernel<<<N, 128>>>(ln1g + li*DM, ln1b + li*DM, Wq + li*DM*DM);
            attn_kernel<<<N, 128>>>(buf);
            oproj_ln2_kernel<<<N, 128>>>(Wo + li*DM*DM, ln2g + li*DM, ln2b + li*DM);
            ffn_kernel<<<(N + 7) / 8, 256>>>(W1 + li*DM*512, b1 + li*512, W2 + li*512*DM, b2 + li*DM, N);
        }
    }
    logits_kernel<<<N, 256>>>(fm, qpos, qbo, n_off, shapes, (float*)d_out);
    // streams/events intentionally not destroyed mid-capture (host-side handles only)
}

// round 15
// speedup vs baseline: 1.0717x; 1.0135x over previous
#include <cuda_runtime.h>
#include <cuda_bf16.h>
#include <math.h>
#include <stdint.h>

#define DM   128
#define NH   8
#define HD   16
#define KTOT 164          // 9 + 25 + 49 + 81
#define PER_B 21504       // 128*128 + 64*64 + 32*32
#define MAXN 2048
#define MAXROWS (2*PER_B + MAXN*9)
#define MAXL 4

typedef unsigned long long ull;

// ---------------- device scratch ----------------
__device__ float g_x  [MAXN*DM];
__device__ float g_q  [MAXN*DM];
__device__ float g_o  [MAXN*DM];
__device__ float g_h  [MAXN*DM];
__device__ float g_qcs[MAXN*16];
__device__ int   g_kidx[MAXN*KTOT];              // bit31 set = INVALID key
__device__ int   g_rowsrc[MAXROWS];
__device__ float g_rcs[MAXROWS*16];              // per-row RoPE cos/sin
__device__ float g_Kc[2][(size_t)MAXROWS*DM];    // ping-pong buffers
__device__ float g_Vc[2][(size_t)MAXROWS*DM];
__device__ __align__(16) __nv_bfloat16 g_WBhi[MAXL*256*128];   // [layer][n: Wk|Wv][k]
__device__ __align__(16) __nv_bfloat16 g_WBlo[MAXL*256*128];

__device__ __constant__ float c_invfreq[4] = {1.0f, 0.56234132519f, 0.316227766017f, 0.177827941004f};

// ---------------- helpers ----------------
__device__ __forceinline__ ull fma2(ull a, ull b, ull c) {
    ull d; asm("fma.rn.f32x2 %0, %1, %2, %3;" : "=l"(d) : "l"(a), "l"(b), "l"(c)); return d;
}
__device__ __forceinline__ ull pack2(float f) {
    ull r; asm("mov.b64 %0, {%1, %1};" : "=l"(r) : "r"(__float_as_uint(f))); return r;
}
__device__ __forceinline__ ull packab(float a, float b) {
    ull r; asm("mov.b64 %0, {%1, %2};" : "=l"(r) : "r"(__float_as_uint(a)), "r"(__float_as_uint(b))); return r;
}
__device__ __forceinline__ void unpack2(ull v, float& lo, float& hi) {
    unsigned int a, b; asm("mov.b64 {%0, %1}, %2;" : "=r"(a), "=r"(b) : "l"(v));
    lo = __uint_as_float(a); hi = __uint_as_float(b);
}
__device__ __forceinline__ float gelu_tanh(float v) {
    float u = 0.7978845608028654f * (v + 0.044715f * v * v * v);
    return 0.5f * v * (1.f + tanhf(u));
}
__device__ __forceinline__ int batch_of(int q, const int* qbo, int n_off) {
    int b = 0;
    for (int t = 1; t < n_off - 1; t++) if (q >= qbo[t]) b = t;
    return b;
}
__device__ __forceinline__ uint32_t smem_u32(const void* p) {
    uint32_t a;
    asm("{ .reg .u64 t; cvta.to.shared.u64 t, %1; cvt.u32.u64 %0, t; }" : "=r"(a) : "l"(p));
    return a;
}
__device__ __forceinline__ uint32_t bf2(float a, float b) {
    __nv_bfloat162 h = __floats2bfloat162_rn(a, b);
    return *(uint32_t*)&h;
}
__device__ __forceinline__ float bflo(float x, __nv_bfloat16 hi) {
    return x - __bfloat162float(hi);
}
__device__ __forceinline__ void ldsm_x4(uint32_t addr, uint32_t& r0, uint32_t& r1, uint32_t& r2, uint32_t& r3) {
    asm volatile("ldmatrix.sync.aligned.m8n8.x4.shared.b16 {%0,%1,%2,%3}, [%4];"
                 : "=r"(r0), "=r"(r1), "=r"(r2), "=r"(r3) : "r"(addr));
}
__device__ __forceinline__ void mma_bf16(float* c, uint32_t a0, uint32_t a1, uint32_t a2, uint32_t a3,
                                         uint32_t b0, uint32_t b1) {
    asm volatile("mma.sync.aligned.m16n8k16.row.col.f32.bf16.bf16.f32 "
                 "{%0,%1,%2,%3}, {%4,%5,%6,%7}, {%8,%9}, {%0,%1,%2,%3};"
                 : "+f"(c[0]), "+f"(c[1]), "+f"(c[2]), "+f"(c[3])
                 : "r"(a0), "r"(a1), "r"(a2), "r"(a3), "r"(b0), "r"(b1));
}

// ---------------- LN1 + Qproj + RoPE body (per-query, 128 threads) ----------------
__device__ void ln_qproj_body(int q, const float* __restrict__ lg, const float* __restrict__ lb,
                              const float* __restrict__ Wq) {
    int tid = threadIdx.x;
    int lane = tid & 31, w = tid >> 5;
    __shared__ float sh[128];
    __shared__ float sraw[128];
    __shared__ float red[8];
    float x = g_x[q*DM + tid];
    float s1 = x, s2 = x * x;
    #pragma unroll
    for (int o = 16; o; o >>= 1) {
        s1 += __shfl_xor_sync(0xffffffffu, s1, o);
        s2 += __shfl_xor_sync(0xffffffffu, s2, o);
    }
    if (lane == 0) { red[w] = s1; red[4 + w] = s2; }
    __syncthreads();
    float mean = (red[0] + red[1] + red[2] + red[3]) * (1.f / 128.f);
    float var  = (red[4] + red[5] + red[6] + red[7]) * (1.f / 128.f) - mean * mean;
    sh[tid] = (x - mean) * rsqrtf(var + 1e-5f) * lg[tid] + lb[tid];
    __syncthreads();
    float acc = 0.f;
    #pragma unroll 8
    for (int i = 0; i < 128; i++) acc += sh[i] * Wq[i * DM + tid];
    sraw[tid] = acc;
    __syncthreads();
    int p = (tid >> 1) & 7;
    float c = g_qcs[q*16 + p], s = g_qcs[q*16 + 8 + p];
    float x1 = sraw[tid & ~1];
    float x2 = sraw[tid |  1];
    g_q[q*DM + tid] = (tid & 1) ? (x1 * s + x2 * c) : (x1 * c - x2 * s);
}

// ---------------- fused prep kernel (256 threads) ----------------
// sections: copy_x | rowsrc | wt-split | qcs | build_keys | build_rcs
__global__ void prep1_kernel(const float* __restrict__ queries,
                             const float* __restrict__ qpos,
                             const int* __restrict__ qbo, int n_off,
                             const int* __restrict__ shapes,
                             const float* __restrict__ Wk, const float* __restrict__ Wv,
                             int N, int nl, int R123, int R,
                             int o1, int o2, int o3, int o4, int o5) {
    int bid = blockIdx.x, tid = threadIdx.x;
    if (bid < o1) {                                      // copy_x
        int i = bid * 256 + tid;
        if (i < N * DM) g_x[i] = queries[i];
    } else if (bid < o2) {                               // rowsrc
        int e = (bid - o1) * 256 + tid;
        if (e >= R) return;
        int src;
        if (e < R123) {
            int b = e / PER_B, r = e % PER_B;
            int l, i, j;
            if (r < 16384)      { l = 1; i = r >> 7; j = r & 127; }
            else if (r < 20480) { int rr = r - 16384; l = 2; i = rr >> 6; j = rr & 63; }
            else                { int rr = r - 20480; l = 3; i = rr >> 5; j = rr & 31; }
            src = ((b * 256 + i) * 256 + j) * 4 + l;
        } else {
            int e2 = e - R123;
            int q = e2 / 9, t = e2 % 9;
            int b = batch_of(q, qbo, n_off);
            int c0 = (int)floorf(qpos[2*q]), c1 = (int)floorf(qpos[2*q+1]);
            int gi = min(max(c0 + t / 3 - 1, 0), 255);
            int gj = min(max(c1 + t % 3 - 1, 0), 255);
            src = ((b * 256 + gi) * 256 + gj) * 4 + 0;
        }
        g_rowsrc[e] = src;
    } else if (bid < o3) {                               // wt split
        int id = (bid - o2) * 256 + tid;
        if (id >= nl * 256 * 128) return;
        int li = id / (256 * 128);
        int r  = id % (256 * 128);
        int n = r / 128, k = r % 128;
        float w = (n < 128) ? Wk[li*DM*DM + k*DM + n] : Wv[li*DM*DM + k*DM + (n - 128)];
        __nv_bfloat16 hi = __float2bfloat16(w);
        g_WBhi[id] = hi;
        g_WBlo[id] = __float2bfloat16(w - __bfloat162float(hi));
    } else if (bid < o4) {                               // qcs
        int q = (bid - o3) * 256 + tid;
        if (q >= N) return;
        float p0 = qpos[2*q], p1 = qpos[2*q+1];
        float* cs = &g_qcs[q * 16];
        #pragma unroll
        for (int f = 0; f < 4; f++) {
            float a0 = p0 * c_invfreq[f];
            float a1 = p1 * c_invfreq[f];
            cs[f]      = cosf(a0);  cs[8  + f] = sinf(a0);
            cs[4 + f]  = cosf(a1);  cs[12 + f] = sinf(a1);
        }
    } else if (bid < o5) {                               // build_keys (idx with valid in bit31)
        int id = (bid - o4) * 256 + tid;
        if (id >= N * KTOT) return;
        int q = id / KTOT, k = id % KTOT;
        int l, t, d;
        if      (k < 9)  { l = 0; t = k;      d = 3; }
        else if (k < 34) { l = 1; t = k - 9;  d = 5; }
        else if (k < 83) { l = 2; t = k - 34; d = 7; }
        else             { l = 3; t = k - 83; d = 9; }
        int Hl = shapes[2*l], Wl = shapes[2*l+1];
        float sh = (float)Hl / (float)shapes[0];
        float sw = (float)Wl / (float)shapes[1];
        int c0 = (int)floorf(qpos[2*q] * sh), c1 = (int)floorf(qpos[2*q+1] * sw);
        int gi = c0 + t / d - d / 2;
        int gj = c1 + t % d - d / 2;
        int valid = (gi >= 0 && gi < Hl && gj >= 0 && gj < Wl);
        int ci = min(max(gi, 0), Hl - 1), cj = min(max(gj, 0), Wl - 1);
        int b = batch_of(q, qbo, n_off);
        int idx;
        if (l == 0) idx = R123 + q * 9 + t;
        else {
            int base = (l == 1) ? 0 : (l == 2) ? 16384 : 20480;
            idx = b * PER_B + base + ci * Wl + cj;
        }
        g_kidx[id] = (int)((unsigned)idx | (valid ? 0u : 0x80000000u));
    } else {                                             // build_rcs (direct sincos; no table dep)
        int e = (bid - o5) * 256 + tid;
        if (e >= R * 16) return;
        int row = e >> 4, idx = e & 15;
        int l, gi, gj;
        if (row < R123) {
            int r = row % PER_B;
            if (r < 16384)      { l = 1; gi = r >> 7; gj = r & 127; }
            else if (r < 20480) { int rr = r - 16384; l = 2; gi = rr >> 6; gj = rr & 63; }
            else                { int rr = r - 20480; l = 3; gi = rr >> 5; gj = rr & 31; }
        } else {
            int e2 = row - R123;
            int q = e2 / 9, t = e2 % 9;
            l = 0;
            gi = min(max((int)floorf(qpos[2*q])   + t / 3 - 1, 0), 255);
            gj = min(max((int)floorf(qpos[2*q+1]) + t % 3 - 1, 0), 255);
        }
        int trig = idx >> 3, p = idx & 7, axis = p >> 2, f = p & 3;
        int g = axis ? gj : gi;
        float scale = (float)shapes[2*l + axis] / (float)shapes[axis];
        float kp = ((float)g + 0.5f) / scale;
        float a = kp * c_invfreq[f];
        g_rcs[e] = trig ? sinf(a) : cosf(a);
    }
}

__global__ void ln_qproj_kernel(const float* __restrict__ lg, const float* __restrict__ lb,
                                const float* __restrict__ Wq) {
    ln_qproj_body(blockIdx.x, lg, lb, Wq);
}

// ---------------- mma.sync KV projection (rope fused into K epilogue) ----------------
#define A_STR 136
#define B_STR 40
#define OFF_AHI 0
#define OFF_ALO 34816
#define OFF_BHI 69632
#define OFF_BLO 79872
#define SM_MMA_TOTAL 90112

__global__ void __launch_bounds__(256, 2)
kvproj_mma_kernel(const float* __restrict__ fm, int li, int R, int buf) {
    extern __shared__ char smem[];
    uint32_t sbase = smem_u32(smem);
    int tid = threadIdx.x;
    int wid = tid >> 5, lane = tid & 31;
    int wm = wid & 3, wn = wid >> 2;
    int row0 = blockIdx.x * 128;

    #pragma unroll
    for (int it = 0; it < 16; it++) {
        int idx = tid + 256 * it;
        int r = idx >> 5, c4 = idx & 31;
        int row = row0 + r; if (row >= R) row = R - 1;
        int src = g_rowsrc[row];
        float4 v = *(const float4*)(fm + (size_t)src * 128 + c4 * 4);
        __nv_bfloat16 hx = __float2bfloat16(v.x);
        __nv_bfloat16 hy = __float2bfloat16(v.y);
        __nv_bfloat16 hz = __float2bfloat16(v.z);
        __nv_bfloat16 hw = __float2bfloat16(v.w);
        uint32_t h01 = ((uint32_t)*(uint16_t*)&hy << 16) | *(uint16_t*)&hx;
        uint32_t h23 = ((uint32_t)*(uint16_t*)&hw << 16) | *(uint16_t*)&hz;
        uint32_t l01 = bf2(bflo(v.x, hx), bflo(v.y, hy));
        uint32_t l23 = bf2(bflo(v.z, hz), bflo(v.w, hw));
        uint32_t off = (uint32_t)(r * A_STR + c4 * 4) * 2;
        *(uint2*)(smem + OFF_AHI + off) = make_uint2(h01, h23);
        *(uint2*)(smem + OFF_ALO + off) = make_uint2(l01, l23);
    }

    const __nv_bfloat16* wbh = g_WBhi + (size_t)li * 256 * 128;
    const __nv_bfloat16* wbl = g_WBlo + (size_t)li * 256 * 128;

    for (int h = 0; h < 2; h++) {
        float acc[2][8][4];
        #pragma unroll
        for (int i = 0; i < 2; i++)
            #pragma unroll
            for (int j = 0; j < 8; j++)
                #pragma unroll
                for (int e = 0; e < 4; e++) acc[i][j][e] = 0.f;

        for (int c = 0; c < 4; c++) {
            __syncthreads();
            #pragma unroll
            for (int it = 0; it < 2; it++) {
                int idx = tid + 256 * it;
                int n = idx >> 2, kk = (idx & 3) * 8;
                const __nv_bfloat16* sh = wbh + ((size_t)(h * 128 + n)) * 128 + c * 32 + kk;
                const __nv_bfloat16* sl = wbl + ((size_t)(h * 128 + n)) * 128 + c * 32 + kk;
                uint32_t off = (uint32_t)(n * B_STR + kk) * 2;
                *(uint4*)(smem + OFF_BHI + off) = *(const uint4*)sh;
                *(uint4*)(smem + OFF_BLO + off) = *(const uint4*)sl;
            }
            __syncthreads();

            #pragma unroll
            for (int s = 0; s < 2; s++) {
                uint32_t ah[2][4], al[2][4];
                #pragma unroll
                for (int i = 0; i < 2; i++) {
                    uint32_t arow = wm * 32 + i * 16 + (lane & 15);
                    uint32_t akol = c * 32 + s * 16 + ((lane >> 4) << 3);
                    uint32_t aoff = (arow * A_STR + akol) * 2;
                    ldsm_x4(sbase + OFF_AHI + aoff, ah[i][0], ah[i][1], ah[i][2], ah[i][3]);
                    ldsm_x4(sbase + OFF_ALO + aoff, al[i][0], al[i][1], al[i][2], al[i][3]);
                }
                #pragma unroll
                for (int jj = 0; jj < 4; jj++) {
                    int m = lane >> 3, w8 = lane & 7;
                    uint32_t bn = wn * 64 + (2 * jj + (m >> 1)) * 8 + w8;
                    uint32_t bk = s * 16 + (m & 1) * 8;
                    uint32_t boff = (bn * B_STR + bk) * 2;
                    uint32_t bh0, bh1, bh2, bh3, bl0, bl1, bl2, bl3;
                    ldsm_x4(sbase + OFF_BHI + boff, bh0, bh1, bh2, bh3);
                    ldsm_x4(sbase + OFF_BLO + boff, bl0, bl1, bl2, bl3);
                    #pragma unroll
                    for (int i = 0; i < 2; i++) {
                        mma_bf16(acc[i][2*jj],   ah[i][0], ah[i][1], ah[i][2], ah[i][3], bh0, bh1);
                        mma_bf16(acc[i][2*jj],   ah[i][0], ah[i][1], ah[i][2], ah[i][3], bl0, bl1);
                        mma_bf16(acc[i][2*jj],   al[i][0], al[i][1], al[i][2], al[i][3], bh0, bh1);
                        mma_bf16(acc[i][2*jj+1], ah[i][0], ah[i][1], ah[i][2], ah[i][3], bh2, bh3);
                        mma_bf16(acc[i][2*jj+1], ah[i][0], ah[i][1], ah[i][2], ah[i][3], bl2, bl3);
                        mma_bf16(acc[i][2*jj+1], al[i][0], al[i][1], al[i][2], al[i][3], bh2, bh3);
                    }
                }
            }
        }
        float* dstbase = h ? g_Vc[buf] : g_Kc[buf];
        int pb = lane & 3;
        #pragma unroll
        for (int i = 0; i < 2; i++) {
            int rA = row0 + wm * 32 + i * 16 + (lane >> 2);
            int rB = rA + 8;
            if (h == 0) {
                float cA0 = g_rcs[rA*16 + pb],     sA0 = g_rcs[rA*16 + 8 + pb];
                float cA1 = g_rcs[rA*16 + 4 + pb], sA1 = g_rcs[rA*16 + 12 + pb];
                float cB0 = g_rcs[rB*16 + pb],     sB0 = g_rcs[rB*16 + 8 + pb];
                float cB1 = g_rcs[rB*16 + 4 + pb], sB1 = g_rcs[rB*16 + 12 + pb];
                #pragma unroll
                for (int j = 0; j < 8; j++) {
                    int col = wn * 64 + j * 8 + pb * 2;
                    float cc = (j & 1) ? cA1 : cA0, ss = (j & 1) ? sA1 : sA0;
                    float a0 = acc[i][j][0], a1 = acc[i][j][1];
                    if (rA < R) *(float2*)(dstbase + (size_t)rA * 128 + col) =
                        make_float2(a0 * cc - a1 * ss, a0 * ss + a1 * cc);
                    float cc2 = (j & 1) ? cB1 : cB0, ss2 = (j & 1) ? sB1 : sB0;
                    float b0 = acc[i][j][2], b1 = acc[i][j][3];
                    if (rB < R) *(float2*)(dstbase + (size_t)rB * 128 + col) =
                        make_float2(b0 * cc2 - b1 * ss2, b0 * ss2 + b1 * cc2);
                }
            } else {
                #pragma unroll
                for (int j = 0; j < 8; j++) {
                    int col = wn * 64 + j * 8 + pb * 2;
                    if (rA < R) *(float2*)(dstbase + (size_t)rA * 128 + col) = make_float2(acc[i][j][0], acc[i][j][1]);
                    if (rB < R) *(float2*)(dstbase + (size_t)rB * 128 + col) = make_float2(acc[i][j][2], acc[i][j][3]);
                }
            }
        }
    }
}

// ---------------- attention (K pre-rotated; validity folded into kidx bit31) ----------------
__global__ void attn_kernel(int buf) {
    int q = blockIdx.x, tid = threadIdx.x;
    int lane = tid & 31, w = tid >> 5;
    __shared__ float sq[128];
    __shared__ float ssc[8 * KTOT];
    __shared__ int   skidx[KTOT];
    __shared__ float smask[KTOT];
    const float* Kc = g_Kc[buf];
    const float* Vc = g_Vc[buf];
    sq[tid] = g_q[q*DM + tid];
    for (int k = tid; k < KTOT; k += 128) {
        unsigned e = (unsigned)g_kidx[q*KTOT + k];
        skidx[k] = (int)(e & 0x7FFFFFFFu);
        smask[k] = (e & 0x80000000u) ? -1.0e9f : 0.f;
    }
    __syncthreads();
    float4 qv = *(const float4*)&sq[lane * 4];
    for (int k = w; k < KTOT; k += 4) {
        int idx = skidx[k];
        float4 kv = *(const float4*)&Kc[(size_t)idx*DM + lane*4];
        float ps = kv.x*qv.x + kv.y*qv.y + kv.z*qv.z + kv.w*qv.w;
        ps += __shfl_xor_sync(0xffffffffu, ps, 1);
        ps += __shfl_xor_sync(0xffffffffu, ps, 2);
        if ((lane & 3) == 0) {
            int h = lane >> 2;
            ssc[h*KTOT + k] = ps * 0.25f + smask[k];
        }
    }
    __syncthreads();
    #pragma unroll
    for (int hh = 0; hh < 2; hh++) {
        int h = w * 2 + hh;
        float mx = -3.0e38f;
        for (int k = lane; k < KTOT; k += 32) mx = fmaxf(mx, ssc[h*KTOT + k]);
        #pragma unroll
        for (int o = 16; o; o >>= 1) mx = fmaxf(mx, __shfl_xor_sync(0xffffffffu, mx, o));
        float sum = 0.f;
        for (int k = lane; k < KTOT; k += 32) {
            float e = expf(ssc[h*KTOT + k] - mx);
            ssc[h*KTOT + k] = e;
            sum += e;
        }
        #pragma unroll
        for (int o = 16; o; o >>= 1) sum += __shfl_xor_sync(0xffffffffu, sum, o);
        float inv = 1.f / sum;
        for (int k = lane; k < KTOT; k += 32) ssc[h*KTOT + k] *= inv;
    }
    __syncthreads();
    int h = tid >> 4;
    float acc = 0.f;
    #pragma unroll 4
    for (int k = 0; k < KTOT; k++)
        acc += ssc[h*KTOT + k] * Vc[(size_t)skidx[k]*DM + tid];
    g_o[q*DM + tid] = acc;
}

__global__ void oproj_ln2_kernel(const float* __restrict__ Wo,
                                 const float* __restrict__ lg, const float* __restrict__ lb) {
    int q = blockIdx.x, tid = threadIdx.x;
    int lane = tid & 31, w = tid >> 5;
    __shared__ float so[128];
    __shared__ float red[8];
    so[tid] = g_o[q*DM + tid];
    __syncthreads();
    float acc = 0.f;
    #pragma unroll 8
    for (int i = 0; i < 128; i++) acc += so[i] * Wo[i * DM + tid];
    float x = g_x[q*DM + tid] + acc;
    g_x[q*DM + tid] = x;
    float s1 = x, s2 = x * x;
    #pragma unroll
    for (int o = 16; o; o >>= 1) {
        s1 += __shfl_xor_sync(0xffffffffu, s1, o);
        s2 += __shfl_xor_sync(0xffffffffu, s2, o);
    }
    if (lane == 0) { red[w] = s1; red[4 + w] = s2; }
    __syncthreads();
    float mean = (red[0] + red[1] + red[2] + red[3]) * (1.f / 128.f);
    float var  = (red[4] + red[5] + red[6] + red[7]) * (1.f / 128.f) - mean * mean;
    g_h[q*DM + tid] = (x - mean) * rsqrtf(var + 1e-5f) * lg[tid] + lb[tid];
}

// t = gelu(h @ W1 + b1), then x += t @ W2 + b2.  8 q/block, 256 thr
__global__ void ffn_kernel(const float* __restrict__ W1, const float* __restrict__ b1v,
                           const float* __restrict__ W2, const float* __restrict__ b2v, int N) {
    int q0 = blockIdx.x * 8, tid = threadIdx.x;
    __shared__ float sh2[8][128];
    __shared__ float st[8][512];
    for (int i = tid; i < 1024; i += 256) {
        int r = i >> 7, c = i & 127;
        int q = q0 + r;
        sh2[r][c] = (q < N) ? g_h[q*DM + c] : 0.f;
    }
    __syncthreads();
    {
        ull acc0[4], acc1[4];
        #pragma unroll
        for (int p = 0; p < 4; p++) { acc0[p] = 0ull; acc1[p] = 0ull; }
        #pragma unroll 4
        for (int i = 0; i < 128; i++) {
            ull w0 = pack2(W1[i*512 + tid]);
            ull w1 = pack2(W1[i*512 + 256 + tid]);
            #pragma unroll
            for (int p = 0; p < 4; p++) {
                ull hp = packab(sh2[2*p][i], sh2[2*p+1][i]);
                acc0[p] = fma2(hp, w0, acc0[p]);
                acc1[p] = fma2(hp, w1, acc1[p]);
            }
        }
        float bb0 = b1v[tid], bb1 = b1v[256 + tid];
        #pragma unroll
        for (int p = 0; p < 4; p++) {
            float a0, a1, c0, c1;
            unpack2(acc0[p], a0, a1);
            unpack2(acc1[p], c0, c1);
            st[2*p][tid]           = gelu_tanh(a0 + bb0);
            st[2*p][256 + tid]     = gelu_tanh(c0 + bb1);
            st[2*p + 1][tid]       = gelu_tanh(a1 + bb0);
            st[2*p + 1][256 + tid] = gelu_tanh(c1 + bb1);
        }
    }
    __syncthreads();
    {
        int col = tid & 127, half = tid >> 7;
        ull a01 = 0ull, a23 = 0ull;
        #pragma unroll 4
        for (int i = 0; i < 512; i++) {
            ull wv = pack2(W2[i*128 + col]);
            a01 = fma2(packab(st[half*4 + 0][i], st[half*4 + 1][i]), wv, a01);
            a23 = fma2(packab(st[half*4 + 2][i], st[half*4 + 3][i]), wv, a23);
        }
        float v0, v1, v2, v3;
        unpack2(a01, v0, v1);
        unpack2(a23, v2, v3);
        float bb = b2v[col];
        int qb = q0 + half * 4;
        if (qb + 0 < N) g_x[(qb+0)*DM + col] += v0 + bb;
        if (qb + 1 < N) g_x[(qb+1)*DM + col] += v1 + bb;
        if (qb + 2 < N) g_x[(qb+2)*DM + col] += v2 + bb;
        if (qb + 3 < N) g_x[(qb+3)*DM + col] += v3 + bb;
    }
}

__global__ void logits_kernel(const float* __restrict__ fm, const float* __restrict__ qpos,
                              const int* __restrict__ qbo, int n_off,
                              const int* __restrict__ shapes, float* __restrict__ out) {
    int q = blockIdx.x, tid = threadIdx.x;
    int lane = tid & 31, w = tid >> 5;
    __shared__ float sx[128];
    __shared__ int sb;
    if (tid < 128) sx[tid] = g_x[q*DM + tid];
    if (tid == 0) sb = batch_of(q, qbo, n_off);
    __syncthreads();
    int H0 = shapes[0], W0 = shapes[1];
    float p0 = qpos[2*q], p1 = qpos[2*q+1];
    int c0 = (int)floorf(p0), c1 = (int)floorf(p1);
    float4 xv = *(const float4*)&sx[lane * 4];
    int b = sb;
    for (int pp = w; pp < 49; pp += 8) {
        int gi = c0 + pp / 7 - 3;
        int gj = c1 + pp % 7 - 3;
        bool valid = (gi >= 0 && gi < H0 && gj >= 0 && gj < W0);
        int ci = min(max(gi, 0), H0 - 1), cj = min(max(gj, 0), W0 - 1);
        const float* f = fm + ((((size_t)b * 256 + ci) * 256 + cj) * 4 + 0) * 128;
        float4 fv = *(const float4*)(f + lane * 4);
        float d = fv.x*xv.x + fv.y*xv.y + fv.z*xv.z + fv.w*xv.w;
        #pragma unroll
        for (int o = 16; o; o >>= 1) d += __shfl_xor_sync(0xffffffffu, d, o);
        if (lane == 0) out[q*49 + pp] = valid ? d : 0.f;
    }
}

// ---------------- launch ----------------
extern "C" void kernel_launch(void* const* d_in, const int* in_sizes, int n_in,
                              void* d_out, int out_size) {
    const float* queries = (const float*)d_in[0];
    const int*   qbo     = (const int*)  d_in[1];
    const float* qpos    = (const float*)d_in[2];
    const float* fm      = (const float*)d_in[3];
    const int*   shapes  = (const int*)  d_in[4];
    const float* Wq      = (const float*)d_in[5];
    const float* Wk      = (const float*)d_in[6];
    const float* Wv      = (const float*)d_in[7];
    const float* Wo      = (const float*)d_in[8];
    const float* ln1g    = (const float*)d_in[9];
    const float* ln1b    = (const float*)d_in[10];
    const float* ln2g    = (const float*)d_in[11];
    const float* ln2b    = (const float*)d_in[12];
    const float* W1      = (const float*)d_in[13];
    const float* b1      = (const float*)d_in[14];
    const float* W2      = (const float*)d_in[15];
    const float* b2      = (const float*)d_in[16];

    int N     = in_sizes[0] / DM;
    int n_off = in_sizes[1];
    int nl    = in_sizes[5] / (DM * DM);
    int B     = in_sizes[3] / (256 * 256 * 4 * DM);
    int R123  = B * PER_B;
    int R     = R123 + N * 9;
    int gridR = (R + 127) / 128;

    cudaFuncSetAttribute(kvproj_mma_kernel, cudaFuncAttributeMaxDynamicSharedMemorySize, SM_MMA_TOTAL);

    int s0 = (N * DM + 255) / 256;
    int s1 = (R + 255) / 256;
    int s2 = (nl * 256 * 128 + 255) / 256;
    int s3 = (N + 255) / 256;
    int s4 = (N * KTOT + 255) / 256;
    int s5 = (R * 16 + 255) / 256;
    int o1 = s0, o2 = o1 + s1, o3 = o2 + s2, o4 = o3 + s3, o5 = o4 + s4;
    int gridP1 = o5 + s5;

    prep1_kernel<<<gridP1, 256>>>(queries, qpos, qbo, n_off, shapes, Wk, Wv,
                                  N, nl, R123, R, o1, o2, o3, o4, o5);

    bool overlap = (nl == 2);
    cudaStream_t sKV = 0;
    cudaEvent_t evReady = 0, evKv0 = 0, evKv1 = 0;
    if (overlap) {
        if (cudaStreamCreateWithFlags(&sKV, cudaStreamNonBlocking) != cudaSuccess ||
            cudaEventCreateWithFlags(&evReady, cudaEventDisableTiming) != cudaSuccess ||
            cudaEventCreateWithFlags(&evKv0, cudaEventDisableTiming) != cudaSuccess ||
            cudaEventCreateWithFlags(&evKv1, cudaEventDisableTiming) != cudaSuccess) {
            overlap = false;
        }
    }

    if (overlap) {
        // fork after prep1: both kvprojs run on sKV while main does ln_qproj(L0) etc.
        cudaEventRecord(evReady, 0);
        cudaStreamWaitEvent(sKV, evReady, 0);
        kvproj_mma_kernel<<<gridR, 256, SM_MMA_TOTAL, sKV>>>(fm, 0, R, 0);
        cudaEventRecord(evKv0, sKV);
        kvproj_mma_kernel<<<gridR, 256, SM_MMA_TOTAL, sKV>>>(fm, 1, R, 1);
        cudaEventRecord(evKv1, sKV);

        ln_qproj_kernel<<<N, 128>>>(ln1g, ln1b, Wq);

        cudaStreamWaitEvent(0, evKv0, 0);
        attn_kernel<<<N, 128>>>(0);
        oproj_ln2_kernel<<<N, 128>>>(Wo, ln2g, ln2b);
        ffn_kernel<<<(N + 7) / 8, 256>>>(W1, b1, W2, b2, N);
        ln_qproj_kernel<<<N, 128>>>(ln1g + DM, ln1b + DM, Wq + DM*DM);

        cudaStreamWaitEvent(0, evKv1, 0);
        attn_kernel<<<N, 128>>>(1);
        oproj_ln2_kernel<<<N, 128>>>(Wo + DM*DM, ln2g + DM, ln2b + DM);
        ffn_kernel<<<(N + 7) / 8, 256>>>(W1 + DM*512, b1 + 512, W2 + 512*DM, b2 + DM, N);
    } else {
        kvproj_mma_kernel<<<gridR, 256, SM_MMA_TOTAL>>>(fm, 0, R, 0);
        ln_qproj_kernel<<<N, 128>>>(ln1g, ln1b, Wq);
        attn_kernel<<<N, 128>>>(0);
        oproj_ln2_kernel<<<N, 128>>>(Wo, ln2g, ln2b);
        ffn_kernel<<<(N + 7) / 8, 256>>>(W1, b1, W2, b2, N);
        for (int li = 1; li < nl; li++) {
            int buf = li & 1;
            kvproj_mma_kernel<<<gridR, 256, SM_MMA_TOTAL>>>(fm, li, R, buf);
            ln_qproj_kernel<<<N, 128>>>(ln1g + li*DM, ln1b + li*DM, Wq + li*DM*DM);
            attn_kernel<<<N, 128>>>(buf);
            oproj_ln2_kernel<<<N, 128>>>(Wo + li*DM*DM, ln2g + li*DM, ln2b + li*DM);
            ffn_kernel<<<(N + 7) / 8, 256>>>(W1 + li*DM*512, b1 + li*512, W2 + li*512*DM, b2 + li*DM, N);
        }
    }
    logits_kernel<<<N, 256>>>(fm, qpos, qbo, n_off, shapes, (float*)d_out);
    // streams/events intentionally not destroyed mid-capture (host-side handles only)
}

// round 16
// speedup vs baseline: 1.0807x; 1.0084x over previous
#include <cuda_runtime.h>
#include <cuda_bf16.h>
#include <math.h>
#include <stdint.h>

#define DM   128
#define NH   8
#define HD   16
#define KTOT 164          // 9 + 25 + 49 + 81
#define PER_B 21504       // 128*128 + 64*64 + 32*32
#define MAXN 2048
#define MAXROWS (2*PER_B + MAXN*9)
#define MAXL 4

typedef unsigned long long ull;

// ---------------- device scratch ----------------
__device__ float g_x  [MAXN*DM];
__device__ float g_q  [MAXN*DM];
__device__ float g_o  [MAXN*DM];
__device__ float g_h  [MAXN*DM];
__device__ float g_qcs[MAXN*16];
__device__ int   g_kidx[MAXN*KTOT];              // bit31 set = INVALID key
__device__ int   g_rowsrc[MAXROWS];
__device__ float g_rcs[MAXROWS*16];              // per-row RoPE cos/sin
__device__ float g_Kc[2][(size_t)MAXROWS*DM];    // ping-pong buffers
__device__ float g_Vc[2][(size_t)MAXROWS*DM];
__device__ __align__(16) __nv_bfloat16 g_WBhi[MAXL*256*128];   // [layer][n: Wk|Wv][k]
__device__ __align__(16) __nv_bfloat16 g_WBlo[MAXL*256*128];

__device__ __constant__ float c_invfreq[4] = {1.0f, 0.56234132519f, 0.316227766017f, 0.177827941004f};

// ---------------- helpers ----------------
__device__ __forceinline__ ull fma2(ull a, ull b, ull c) {
    ull d; asm("fma.rn.f32x2 %0, %1, %2, %3;" : "=l"(d) : "l"(a), "l"(b), "l"(c)); return d;
}
__device__ __forceinline__ ull pack2(float f) {
    ull r; asm("mov.b64 %0, {%1, %1};" : "=l"(r) : "r"(__float_as_uint(f))); return r;
}
__device__ __forceinline__ ull packab(float a, float b) {
    ull r; asm("mov.b64 %0, {%1, %2};" : "=l"(r) : "r"(__float_as_uint(a)), "r"(__float_as_uint(b))); return r;
}
__device__ __forceinline__ void unpack2(ull v, float& lo, float& hi) {
    unsigned int a, b; asm("mov.b64 {%0, %1}, %2;" : "=r"(a), "=r"(b) : "l"(v));
    lo = __uint_as_float(a); hi = __uint_as_float(b);
}
__device__ __forceinline__ float gelu_tanh(float v) {
    float u = 0.7978845608028654f * (v + 0.044715f * v * v * v);
    return 0.5f * v * (1.f + tanhf(u));
}
__device__ __forceinline__ int batch_of(int q, const int* qbo, int n_off) {
    int b = 0;
    for (int t = 1; t < n_off - 1; t++) if (q >= qbo[t]) b = t;
    return b;
}
__device__ __forceinline__ uint32_t smem_u32(const void* p) {
    uint32_t a;
    asm("{ .reg .u64 t; cvta.to.shared.u64 t, %1; cvt.u32.u64 %0, t; }" : "=r"(a) : "l"(p));
    return a;
}
__device__ __forceinline__ uint32_t bf2(float a, float b) {
    __nv_bfloat162 h = __floats2bfloat162_rn(a, b);
    return *(uint32_t*)&h;
}
__device__ __forceinline__ float bflo(float x, __nv_bfloat16 hi) {
    return x - __bfloat162float(hi);
}
__device__ __forceinline__ void ldsm_x4(uint32_t addr, uint32_t& r0, uint32_t& r1, uint32_t& r2, uint32_t& r3) {
    asm volatile("ldmatrix.sync.aligned.m8n8.x4.shared.b16 {%0,%1,%2,%3}, [%4];"
                 : "=r"(r0), "=r"(r1), "=r"(r2), "=r"(r3) : "r"(addr));
}
__device__ __forceinline__ void mma_bf16(float* c, uint32_t a0, uint32_t a1, uint32_t a2, uint32_t a3,
                                         uint32_t b0, uint32_t b1) {
    asm volatile("mma.sync.aligned.m16n8k16.row.col.f32.bf16.bf16.f32 "
                 "{%0,%1,%2,%3}, {%4,%5,%6,%7}, {%8,%9}, {%0,%1,%2,%3};"
                 : "+f"(c[0]), "+f"(c[1]), "+f"(c[2]), "+f"(c[3])
                 : "r"(a0), "r"(a1), "r"(a2), "r"(a3), "r"(b0), "r"(b1));
}

// ---------------- LN1 + Qproj + RoPE body (per-query, 128 threads) ----------------
__device__ void ln_qproj_body(int q, const float* __restrict__ lg, const float* __restrict__ lb,
                              const float* __restrict__ Wq) {
    int tid = threadIdx.x;
    int lane = tid & 31, w = tid >> 5;
    __shared__ float sh[128];
    __shared__ float sraw[128];
    __shared__ float red[8];
    float x = g_x[q*DM + tid];
    float s1 = x, s2 = x * x;
    #pragma unroll
    for (int o = 16; o; o >>= 1) {
        s1 += __shfl_xor_sync(0xffffffffu, s1, o);
        s2 += __shfl_xor_sync(0xffffffffu, s2, o);
    }
    if (lane == 0) { red[w] = s1; red[4 + w] = s2; }
    __syncthreads();
    float mean = (red[0] + red[1] + red[2] + red[3]) * (1.f / 128.f);
    float var  = (red[4] + red[5] + red[6] + red[7]) * (1.f / 128.f) - mean * mean;
    sh[tid] = (x - mean) * rsqrtf(var + 1e-5f) * lg[tid] + lb[tid];
    __syncthreads();
    float acc = 0.f;
    #pragma unroll 8
    for (int i = 0; i < 128; i++) acc += sh[i] * Wq[i * DM + tid];
    sraw[tid] = acc;
    __syncthreads();
    int p = (tid >> 1) & 7;
    float c = g_qcs[q*16 + p], s = g_qcs[q*16 + 8 + p];
    float x1 = sraw[tid & ~1];
    float x2 = sraw[tid |  1];
    g_q[q*DM + tid] = (tid & 1) ? (x1 * s + x2 * c) : (x1 * c - x2 * s);
}

// ---------------- prepA: what kvproj needs (rowsrc | wt-split | rcs-per-row) ----------------
__global__ void prepA_kernel(const float* __restrict__ qpos,
                             const int* __restrict__ qbo, int n_off,
                             const int* __restrict__ shapes,
                             const float* __restrict__ Wk, const float* __restrict__ Wv,
                             int nl, int R123, int R,
                             int a1, int a2) {
    int bid = blockIdx.x, tid = threadIdx.x;
    if (bid < a1) {                                      // rowsrc
        int e = bid * 256 + tid;
        if (e >= R) return;
        int src;
        if (e < R123) {
            int b = e / PER_B, r = e % PER_B;
            int l, i, j;
            if (r < 16384)      { l = 1; i = r >> 7; j = r & 127; }
            else if (r < 20480) { int rr = r - 16384; l = 2; i = rr >> 6; j = rr & 63; }
            else                { int rr = r - 20480; l = 3; i = rr >> 5; j = rr & 31; }
            src = ((b * 256 + i) * 256 + j) * 4 + l;
        } else {
            int e2 = e - R123;
            int q = e2 / 9, t = e2 % 9;
            int b = batch_of(q, qbo, n_off);
            int c0 = (int)floorf(qpos[2*q]), c1 = (int)floorf(qpos[2*q+1]);
            int gi = min(max(c0 + t / 3 - 1, 0), 255);
            int gj = min(max(c1 + t % 3 - 1, 0), 255);
            src = ((b * 256 + gi) * 256 + gj) * 4 + 0;
        }
        g_rowsrc[e] = src;
    } else if (bid < a2) {                               // wt split
        int id = (bid - a1) * 256 + tid;
        if (id >= nl * 256 * 128) return;
        int li = id / (256 * 128);
        int r  = id % (256 * 128);
        int n = r / 128, k = r % 128;
        float w = (n < 128) ? Wk[li*DM*DM + k*DM + n] : Wv[li*DM*DM + k*DM + (n - 128)];
        __nv_bfloat16 hi = __float2bfloat16(w);
        g_WBhi[id] = hi;
        g_WBlo[id] = __float2bfloat16(w - __bfloat162float(hi));
    } else {                                             // rcs: one thread per row
        int row = (bid - a2) * 256 + tid;
        if (row >= R) return;
        int l, gi, gj;
        if (row < R123) {
            int r = row % PER_B;
            if (r < 16384)      { l = 1; gi = r >> 7; gj = r & 127; }
            else if (r < 20480) { int rr = r - 16384; l = 2; gi = rr >> 6; gj = rr & 63; }
            else                { int rr = r - 20480; l = 3; gi = rr >> 5; gj = rr & 31; }
        } else {
            int e2 = row - R123;
            int q = e2 / 9, t = e2 % 9;
            l = 0;
            gi = min(max((int)floorf(qpos[2*q])   + t / 3 - 1, 0), 255);
            gj = min(max((int)floorf(qpos[2*q+1]) + t % 3 - 1, 0), 255);
        }
        float* dst = &g_rcs[(size_t)row * 16];
        #pragma unroll
        for (int axis = 0; axis < 2; axis++) {
            float scale = (float)shapes[2*l + axis] / (float)shapes[axis];
            float kp = ((float)(axis ? gj : gi) + 0.5f) / scale;
            #pragma unroll
            for (int f = 0; f < 4; f++) {
                float a = kp * c_invfreq[f];
                dst[axis * 4 + f]     = cosf(a);
                dst[8 + axis * 4 + f] = sinf(a);
            }
        }
    }
}

// ---------------- prepB: what the main path needs (copy_x | qcs | build_keys) ----------------
__global__ void prepB_kernel(const float* __restrict__ queries,
                             const float* __restrict__ qpos,
                             const int* __restrict__ qbo, int n_off,
                             const int* __restrict__ shapes,
                             int N, int R123,
                             int b1, int b2) {
    int bid = blockIdx.x, tid = threadIdx.x;
    if (bid < b1) {                                      // copy_x
        int i = bid * 256 + tid;
        if (i < N * DM) g_x[i] = queries[i];
    } else if (bid < b2) {                               // qcs
        int q = (bid - b1) * 256 + tid;
        if (q >= N) return;
        float p0 = qpos[2*q], p1 = qpos[2*q+1];
        float* cs = &g_qcs[q * 16];
        #pragma unroll
        for (int f = 0; f < 4; f++) {
            float a0 = p0 * c_invfreq[f];
            float a1 = p1 * c_invfreq[f];
            cs[f]      = cosf(a0);  cs[8  + f] = sinf(a0);
            cs[4 + f]  = cosf(a1);  cs[12 + f] = sinf(a1);
        }
    } else {                                             // build_keys (idx with valid in bit31)
        int id = (bid - b2) * 256 + tid;
        if (id >= N * KTOT) return;
        int q = id / KTOT, k = id % KTOT;
        int l, t, d;
        if      (k < 9)  { l = 0; t = k;      d = 3; }
        else if (k < 34) { l = 1; t = k - 9;  d = 5; }
        else if (k < 83) { l = 2; t = k - 34; d = 7; }
        else             { l = 3; t = k - 83; d = 9; }
        int Hl = shapes[2*l], Wl = shapes[2*l+1];
        float sh = (float)Hl / (float)shapes[0];
        float sw = (float)Wl / (float)shapes[1];
        int c0 = (int)floorf(qpos[2*q] * sh), c1 = (int)floorf(qpos[2*q+1] * sw);
        int gi = c0 + t / d - d / 2;
        int gj = c1 + t % d - d / 2;
        int valid = (gi >= 0 && gi < Hl && gj >= 0 && gj < Wl);
        int ci = min(max(gi, 0), Hl - 1), cj = min(max(gj, 0), Wl - 1);
        int b = batch_of(q, qbo, n_off);
        int idx;
        if (l == 0) idx = R123 + q * 9 + t;
        else {
            int base = (l == 1) ? 0 : (l == 2) ? 16384 : 20480;
            idx = b * PER_B + base + ci * Wl + cj;
        }
        g_kidx[id] = (int)((unsigned)idx | (valid ? 0u : 0x80000000u));
    }
}

__global__ void ln_qproj_kernel(const float* __restrict__ lg, const float* __restrict__ lb,
                                const float* __restrict__ Wq) {
    ln_qproj_body(blockIdx.x, lg, lb, Wq);
}

// ---------------- mma.sync KV projection (rope fused into K epilogue) ----------------
#define A_STR 136
#define B_STR 40
#define OFF_AHI 0
#define OFF_ALO 34816
#define OFF_BHI 69632
#define OFF_BLO 79872
#define SM_MMA_TOTAL 90112

__global__ void __launch_bounds__(256, 2)
kvproj_mma_kernel(const float* __restrict__ fm, int li, int R, int buf) {
    extern __shared__ char smem[];
    uint32_t sbase = smem_u32(smem);
    int tid = threadIdx.x;
    int wid = tid >> 5, lane = tid & 31;
    int wm = wid & 3, wn = wid >> 2;
    int row0 = blockIdx.x * 128;

    #pragma unroll
    for (int it = 0; it < 16; it++) {
        int idx = tid + 256 * it;
        int r = idx >> 5, c4 = idx & 31;
        int row = row0 + r; if (row >= R) row = R - 1;
        int src = g_rowsrc[row];
        float4 v = *(const float4*)(fm + (size_t)src * 128 + c4 * 4);
        __nv_bfloat16 hx = __float2bfloat16(v.x);
        __nv_bfloat16 hy = __float2bfloat16(v.y);
        __nv_bfloat16 hz = __float2bfloat16(v.z);
        __nv_bfloat16 hw = __float2bfloat16(v.w);
        uint32_t h01 = ((uint32_t)*(uint16_t*)&hy << 16) | *(uint16_t*)&hx;
        uint32_t h23 = ((uint32_t)*(uint16_t*)&hw << 16) | *(uint16_t*)&hz;
        uint32_t l01 = bf2(bflo(v.x, hx), bflo(v.y, hy));
        uint32_t l23 = bf2(bflo(v.z, hz), bflo(v.w, hw));
        uint32_t off = (uint32_t)(r * A_STR + c4 * 4) * 2;
        *(uint2*)(smem + OFF_AHI + off) = make_uint2(h01, h23);
        *(uint2*)(smem + OFF_ALO + off) = make_uint2(l01, l23);
    }

    const __nv_bfloat16* wbh = g_WBhi + (size_t)li * 256 * 128;
    const __nv_bfloat16* wbl = g_WBlo + (size_t)li * 256 * 128;

    for (int h = 0; h < 2; h++) {
        float acc[2][8][4];
        #pragma unroll
        for (int i = 0; i < 2; i++)
            #pragma unroll
            for (int j = 0; j < 8; j++)
                #pragma unroll
                for (int e = 0; e < 4; e++) acc[i][j][e] = 0.f;

        for (int c = 0; c < 4; c++) {
            __syncthreads();
            #pragma unroll
            for (int it = 0; it < 2; it++) {
                int idx = tid + 256 * it;
                int n = idx >> 2, kk = (idx & 3) * 8;
                const __nv_bfloat16* sh = wbh + ((size_t)(h * 128 + n)) * 128 + c * 32 + kk;
                const __nv_bfloat16* sl = wbl + ((size_t)(h * 128 + n)) * 128 + c * 32 + kk;
                uint32_t off = (uint32_t)(n * B_STR + kk) * 2;
                *(uint4*)(smem + OFF_BHI + off) = *(const uint4*)sh;
                *(uint4*)(smem + OFF_BLO + off) = *(const uint4*)sl;
            }
            __syncthreads();

            #pragma unroll
            for (int s = 0; s < 2; s++) {
                uint32_t ah[2][4], al[2][4];
                #pragma unroll
                for (int i = 0; i < 2; i++) {
                    uint32_t arow = wm * 32 + i * 16 + (lane & 15);
                    uint32_t akol = c * 32 + s * 16 + ((lane >> 4) << 3);
                    uint32_t aoff = (arow * A_STR + akol) * 2;
                    ldsm_x4(sbase + OFF_AHI + aoff, ah[i][0], ah[i][1], ah[i][2], ah[i][3]);
                    ldsm_x4(sbase + OFF_ALO + aoff, al[i][0], al[i][1], al[i][2], al[i][3]);
                }
                #pragma unroll
                for (int jj = 0; jj < 4; jj++) {
                    int m = lane >> 3, w8 = lane & 7;
                    uint32_t bn = wn * 64 + (2 * jj + (m >> 1)) * 8 + w8;
                    uint32_t bk = s * 16 + (m & 1) * 8;
                    uint32_t boff = (bn * B_STR + bk) * 2;
                    uint32_t bh0, bh1, bh2, bh3, bl0, bl1, bl2, bl3;
                    ldsm_x4(sbase + OFF_BHI + boff, bh0, bh1, bh2, bh3);
                    ldsm_x4(sbase + OFF_BLO + boff, bl0, bl1, bl2, bl3);
                    #pragma unroll
                    for (int i = 0; i < 2; i++) {
                        mma_bf16(acc[i][2*jj],   ah[i][0], ah[i][1], ah[i][2], ah[i][3], bh0, bh1);
                        mma_bf16(acc[i][2*jj],   ah[i][0], ah[i][1], ah[i][2], ah[i][3], bl0, bl1);
                        mma_bf16(acc[i][2*jj],   al[i][0], al[i][1], al[i][2], al[i][3], bh0, bh1);
                        mma_bf16(acc[i][2*jj+1], ah[i][0], ah[i][1], ah[i][2], ah[i][3], bh2, bh3);
                        mma_bf16(acc[i][2*jj+1], ah[i][0], ah[i][1], ah[i][2], ah[i][3], bl2, bl3);
                        mma_bf16(acc[i][2*jj+1], al[i][0], al[i][1], al[i][2], al[i][3], bh2, bh3);
                    }
                }
            }
        }
        float* dstbase = h ? g_Vc[buf] : g_Kc[buf];
        int pb = lane & 3;
        #pragma unroll
        for (int i = 0; i < 2; i++) {
            int rA = row0 + wm * 32 + i * 16 + (lane >> 2);
            int rB = rA + 8;
            if (h == 0) {
                float cA0 = g_rcs[rA*16 + pb],     sA0 = g_rcs[rA*16 + 8 + pb];
                float cA1 = g_rcs[rA*16 + 4 + pb], sA1 = g_rcs[rA*16 + 12 + pb];
                float cB0 = g_rcs[rB*16 + pb],     sB0 = g_rcs[rB*16 + 8 + pb];
                float cB1 = g_rcs[rB*16 + 4 + pb], sB1 = g_rcs[rB*16 + 12 + pb];
                #pragma unroll
                for (int j = 0; j < 8; j++) {
                    int col = wn * 64 + j * 8 + pb * 2;
                    float cc = (j & 1) ? cA1 : cA0, ss = (j & 1) ? sA1 : sA0;
                    float a0 = acc[i][j][0], a1 = acc[i][j][1];
                    if (rA < R) *(float2*)(dstbase + (size_t)rA * 128 + col) =
                        make_float2(a0 * cc - a1 * ss, a0 * ss + a1 * cc);
                    float cc2 = (j & 1) ? cB1 : cB0, ss2 = (j & 1) ? sB1 : sB0;
                    float b0 = acc[i][j][2], b1 = acc[i][j][3];
                    if (rB < R) *(float2*)(dstbase + (size_t)rB * 128 + col) =
                        make_float2(b0 * cc2 - b1 * ss2, b0 * ss2 + b1 * cc2);
                }
            } else {
                #pragma unroll
                for (int j = 0; j < 8; j++) {
                    int col = wn * 64 + j * 8 + pb * 2;
                    if (rA < R) *(float2*)(dstbase + (size_t)rA * 128 + col) = make_float2(acc[i][j][0], acc[i][j][1]);
                    if (rB < R) *(float2*)(dstbase + (size_t)rB * 128 + col) = make_float2(acc[i][j][2], acc[i][j][3]);
                }
            }
        }
    }
}

// ---------------- attention (K pre-rotated; validity folded into kidx bit31) ----------------
__global__ void attn_kernel(int buf) {
    int q = blockIdx.x, tid = threadIdx.x;
    int lane = tid & 31, w = tid >> 5;
    __shared__ float sq[128];
    __shared__ float ssc[8 * KTOT];
    __shared__ int   skidx[KTOT];
    __shared__ float smask[KTOT];
    const float* Kc = g_Kc[buf];
    const float* Vc = g_Vc[buf];
    sq[tid] = g_q[q*DM + tid];
    for (int k = tid; k < KTOT; k += 128) {
        unsigned e = (unsigned)g_kidx[q*KTOT + k];
        skidx[k] = (int)(e & 0x7FFFFFFFu);
        smask[k] = (e & 0x80000000u) ? -1.0e9f : 0.f;
    }
    __syncthreads();
    float4 qv = *(const float4*)&sq[lane * 4];
    for (int k = w; k < KTOT; k += 4) {
        int idx = skidx[k];
        float4 kv = *(const float4*)&Kc[(size_t)idx*DM + lane*4];
        float ps = kv.x*qv.x + kv.y*qv.y + kv.z*qv.z + kv.w*qv.w;
        ps += __shfl_xor_sync(0xffffffffu, ps, 1);
        ps += __shfl_xor_sync(0xffffffffu, ps, 2);
        if ((lane & 3) == 0) {
            int h = lane >> 2;
            ssc[h*KTOT + k] = ps * 0.25f + smask[k];
        }
    }
    __syncthreads();
    #pragma unroll
    for (int hh = 0; hh < 2; hh++) {
        int h = w * 2 + hh;
        float mx = -3.0e38f;
        for (int k = lane; k < KTOT; k += 32) mx = fmaxf(mx, ssc[h*KTOT + k]);
        #pragma unroll
        for (int o = 16; o; o >>= 1) mx = fmaxf(mx, __shfl_xor_sync(0xffffffffu, mx, o));
        float sum = 0.f;
        for (int k = lane; k < KTOT; k += 32) {
            float e = expf(ssc[h*KTOT + k] - mx);
            ssc[h*KTOT + k] = e;
            sum += e;
        }
        #pragma unroll
        for (int o = 16; o; o >>= 1) sum += __shfl_xor_sync(0xffffffffu, sum, o);
        float inv = 1.f / sum;
        for (int k = lane; k < KTOT; k += 32) ssc[h*KTOT + k] *= inv;
    }
    __syncthreads();
    int h = tid >> 4;
    float acc = 0.f;
    #pragma unroll 4
    for (int k = 0; k < KTOT; k++)
        acc += ssc[h*KTOT + k] * Vc[(size_t)skidx[k]*DM + tid];
    g_o[q*DM + tid] = acc;
}

__global__ void oproj_ln2_kernel(const float* __restrict__ Wo,
                                 const float* __restrict__ lg, const float* __restrict__ lb) {
    int q = blockIdx.x, tid = threadIdx.x;
    int lane = tid & 31, w = tid >> 5;
    __shared__ float so[128];
    __shared__ float red[8];
    so[tid] = g_o[q*DM + tid];
    __syncthreads();
    float acc = 0.f;
    #pragma unroll 8
    for (int i = 0; i < 128; i++) acc += so[i] * Wo[i * DM + tid];
    float x = g_x[q*DM + tid] + acc;
    g_x[q*DM + tid] = x;
    float s1 = x, s2 = x * x;
    #pragma unroll
    for (int o = 16; o; o >>= 1) {
        s1 += __shfl_xor_sync(0xffffffffu, s1, o);
        s2 += __shfl_xor_sync(0xffffffffu, s2, o);
    }
    if (lane == 0) { red[w] = s1; red[4 + w] = s2; }
    __syncthreads();
    float mean = (red[0] + red[1] + red[2] + red[3]) * (1.f / 128.f);
    float var  = (red[4] + red[5] + red[6] + red[7]) * (1.f / 128.f) - mean * mean;
    g_h[q*DM + tid] = (x - mean) * rsqrtf(var + 1e-5f) * lg[tid] + lb[tid];
}

// t = gelu(h @ W1 + b1), then x += t @ W2 + b2.  8 q/block, 256 thr
__global__ void ffn_kernel(const float* __restrict__ W1, const float* __restrict__ b1v,
                           const float* __restrict__ W2, const float* __restrict__ b2v, int N) {
    int q0 = blockIdx.x * 8, tid = threadIdx.x;
    __shared__ float sh2[8][128];
    __shared__ float st[8][512];
    for (int i = tid; i < 1024; i += 256) {
        int r = i >> 7, c = i & 127;
        int q = q0 + r;
        sh2[r][c] = (q < N) ? g_h[q*DM + c] : 0.f;
    }
    __syncthreads();
    {
        ull acc0[4], acc1[4];
        #pragma unroll
        for (int p = 0; p < 4; p++) { acc0[p] = 0ull; acc1[p] = 0ull; }
        #pragma unroll 4
        for (int i = 0; i < 128; i++) {
            ull w0 = pack2(W1[i*512 + tid]);
            ull w1 = pack2(W1[i*512 + 256 + tid]);
            #pragma unroll
            for (int p = 0; p < 4; p++) {
                ull hp = packab(sh2[2*p][i], sh2[2*p+1][i]);
                acc0[p] = fma2(hp, w0, acc0[p]);
                acc1[p] = fma2(hp, w1, acc1[p]);
            }
        }
        float bb0 = b1v[tid], bb1 = b1v[256 + tid];
        #pragma unroll
        for (int p = 0; p < 4; p++) {
            float a0, a1, c0, c1;
            unpack2(acc0[p], a0, a1);
            unpack2(acc1[p], c0, c1);
            st[2*p][tid]           = gelu_tanh(a0 + bb0);
            st[2*p][256 + tid]     = gelu_tanh(c0 + bb1);
            st[2*p + 1][tid]       = gelu_tanh(a1 + bb0);
            st[2*p + 1][256 + tid] = gelu_tanh(c1 + bb1);
        }
    }
    __syncthreads();
    {
        int col = tid & 127, half = tid >> 7;
        ull a01 = 0ull, a23 = 0ull;
        #pragma unroll 4
        for (int i = 0; i < 512; i++) {
            ull wv = pack2(W2[i*128 + col]);
            a01 = fma2(packab(st[half*4 + 0][i], st[half*4 + 1][i]), wv, a01);
            a23 = fma2(packab(st[half*4 + 2][i], st[half*4 + 3][i]), wv, a23);
        }
        float v0, v1, v2, v3;
        unpack2(a01, v0, v1);
        unpack2(a23, v2, v3);
        float bb = b2v[col];
        int qb = q0 + half * 4;
        if (qb + 0 < N) g_x[(qb+0)*DM + col] += v0 + bb;
        if (qb + 1 < N) g_x[(qb+1)*DM + col] += v1 + bb;
        if (qb + 2 < N) g_x[(qb+2)*DM + col] += v2 + bb;
        if (qb + 3 < N) g_x[(qb+3)*DM + col] += v3 + bb;
    }
}

__global__ void logits_kernel(const float* __restrict__ fm, const float* __restrict__ qpos,
                              const int* __restrict__ qbo, int n_off,
                              const int* __restrict__ shapes, float* __restrict__ out) {
    int q = blockIdx.x, tid = threadIdx.x;
    int lane = tid & 31, w = tid >> 5;
    __shared__ float sx[128];
    __shared__ int sb;
    if (tid < 128) sx[tid] = g_x[q*DM + tid];
    if (tid == 0) sb = batch_of(q, qbo, n_off);
    __syncthreads();
    int H0 = shapes[0], W0 = shapes[1];
    float p0 = qpos[2*q], p1 = qpos[2*q+1];
    int c0 = (int)floorf(p0), c1 = (int)floorf(p1);
    float4 xv = *(const float4*)&sx[lane * 4];
    int b = sb;
    for (int pp = w; pp < 49; pp += 8) {
        int gi = c0 + pp / 7 - 3;
        int gj = c1 + pp % 7 - 3;
        bool valid = (gi >= 0 && gi < H0 && gj >= 0 && gj < W0);
        int ci = min(max(gi, 0), H0 - 1), cj = min(max(gj, 0), W0 - 1);
        const float* f = fm + ((((size_t)b * 256 + ci) * 256 + cj) * 4 + 0) * 128;
        float4 fv = *(const float4*)(f + lane * 4);
        float d = fv.x*xv.x + fv.y*xv.y + fv.z*xv.z + fv.w*xv.w;
        #pragma unroll
        for (int o = 16; o; o >>= 1) d += __shfl_xor_sync(0xffffffffu, d, o);
        if (lane == 0) out[q*49 + pp] = valid ? d : 0.f;
    }
}

// ---------------- launch ----------------
extern "C" void kernel_launch(void* const* d_in, const int* in_sizes, int n_in,
                              void* d_out, int out_size) {
    const float* queries = (const float*)d_in[0];
    const int*   qbo     = (const int*)  d_in[1];
    const float* qpos    = (const float*)d_in[2];
    const float* fm      = (const float*)d_in[3];
    const int*   shapes  = (const int*)  d_in[4];
    const float* Wq      = (const float*)d_in[5];
    const float* Wk      = (const float*)d_in[6];
    const float* Wv      = (const float*)d_in[7];
    const float* Wo      = (const float*)d_in[8];
    const float* ln1g    = (const float*)d_in[9];
    const float* ln1b    = (const float*)d_in[10];
    const float* ln2g    = (const float*)d_in[11];
    const float* ln2b    = (const float*)d_in[12];
    const float* W1      = (const float*)d_in[13];
    const float* b1      = (const float*)d_in[14];
    const float* W2      = (const float*)d_in[15];
    const float* b2      = (const float*)d_in[16];

    int N     = in_sizes[0] / DM;
    int n_off = in_sizes[1];
    int nl    = in_sizes[5] / (DM * DM);
    int B     = in_sizes[3] / (256 * 256 * 4 * DM);
    int R123  = B * PER_B;
    int R     = R123 + N * 9;
    int gridR = (R + 127) / 128;

    cudaFuncSetAttribute(kvproj_mma_kernel, cudaFuncAttributeMaxDynamicSharedMemorySize, SM_MMA_TOTAL);

    // prepA sections: rowsrc | wt | rcs(per-row)
    int pa1 = (R + 255) / 256;
    int pa2 = (nl * 256 * 128 + 255) / 256;
    int pa3 = (R + 255) / 256;
    int a1 = pa1, a2 = a1 + pa2;
    int gridA = a2 + pa3;

    // prepB sections: copy_x | qcs | keys
    int pb1 = (N * DM + 255) / 256;
    int pb2 = (N + 255) / 256;
    int pb3 = (N * KTOT + 255) / 256;
    int b1o = pb1, b2o = b1o + pb2;
    int gridB = b2o + pb3;

    prepA_kernel<<<gridA, 256>>>(qpos, qbo, n_off, shapes, Wk, Wv, nl, R123, R, a1, a2);

    bool overlap = (nl == 2);
    cudaStream_t sKV = 0;
    cudaEvent_t evReady = 0, evKv0 = 0, evKv1 = 0;
    if (overlap) {
        if (cudaStreamCreateWithFlags(&sKV, cudaStreamNonBlocking) != cudaSuccess ||
            cudaEventCreateWithFlags(&evReady, cudaEventDisableTiming) != cudaSuccess ||
            cudaEventCreateWithFlags(&evKv0, cudaEventDisableTiming) != cudaSuccess ||
            cudaEventCreateWithFlags(&evKv1, cudaEventDisableTiming) != cudaSuccess) {
            overlap = false;
        }
    }

    if (overlap) {
        // fork right after prepA: kvprojs on sKV; prepB + layer-0 front on main
        cudaEventRecord(evReady, 0);
        cudaStreamWaitEvent(sKV, evReady, 0);
        kvproj_mma_kernel<<<gridR, 256, SM_MMA_TOTAL, sKV>>>(fm, 0, R, 0);
        cudaEventRecord(evKv0, sKV);
        kvproj_mma_kernel<<<gridR, 256, SM_MMA_TOTAL, sKV>>>(fm, 1, R, 1);
        cudaEventRecord(evKv1, sKV);

        prepB_kernel<<<gridB, 256>>>(queries, qpos, qbo, n_off, shapes, N, R123, b1o, b2o);
        ln_qproj_kernel<<<N, 128>>>(ln1g, ln1b, Wq);

        cudaStreamWaitEvent(0, evKv0, 0);
        attn_kernel<<<N, 128>>>(0);
        oproj_ln2_kernel<<<N, 128>>>(Wo, ln2g, ln2b);
        ffn_kernel<<<(N + 7) / 8, 256>>>(W1, b1, W2, b2, N);
        ln_qproj_kernel<<<N, 128>>>(ln1g + DM, ln1b + DM, Wq + DM*DM);

        cudaStreamWaitEvent(0, evKv1, 0);
        attn_kernel<<<N, 128>>>(1);
        oproj_ln2_kernel<<<N, 128>>>(Wo + DM*DM, ln2g + DM, ln2b + DM);
        ffn_kernel<<<(N + 7) / 8, 256>>>(W1 + DM*512, b1 + 512, W2 + 512*DM, b2 + DM, N);
    } else {
        prepB_kernel<<<gridB, 256>>>(queries, qpos, qbo, n_off, shapes, N, R123, b1o, b2o);
        kvproj_mma_kernel<<<gridR, 256, SM_MMA_TOTAL>>>(fm, 0, R, 0);
        ln_qproj_kernel<<<N, 128>>>(ln1g, ln1b, Wq);
        attn_kernel<<<N, 128>>>(0);
        oproj_ln2_kernel<<<N, 128>>>(Wo, ln2g, ln2b);
        ffn_kernel<<<(N + 7) / 8, 256>>>(W1, b1, W2, b2, N);
        for (int li = 1; li < nl; li++) {
            int buf = li & 1;
            kvproj_mma_kernel<<<gridR, 256, SM_MMA_TOTAL>>>(fm, li, R, buf);
            ln_qproj_kernel<<<N, 128>>>(ln1g + li*DM, ln1b + li*DM, Wq + li*DM*DM);
            attn_kernel<<<N, 128>>>(buf);
            oproj_ln2_kernel<<<N, 128>>>(Wo + li*DM*DM, ln2g + li*DM, ln2b + li*DM);
            ffn_kernel<<<(N + 7) / 8, 256>>>(W1 + li*DM*512, b1 + li*512, W2 + li*512*DM, b2 + li*DM, N);
        }
    }
    logits_kernel<<<N, 256>>>(fm, qpos, qbo, n_off, shapes, (float*)d_out);
    // streams/events intentionally not destroyed mid-capture (host-side handles only)
}

// round 17
// speedup vs baseline: 1.1078x; 1.0251x over previous
#include <cuda_runtime.h>
#include <cuda_bf16.h>
#include <math.h>
#include <stdint.h>

#define DM   128
#define NH   8
#define HD   16
#define KTOT 164          // 9 + 25 + 49 + 81
#define PER_B 21504       // 128*128 + 64*64 + 32*32
#define MAXN 2048
#define MAXROWS (2*PER_B + MAXN*9)
#define MAXL 4

typedef unsigned long long ull;

// ---------------- device scratch ----------------
__device__ float g_x  [MAXN*DM];
__device__ float g_q  [MAXN*DM];
__device__ float g_h  [MAXN*DM];
__device__ float g_qcs[MAXN*16];
__device__ int   g_kidx[MAXN*KTOT];              // bit31 set = INVALID key
__device__ int   g_rowsrc[MAXROWS];
__device__ float g_rcs[MAXROWS*16];              // per-row RoPE cos/sin
__device__ float g_Kc[2][(size_t)MAXROWS*DM];    // ping-pong buffers
__device__ float g_Vc[2][(size_t)MAXROWS*DM];
__device__ __align__(16) __nv_bfloat16 g_WBhi[MAXL*256*128];   // [layer][n: Wk|Wv][k]
__device__ __align__(16) __nv_bfloat16 g_WBlo[MAXL*256*128];

__device__ __constant__ float c_invfreq[4] = {1.0f, 0.56234132519f, 0.316227766017f, 0.177827941004f};

// ---------------- helpers ----------------
__device__ __forceinline__ ull fma2(ull a, ull b, ull c) {
    ull d; asm("fma.rn.f32x2 %0, %1, %2, %3;" : "=l"(d) : "l"(a), "l"(b), "l"(c)); return d;
}
__device__ __forceinline__ ull pack2(float f) {
    ull r; asm("mov.b64 %0, {%1, %1};" : "=l"(r) : "r"(__float_as_uint(f))); return r;
}
__device__ __forceinline__ ull packab(float a, float b) {
    ull r; asm("mov.b64 %0, {%1, %2};" : "=l"(r) : "r"(__float_as_uint(a)), "r"(__float_as_uint(b))); return r;
}
__device__ __forceinline__ void unpack2(ull v, float& lo, float& hi) {
    unsigned int a, b; asm("mov.b64 {%0, %1}, %2;" : "=r"(a), "=r"(b) : "l"(v));
    lo = __uint_as_float(a); hi = __uint_as_float(b);
}
__device__ __forceinline__ float gelu_tanh(float v) {
    float u = 0.7978845608028654f * (v + 0.044715f * v * v * v);
    return 0.5f * v * (1.f + tanhf(u));
}
__device__ __forceinline__ int batch_of(int q, const int* qbo, int n_off) {
    int b = 0;
    for (int t = 1; t < n_off - 1; t++) if (q >= qbo[t]) b = t;
    return b;
}
__device__ __forceinline__ uint32_t smem_u32(const void* p) {
    uint32_t a;
    asm("{ .reg .u64 t; cvta.to.shared.u64 t, %1; cvt.u32.u64 %0, t; }" : "=r"(a) : "l"(p));
    return a;
}
__device__ __forceinline__ uint32_t bf2(float a, float b) {
    __nv_bfloat162 h = __floats2bfloat162_rn(a, b);
    return *(uint32_t*)&h;
}
__device__ __forceinline__ float bflo(float x, __nv_bfloat16 hi) {
    return x - __bfloat162float(hi);
}
__device__ __forceinline__ void ldsm_x4(uint32_t addr, uint32_t& r0, uint32_t& r1, uint32_t& r2, uint32_t& r3) {
    asm volatile("ldmatrix.sync.aligned.m8n8.x4.shared.b16 {%0,%1,%2,%3}, [%4];"
                 : "=r"(r0), "=r"(r1), "=r"(r2), "=r"(r3) : "r"(addr));
}
__device__ __forceinline__ void mma_bf16(float* c, uint32_t a0, uint32_t a1, uint32_t a2, uint32_t a3,
                                         uint32_t b0, uint32_t b1) {
    asm volatile("mma.sync.aligned.m16n8k16.row.col.f32.bf16.bf16.f32 "
                 "{%0,%1,%2,%3}, {%4,%5,%6,%7}, {%8,%9}, {%0,%1,%2,%3};"
                 : "+f"(c[0]), "+f"(c[1]), "+f"(c[2]), "+f"(c[3])
                 : "r"(a0), "r"(a1), "r"(a2), "r"(a3), "r"(b0), "r"(b1));
}

// ---------------- LN1 + Qproj + RoPE body (per-query, 128 threads) ----------------
__device__ void ln_qproj_body(int q, const float* __restrict__ lg, const float* __restrict__ lb,
                              const float* __restrict__ Wq) {
    int tid = threadIdx.x;
    int lane = tid & 31, w = tid >> 5;
    __shared__ float sh[128];
    __shared__ float sraw[128];
    __shared__ float red[8];
    float x = g_x[q*DM + tid];
    float s1 = x, s2 = x * x;
    #pragma unroll
    for (int o = 16; o; o >>= 1) {
        s1 += __shfl_xor_sync(0xffffffffu, s1, o);
        s2 += __shfl_xor_sync(0xffffffffu, s2, o);
    }
    if (lane == 0) { red[w] = s1; red[4 + w] = s2; }
    __syncthreads();
    float mean = (red[0] + red[1] + red[2] + red[3]) * (1.f / 128.f);
    float var  = (red[4] + red[5] + red[6] + red[7]) * (1.f / 128.f) - mean * mean;
    sh[tid] = (x - mean) * rsqrtf(var + 1e-5f) * lg[tid] + lb[tid];
    __syncthreads();
    float acc = 0.f;
    #pragma unroll 8
    for (int i = 0; i < 128; i++) acc += sh[i] * Wq[i * DM + tid];
    sraw[tid] = acc;
    __syncthreads();
    int p = (tid >> 1) & 7;
    float c = g_qcs[q*16 + p], s = g_qcs[q*16 + 8 + p];
    float x1 = sraw[tid & ~1];
    float x2 = sraw[tid |  1];
    g_q[q*DM + tid] = (tid & 1) ? (x1 * s + x2 * c) : (x1 * c - x2 * s);
}

// ---------------- prepA: what kvproj needs (rowsrc | wt-split | rcs-per-row) ----------------
__global__ void prepA_kernel(const float* __restrict__ qpos,
                             const int* __restrict__ qbo, int n_off,
                             const int* __restrict__ shapes,
                             const float* __restrict__ Wk, const float* __restrict__ Wv,
                             int nl, int R123, int R,
                             int a1, int a2) {
    int bid = blockIdx.x, tid = threadIdx.x;
    if (bid < a1) {                                      // rowsrc
        int e = bid * 256 + tid;
        if (e >= R) return;
        int src;
        if (e < R123) {
            int b = e / PER_B, r = e % PER_B;
            int l, i, j;
            if (r < 16384)      { l = 1; i = r >> 7; j = r & 127; }
            else if (r < 20480) { int rr = r - 16384; l = 2; i = rr >> 6; j = rr & 63; }
            else                { int rr = r - 20480; l = 3; i = rr >> 5; j = rr & 31; }
            src = ((b * 256 + i) * 256 + j) * 4 + l;
        } else {
            int e2 = e - R123;
            int q = e2 / 9, t = e2 % 9;
            int b = batch_of(q, qbo, n_off);
            int c0 = (int)floorf(qpos[2*q]), c1 = (int)floorf(qpos[2*q+1]);
            int gi = min(max(c0 + t / 3 - 1, 0), 255);
            int gj = min(max(c1 + t % 3 - 1, 0), 255);
            src = ((b * 256 + gi) * 256 + gj) * 4 + 0;
        }
        g_rowsrc[e] = src;
    } else if (bid < a2) {                               // wt split
        int id = (bid - a1) * 256 + tid;
        if (id >= nl * 256 * 128) return;
        int li = id / (256 * 128);
        int r  = id % (256 * 128);
        int n = r / 128, k = r % 128;
        float w = (n < 128) ? Wk[li*DM*DM + k*DM + n] : Wv[li*DM*DM + k*DM + (n - 128)];
        __nv_bfloat16 hi = __float2bfloat16(w);
        g_WBhi[id] = hi;
        g_WBlo[id] = __float2bfloat16(w - __bfloat162float(hi));
    } else {                                             // rcs: one thread per row
        int row = (bid - a2) * 256 + tid;
        if (row >= R) return;
        int l, gi, gj;
        if (row < R123) {
            int r = row % PER_B;
            if (r < 16384)      { l = 1; gi = r >> 7; gj = r & 127; }
            else if (r < 20480) { int rr = r - 16384; l = 2; gi = rr >> 6; gj = rr & 63; }
            else                { int rr = r - 20480; l = 3; gi = rr >> 5; gj = rr & 31; }
        } else {
            int e2 = row - R123;
            int q = e2 / 9, t = e2 % 9;
            l = 0;
            gi = min(max((int)floorf(qpos[2*q])   + t / 3 - 1, 0), 255);
            gj = min(max((int)floorf(qpos[2*q+1]) + t % 3 - 1, 0), 255);
        }
        float* dst = &g_rcs[(size_t)row * 16];
        #pragma unroll
        for (int axis = 0; axis < 2; axis++) {
            float scale = (float)shapes[2*l + axis] / (float)shapes[axis];
            float kp = ((float)(axis ? gj : gi) + 0.5f) / scale;
            #pragma unroll
            for (int f = 0; f < 4; f++) {
                float a = kp * c_invfreq[f];
                dst[axis * 4 + f]     = cosf(a);
                dst[8 + axis * 4 + f] = sinf(a);
            }
        }
    }
}

// ---------------- prepB: what the main path needs (copy_x | qcs | build_keys) ----------------
__global__ void prepB_kernel(const float* __restrict__ queries,
                             const float* __restrict__ qpos,
                             const int* __restrict__ qbo, int n_off,
                             const int* __restrict__ shapes,
                             int N, int R123,
                             int b1, int b2) {
    int bid = blockIdx.x, tid = threadIdx.x;
    if (bid < b1) {                                      // copy_x
        int i = bid * 256 + tid;
        if (i < N * DM) g_x[i] = queries[i];
    } else if (bid < b2) {                               // qcs
        int q = (bid - b1) * 256 + tid;
        if (q >= N) return;
        float p0 = qpos[2*q], p1 = qpos[2*q+1];
        float* cs = &g_qcs[q * 16];
        #pragma unroll
        for (int f = 0; f < 4; f++) {
            float a0 = p0 * c_invfreq[f];
            float a1 = p1 * c_invfreq[f];
            cs[f]      = cosf(a0);  cs[8  + f] = sinf(a0);
            cs[4 + f]  = cosf(a1);  cs[12 + f] = sinf(a1);
        }
    } else {                                             // build_keys (idx with valid in bit31)
        int id = (bid - b2) * 256 + tid;
        if (id >= N * KTOT) return;
        int q = id / KTOT, k = id % KTOT;
        int l, t, d;
        if      (k < 9)  { l = 0; t = k;      d = 3; }
        else if (k < 34) { l = 1; t = k - 9;  d = 5; }
        else if (k < 83) { l = 2; t = k - 34; d = 7; }
        else             { l = 3; t = k - 83; d = 9; }
        int Hl = shapes[2*l], Wl = shapes[2*l+1];
        float sh = (float)Hl / (float)shapes[0];
        float sw = (float)Wl / (float)shapes[1];
        int c0 = (int)floorf(qpos[2*q] * sh), c1 = (int)floorf(qpos[2*q+1] * sw);
        int gi = c0 + t / d - d / 2;
        int gj = c1 + t % d - d / 2;
        int valid = (gi >= 0 && gi < Hl && gj >= 0 && gj < Wl);
        int ci = min(max(gi, 0), Hl - 1), cj = min(max(gj, 0), Wl - 1);
        int b = batch_of(q, qbo, n_off);
        int idx;
        if (l == 0) idx = R123 + q * 9 + t;
        else {
            int base = (l == 1) ? 0 : (l == 2) ? 16384 : 20480;
            idx = b * PER_B + base + ci * Wl + cj;
        }
        g_kidx[id] = (int)((unsigned)idx | (valid ? 0u : 0x80000000u));
    }
}

__global__ void ln_qproj_kernel(const float* __restrict__ lg, const float* __restrict__ lb,
                                const float* __restrict__ Wq) {
    ln_qproj_body(blockIdx.x, lg, lb, Wq);
}

// ---------------- mma.sync KV projection (rope fused into K epilogue) ----------------
#define A_STR 136
#define B_STR 40
#define OFF_AHI 0
#define OFF_ALO 34816
#define OFF_BHI 69632
#define OFF_BLO 79872
#define SM_MMA_TOTAL 90112

__global__ void __launch_bounds__(256, 2)
kvproj_mma_kernel(const float* __restrict__ fm, int li, int R, int buf) {
    extern __shared__ char smem[];
    uint32_t sbase = smem_u32(smem);
    int tid = threadIdx.x;
    int wid = tid >> 5, lane = tid & 31;
    int wm = wid & 3, wn = wid >> 2;
    int row0 = blockIdx.x * 128;

    #pragma unroll
    for (int it = 0; it < 16; it++) {
        int idx = tid + 256 * it;
        int r = idx >> 5, c4 = idx & 31;
        int row = row0 + r; if (row >= R) row = R - 1;
        int src = g_rowsrc[row];
        float4 v = *(const float4*)(fm + (size_t)src * 128 + c4 * 4);
        __nv_bfloat16 hx = __float2bfloat16(v.x);
        __nv_bfloat16 hy = __float2bfloat16(v.y);
        __nv_bfloat16 hz = __float2bfloat16(v.z);
        __nv_bfloat16 hw = __float2bfloat16(v.w);
        uint32_t h01 = ((uint32_t)*(uint16_t*)&hy << 16) | *(uint16_t*)&hx;
        uint32_t h23 = ((uint32_t)*(uint16_t*)&hw << 16) | *(uint16_t*)&hz;
        uint32_t l01 = bf2(bflo(v.x, hx), bflo(v.y, hy));
        uint32_t l23 = bf2(bflo(v.z, hz), bflo(v.w, hw));
        uint32_t off = (uint32_t)(r * A_STR + c4 * 4) * 2;
        *(uint2*)(smem + OFF_AHI + off) = make_uint2(h01, h23);
        *(uint2*)(smem + OFF_ALO + off) = make_uint2(l01, l23);
    }

    const __nv_bfloat16* wbh = g_WBhi + (size_t)li * 256 * 128;
    const __nv_bfloat16* wbl = g_WBlo + (size_t)li * 256 * 128;

    for (int h = 0; h < 2; h++) {
        float acc[2][8][4];
        #pragma unroll
        for (int i = 0; i < 2; i++)
            #pragma unroll
            for (int j = 0; j < 8; j++)
                #pragma unroll
                for (int e = 0; e < 4; e++) acc[i][j][e] = 0.f;

        for (int c = 0; c < 4; c++) {
            __syncthreads();
            #pragma unroll
            for (int it = 0; it < 2; it++) {
                int idx = tid + 256 * it;
                int n = idx >> 2, kk = (idx & 3) * 8;
                const __nv_bfloat16* sh = wbh + ((size_t)(h * 128 + n)) * 128 + c * 32 + kk;
                const __nv_bfloat16* sl = wbl + ((size_t)(h * 128 + n)) * 128 + c * 32 + kk;
                uint32_t off = (uint32_t)(n * B_STR + kk) * 2;
                *(uint4*)(smem + OFF_BHI + off) = *(const uint4*)sh;
                *(uint4*)(smem + OFF_BLO + off) = *(const uint4*)sl;
            }
            __syncthreads();

            #pragma unroll
            for (int s = 0; s < 2; s++) {
                uint32_t ah[2][4], al[2][4];
                #pragma unroll
                for (int i = 0; i < 2; i++) {
                    uint32_t arow = wm * 32 + i * 16 + (lane & 15);
                    uint32_t akol = c * 32 + s * 16 + ((lane >> 4) << 3);
                    uint32_t aoff = (arow * A_STR + akol) * 2;
                    ldsm_x4(sbase + OFF_AHI + aoff, ah[i][0], ah[i][1], ah[i][2], ah[i][3]);
                    ldsm_x4(sbase + OFF_ALO + aoff, al[i][0], al[i][1], al[i][2], al[i][3]);
                }
                #pragma unroll
                for (int jj = 0; jj < 4; jj++) {
                    int m = lane >> 3, w8 = lane & 7;
                    uint32_t bn = wn * 64 + (2 * jj + (m >> 1)) * 8 + w8;
                    uint32_t bk = s * 16 + (m & 1) * 8;
                    uint32_t boff = (bn * B_STR + bk) * 2;
                    uint32_t bh0, bh1, bh2, bh3, bl0, bl1, bl2, bl3;
                    ldsm_x4(sbase + OFF_BHI + boff, bh0, bh1, bh2, bh3);
                    ldsm_x4(sbase + OFF_BLO + boff, bl0, bl1, bl2, bl3);
                    #pragma unroll
                    for (int i = 0; i < 2; i++) {
                        mma_bf16(acc[i][2*jj],   ah[i][0], ah[i][1], ah[i][2], ah[i][3], bh0, bh1);
                        mma_bf16(acc[i][2*jj],   ah[i][0], ah[i][1], ah[i][2], ah[i][3], bl0, bl1);
                        mma_bf16(acc[i][2*jj],   al[i][0], al[i][1], al[i][2], al[i][3], bh0, bh1);
                        mma_bf16(acc[i][2*jj+1], ah[i][0], ah[i][1], ah[i][2], ah[i][3], bh2, bh3);
                        mma_bf16(acc[i][2*jj+1], ah[i][0], ah[i][1], ah[i][2], ah[i][3], bl2, bl3);
                        mma_bf16(acc[i][2*jj+1], al[i][0], al[i][1], al[i][2], al[i][3], bh2, bh3);
                    }
                }
            }
        }
        float* dstbase = h ? g_Vc[buf] : g_Kc[buf];
        int pb = lane & 3;
        #pragma unroll
        for (int i = 0; i < 2; i++) {
            int rA = row0 + wm * 32 + i * 16 + (lane >> 2);
            int rB = rA + 8;
            if (h == 0) {
                float cA0 = g_rcs[rA*16 + pb],     sA0 = g_rcs[rA*16 + 8 + pb];
                float cA1 = g_rcs[rA*16 + 4 + pb], sA1 = g_rcs[rA*16 + 12 + pb];
                float cB0 = g_rcs[rB*16 + pb],     sB0 = g_rcs[rB*16 + 8 + pb];
                float cB1 = g_rcs[rB*16 + 4 + pb], sB1 = g_rcs[rB*16 + 12 + pb];
                #pragma unroll
                for (int j = 0; j < 8; j++) {
                    int col = wn * 64 + j * 8 + pb * 2;
                    float cc = (j & 1) ? cA1 : cA0, ss = (j & 1) ? sA1 : sA0;
                    float a0 = acc[i][j][0], a1 = acc[i][j][1];
                    if (rA < R) *(float2*)(dstbase + (size_t)rA * 128 + col) =
                        make_float2(a0 * cc - a1 * ss, a0 * ss + a1 * cc);
                    float cc2 = (j & 1) ? cB1 : cB0, ss2 = (j & 1) ? sB1 : sB0;
                    float b0 = acc[i][j][2], b1 = acc[i][j][3];
                    if (rB < R) *(float2*)(dstbase + (size_t)rB * 128 + col) =
                        make_float2(b0 * cc2 - b1 * ss2, b0 * ss2 + b1 * cc2);
                }
            } else {
                #pragma unroll
                for (int j = 0; j < 8; j++) {
                    int col = wn * 64 + j * 8 + pb * 2;
                    if (rA < R) *(float2*)(dstbase + (size_t)rA * 128 + col) = make_float2(acc[i][j][0], acc[i][j][1]);
                    if (rB < R) *(float2*)(dstbase + (size_t)rB * 128 + col) = make_float2(acc[i][j][2], acc[i][j][3]);
                }
            }
        }
    }
}

// ---------------- fused attention + oproj + LN2 (per query, 128 threads) ----------------
__global__ void attn_kernel(int buf, const float* __restrict__ Wo,
                            const float* __restrict__ lg, const float* __restrict__ lb) {
    int q = blockIdx.x, tid = threadIdx.x;
    int lane = tid & 31, w = tid >> 5;
    __shared__ float sq[128];
    __shared__ float ssc[8 * KTOT];
    __shared__ int   skidx[KTOT];
    __shared__ float smask[KTOT];
    __shared__ float so[128];
    __shared__ float red[8];
    const float* Kc = g_Kc[buf];
    const float* Vc = g_Vc[buf];
    sq[tid] = g_q[q*DM + tid];
    for (int k = tid; k < KTOT; k += 128) {
        unsigned e = (unsigned)g_kidx[q*KTOT + k];
        skidx[k] = (int)(e & 0x7FFFFFFFu);
        smask[k] = (e & 0x80000000u) ? -1.0e9f : 0.f;
    }
    __syncthreads();
    float4 qv = *(const float4*)&sq[lane * 4];
    for (int k = w; k < KTOT; k += 4) {
        int idx = skidx[k];
        float4 kv = *(const float4*)&Kc[(size_t)idx*DM + lane*4];
        float ps = kv.x*qv.x + kv.y*qv.y + kv.z*qv.z + kv.w*qv.w;
        ps += __shfl_xor_sync(0xffffffffu, ps, 1);
        ps += __shfl_xor_sync(0xffffffffu, ps, 2);
        if ((lane & 3) == 0) {
            int h = lane >> 2;
            ssc[h*KTOT + k] = ps * 0.25f + smask[k];
        }
    }
    __syncthreads();
    #pragma unroll
    for (int hh = 0; hh < 2; hh++) {
        int h = w * 2 + hh;
        float mx = -3.0e38f;
        for (int k = lane; k < KTOT; k += 32) mx = fmaxf(mx, ssc[h*KTOT + k]);
        #pragma unroll
        for (int o = 16; o; o >>= 1) mx = fmaxf(mx, __shfl_xor_sync(0xffffffffu, mx, o));
        float sum = 0.f;
        for (int k = lane; k < KTOT; k += 32) {
            float e = expf(ssc[h*KTOT + k] - mx);
            ssc[h*KTOT + k] = e;
            sum += e;
        }
        #pragma unroll
        for (int o = 16; o; o >>= 1) sum += __shfl_xor_sync(0xffffffffu, sum, o);
        float inv = 1.f / sum;
        for (int k = lane; k < KTOT; k += 32) ssc[h*KTOT + k] *= inv;
    }
    __syncthreads();
    {
        int h = tid >> 4;
        float acc = 0.f;
        #pragma unroll 4
        for (int k = 0; k < KTOT; k++)
            acc += ssc[h*KTOT + k] * Vc[(size_t)skidx[k]*DM + tid];
        so[tid] = acc;
    }
    __syncthreads();
    // ---- fused oproj + residual + LN2 ----
    float aw = 0.f;
    #pragma unroll 8
    for (int i = 0; i < 128; i++) aw += so[i] * Wo[i * DM + tid];
    float x = g_x[q*DM + tid] + aw;
    g_x[q*DM + tid] = x;
    float s1 = x, s2 = x * x;
    #pragma unroll
    for (int o = 16; o; o >>= 1) {
        s1 += __shfl_xor_sync(0xffffffffu, s1, o);
        s2 += __shfl_xor_sync(0xffffffffu, s2, o);
    }
    if (lane == 0) { red[w] = s1; red[4 + w] = s2; }
    __syncthreads();
    float mean = (red[0] + red[1] + red[2] + red[3]) * (1.f / 128.f);
    float var  = (red[4] + red[5] + red[6] + red[7]) * (1.f / 128.f) - mean * mean;
    g_h[q*DM + tid] = (x - mean) * rsqrtf(var + 1e-5f) * lg[tid] + lb[tid];
}

// t = gelu(h @ W1 + b1), then x += t @ W2 + b2.  8 q/block, 256 thr
__global__ void ffn_kernel(const float* __restrict__ W1, const float* __restrict__ b1v,
                           const float* __restrict__ W2, const float* __restrict__ b2v, int N) {
    int q0 = blockIdx.x * 8, tid = threadIdx.x;
    __shared__ float sh2[8][128];
    __shared__ float st[8][512];
    for (int i = tid; i < 1024; i += 256) {
        int r = i >> 7, c = i & 127;
        int q = q0 + r;
        sh2[r][c] = (q < N) ? g_h[q*DM + c] : 0.f;
    }
    __syncthreads();
    {
        ull acc0[4], acc1[4];
        #pragma unroll
        for (int p = 0; p < 4; p++) { acc0[p] = 0ull; acc1[p] = 0ull; }
        #pragma unroll 4
        for (int i = 0; i < 128; i++) {
            ull w0 = pack2(W1[i*512 + tid]);
            ull w1 = pack2(W1[i*512 + 256 + tid]);
            #pragma unroll
            for (int p = 0; p < 4; p++) {
                ull hp = packab(sh2[2*p][i], sh2[2*p+1][i]);
                acc0[p] = fma2(hp, w0, acc0[p]);
                acc1[p] = fma2(hp, w1, acc1[p]);
            }
        }
        float bb0 = b1v[tid], bb1 = b1v[256 + tid];
        #pragma unroll
        for (int p = 0; p < 4; p++) {
            float a0, a1, c0, c1;
            unpack2(acc0[p], a0, a1);
            unpack2(acc1[p], c0, c1);
            st[2*p][tid]           = gelu_tanh(a0 + bb0);
            st[2*p][256 + tid]     = gelu_tanh(c0 + bb1);
            st[2*p + 1][tid]       = gelu_tanh(a1 + bb0);
            st[2*p + 1][256 + tid] = gelu_tanh(c1 + bb1);
        }
    }
    __syncthreads();
    {
        int col = tid & 127, half = tid >> 7;
        ull a01 = 0ull, a23 = 0ull;
        #pragma unroll 4
        for (int i = 0; i < 512; i++) {
            ull wv = pack2(W2[i*128 + col]);
            a01 = fma2(packab(st[half*4 + 0][i], st[half*4 + 1][i]), wv, a01);
            a23 = fma2(packab(st[half*4 + 2][i], st[half*4 + 3][i]), wv, a23);
        }
        float v0, v1, v2, v3;
        unpack2(a01, v0, v1);
        unpack2(a23, v2, v3);
        float bb = b2v[col];
        int qb = q0 + half * 4;
        if (qb + 0 < N) g_x[(qb+0)*DM + col] += v0 + bb;
        if (qb + 1 < N) g_x[(qb+1)*DM + col] += v1 + bb;
        if (qb + 2 < N) g_x[(qb+2)*DM + col] += v2 + bb;
        if (qb + 3 < N) g_x[(qb+3)*DM + col] += v3 + bb;
    }
}

__global__ void logits_kernel(const float* __restrict__ fm, const float* __restrict__ qpos,
                              const int* __restrict__ qbo, int n_off,
                              const int* __restrict__ shapes, float* __restrict__ out) {
    int q = blockIdx.x, tid = threadIdx.x;
    int lane = tid & 31, w = tid >> 5;
    __shared__ float sx[128];
    __shared__ int sb;
    if (tid < 128) sx[tid] = g_x[q*DM + tid];
    if (tid == 0) sb = batch_of(q, qbo, n_off);
    __syncthreads();
    int H0 = shapes[0], W0 = shapes[1];
    float p0 = qpos[2*q], p1 = qpos[2*q+1];
    int c0 = (int)floorf(p0), c1 = (int)floorf(p1);
    float4 xv = *(const float4*)&sx[lane * 4];
    int b = sb;
    for (int pp = w; pp < 49; pp += 8) {
        int gi = c0 + pp / 7 - 3;
        int gj = c1 + pp % 7 - 3;
        bool valid = (gi >= 0 && gi < H0 && gj >= 0 && gj < W0);
        int ci = min(max(gi, 0), H0 - 1), cj = min(max(gj, 0), W0 - 1);
        const float* f = fm + ((((size_t)b * 256 + ci) * 256 + cj) * 4 + 0) * 128;
        float4 fv = *(const float4*)(f + lane * 4);
        float d = fv.x*xv.x + fv.y*xv.y + fv.z*xv.z + fv.w*xv.w;
        #pragma unroll
        for (int o = 16; o; o >>= 1) d += __shfl_xor_sync(0xffffffffu, d, o);
        if (lane == 0) out[q*49 + pp] = valid ? d : 0.f;
    }
}

// ---------------- launch ----------------
extern "C" void kernel_launch(void* const* d_in, const int* in_sizes, int n_in,
                              void* d_out, int out_size) {
    const float* queries = (const float*)d_in[0];
    const int*   qbo     = (const int*)  d_in[1];
    const float* qpos    = (const float*)d_in[2];
    const float* fm      = (const float*)d_in[3];
    const int*   shapes  = (const int*)  d_in[4];
    const float* Wq      = (const float*)d_in[5];
    const float* Wk      = (const float*)d_in[6];
    const float* Wv      = (const float*)d_in[7];
    const float* Wo      = (const float*)d_in[8];
    const float* ln1g    = (const float*)d_in[9];
    const float* ln1b    = (const float*)d_in[10];
    const float* ln2g    = (const float*)d_in[11];
    const float* ln2b    = (const float*)d_in[12];
    const float* W1      = (const float*)d_in[13];
    const float* b1      = (const float*)d_in[14];
    const float* W2      = (const float*)d_in[15];
    const float* b2      = (const float*)d_in[16];

    int N     = in_sizes[0] / DM;
    int n_off = in_sizes[1];
    int nl    = in_sizes[5] / (DM * DM);
    int B     = in_sizes[3] / (256 * 256 * 4 * DM);
    int R123  = B * PER_B;
    int R     = R123 + N * 9;
    int gridR = (R + 127) / 128;

    cudaFuncSetAttribute(kvproj_mma_kernel, cudaFuncAttributeMaxDynamicSharedMemorySize, SM_MMA_TOTAL);

    // prepA sections: rowsrc | wt | rcs(per-row)
    int pa1 = (R + 255) / 256;
    int pa2 = (nl * 256 * 128 + 255) / 256;
    int pa3 = (R + 255) / 256;
    int a1 = pa1, a2 = a1 + pa2;
    int gridA = a2 + pa3;

    // prepB sections: copy_x | qcs | keys
    int pb1 = (N * DM + 255) / 256;
    int pb2 = (N + 255) / 256;
    int pb3 = (N * KTOT + 255) / 256;
    int b1o = pb1, b2o = b1o + pb2;
    int gridB = b2o + pb3;

    prepA_kernel<<<gridA, 256>>>(qpos, qbo, n_off, shapes, Wk, Wv, nl, R123, R, a1, a2);

    bool overlap = (nl == 2);
    cudaStream_t sKV = 0;
    cudaEvent_t evReady = 0, evKv0 = 0, evKv1 = 0;
    if (overlap) {
        if (cudaStreamCreateWithFlags(&sKV, cudaStreamNonBlocking) != cudaSuccess ||
            cudaEventCreateWithFlags(&evReady, cudaEventDisableTiming) != cudaSuccess ||
            cudaEventCreateWithFlags(&evKv0, cudaEventDisableTiming) != cudaSuccess ||
            cudaEventCreateWithFlags(&evKv1, cudaEventDisableTiming) != cudaSuccess) {
            overlap = false;
        }
    }

    if (overlap) {
        cudaEventRecord(evReady, 0);
        cudaStreamWaitEvent(sKV, evReady, 0);
        kvproj_mma_kernel<<<gridR, 256, SM_MMA_TOTAL, sKV>>>(fm, 0, R, 0);
        cudaEventRecord(evKv0, sKV);
        kvproj_mma_kernel<<<gridR, 256, SM_MMA_TOTAL, sKV>>>(fm, 1, R, 1);
        cudaEventRecord(evKv1, sKV);

        prepB_kernel<<<gridB, 256>>>(queries, qpos, qbo, n_off, shapes, N, R123, b1o, b2o);
        ln_qproj_kernel<<<N, 128>>>(ln1g, ln1b, Wq);

        cudaStreamWaitEvent(0, evKv0, 0);
        attn_kernel<<<N, 128>>>(0, Wo, ln2g, ln2b);
        ffn_kernel<<<(N + 7) / 8, 256>>>(W1, b1, W2, b2, N);
        ln_qproj_kernel<<<N, 128>>>(ln1g + DM, ln1b + DM, Wq + DM*DM);

        cudaStreamWaitEvent(0, evKv1, 0);
        attn_kernel<<<N, 128>>>(1, Wo + DM*DM, ln2g + DM, ln2b + DM);
        ffn_kernel<<<(N + 7) / 8, 256>>>(W1 + DM*512, b1 + 512, W2 + 512*DM, b2 + DM, N);
    } else {
        prepB_kernel<<<gridB, 256>>>(queries, qpos, qbo, n_off, shapes, N, R123, b1o, b2o);
        kvproj_mma_kernel<<<gridR, 256, SM_MMA_TOTAL>>>(fm, 0, R, 0);
        ln_qproj_kernel<<<N, 128>>>(ln1g, ln1b, Wq);
        attn_kernel<<<N, 128>>>(0, Wo, ln2g, ln2b);
        ffn_kernel<<<(N + 7) / 8, 256>>>(W1, b1, W2, b2, N);
        for (int li = 1; li < nl; li++) {
            int buf = li & 1;
            kvproj_mma_kernel<<<gridR, 256, SM_MMA_TOTAL>>>(fm, li, R, buf);
            ln_qproj_kernel<<<N, 128>>>(ln1g + li*DM, ln1b + li*DM, Wq + li*DM*DM);
            attn_kernel<<<N, 128>>>(buf, Wo + li*DM*DM, ln2g + li*DM, ln2b + li*DM);
            ffn_kernel<<<(N + 7) / 8, 256>>>(W1 + li*DM*512, b1 + li*512, W2 + li*512*DM, b2 + li*DM, N);
        }
    }
    logits_kernel<<<N, 256>>>(fm, qpos, qbo, n_off, shapes, (float*)d_out);
    // streams/events intentionally not destroyed mid-capture (host-side handles only)
}